// round 6
// baseline (speedup 1.0000x reference)
#include <cuda_runtime.h>
#include <cuda_bf16.h>
#include <math.h>
#include <stdint.h>

#define BB 4
#define TT 2048
#define CC 1024
#define HH 16
#define DD 64
#define EPS 1.1920929e-07f

// ---------------------------------------------------------------------------
// Scratch (allocation-free rule)
// ---------------------------------------------------------------------------
__device__ float g_q[BB * TT * CC];
__device__ float g_k[BB * TT * CC];
__device__ float g_v[BB * TT * CC];
__device__ float g_y[BB * TT * CC];
__device__ float g_x[BB * TT * CC];
__device__ float g_w[4 * CC * CC];

// ---------------------------------------------------------------------------
// helpers
// ---------------------------------------------------------------------------
__device__ __forceinline__ float to_tf32(float x) {
    uint32_t u;
    asm("cvt.rna.tf32.f32 %0, %1;" : "=r"(u) : "f"(x));
    return __uint_as_float(u);
}

__device__ __forceinline__ void mma_tf32(float* c, const uint32_t* a, const uint32_t* b) {
    asm volatile(
        "mma.sync.aligned.m16n8k8.row.col.f32.tf32.tf32.f32 "
        "{%0,%1,%2,%3}, {%4,%5,%6,%7}, {%8,%9}, {%0,%1,%2,%3};"
        : "+f"(c[0]), "+f"(c[1]), "+f"(c[2]), "+f"(c[3])
        : "r"(a[0]), "r"(a[1]), "r"(a[2]), "r"(a[3]), "r"(b[0]), "r"(b[1]));
}

__device__ __forceinline__ void cp16(uint32_t dst, const void* src) {
    asm volatile("cp.async.ca.shared.global [%0], [%1], 16;" :: "r"(dst), "l"(src));
}
__device__ __forceinline__ void cp_commit() {
    asm volatile("cp.async.commit_group;");
}
template <int N>
__device__ __forceinline__ void cp_wait() {
    asm volatile("cp.async.wait_group %0;" :: "n"(N));
}

// ---------------------------------------------------------------------------
// Pre-pass: tf32-round (rna) src -> dst
// ---------------------------------------------------------------------------
__global__ __launch_bounds__(256) void round_pass(
    const float* __restrict__ src, float* __restrict__ dst, int n)
{
    int i = (blockIdx.x * 256 + threadIdx.x) * 4;
    if (i < n) {
        float4 v = *(const float4*)(src + i);
        *(float4*)(dst + i) =
            make_float4(to_tf32(v.x), to_tf32(v.y), to_tf32(v.z), to_tf32(v.w));
    }
}

// ---------------------------------------------------------------------------
// GEMM NT (tf32 MMA): C[m,n] = sum_k A[m,k] * W[n,k]. Inputs pre-rounded.
// 128x128x16 tile, 256 threads (8 warps 2x4), warp tile 64x32.
// 3-stage cp.async pipeline, ONE __syncthreads per k-iter.
// blockIdx.z selects among up to 3 (W, C) pairs.
// ---------------------------------------------------------------------------
#define GBM 128
#define GBN 128
#define GBK 16
#define GPAD 20
#define GSTG (GBM * GPAD)          // floats per stage (A or W)

__global__ __launch_bounds__(256, 2) void gemm3_tf32(
    const float* __restrict__ A, const float* __restrict__ Wbase,
    float* __restrict__ C0, float* __restrict__ C1, float* __restrict__ C2,
    int M, int N, int K)
{
    extern __shared__ float sg[];
    float* As = sg;                 // 3 x 128 x 20
    float* Ws = sg + 3 * GSTG;      // 3 x 128 x 20

    const float* W = Wbase + (size_t)blockIdx.z * CC * CC;
    float* Cout    = blockIdx.z == 0 ? C0 : (blockIdx.z == 1 ? C1 : C2);

    const int tid = threadIdx.x;
    const int wid = tid >> 5;
    const int lane = tid & 31;
    const int wm = wid & 1;
    const int wn = wid >> 1;
    const int g = lane >> 2;
    const int tg = lane & 3;

    const int m0 = blockIdx.y * GBM;
    const int n0 = blockIdx.x * GBN;

    const int lr = tid >> 2;          // 0..63
    const int lc = (tid & 3) << 2;    // 0,4,8,12

    const float* a0 = &A[(size_t)(m0 + lr) * K + lc];
    const float* a1 = &A[(size_t)(m0 + lr + 64) * K + lc];
    const float* w0 = &W[(size_t)(n0 + lr) * K + lc];
    const float* w1 = &W[(size_t)(n0 + lr + 64) * K + lc];

    const uint32_t sA = (uint32_t)__cvta_generic_to_shared(As);
    const uint32_t sW = (uint32_t)__cvta_generic_to_shared(Ws);
    const uint32_t dA0 = sA + ((lr) * GPAD + lc) * 4;
    const uint32_t dA1 = sA + ((lr + 64) * GPAD + lc) * 4;
    const uint32_t dW0 = sW + ((lr) * GPAD + lc) * 4;
    const uint32_t dW1 = sW + ((lr + 64) * GPAD + lc) * 4;
    const uint32_t stgB = GSTG * 4;   // bytes per stage

    float acc[4][4][4] = {};

    const int nt = K / GBK;   // 64
    // prologue: stages 0 and 1
    #pragma unroll
    for (int s = 0; s < 2; s++) {
        const uint32_t off = s * stgB;
        const int kk = s * GBK;
        cp16(dA0 + off, a0 + kk); cp16(dA1 + off, a1 + kk);
        cp16(dW0 + off, w0 + kk); cp16(dW1 + off, w1 + kk);
        cp_commit();
    }

    int cur = 0;
    for (int kt = 0; kt < nt; kt++) {
        if (kt + 1 < nt) cp_wait<1>(); else cp_wait<0>();
        __syncthreads();

        // issue stage kt+2 (buffer shared with stage kt-1; safe post-sync)
        if (kt + 2 < nt) {
            int nxt = cur + 2; if (nxt >= 3) nxt -= 3;
            const uint32_t off = nxt * stgB;
            const int kk = (kt + 2) * GBK;
            cp16(dA0 + off, a0 + kk); cp16(dA1 + off, a1 + kk);
            cp16(dW0 + off, w0 + kk); cp16(dW1 + off, w1 + kk);
            cp_commit();
        }

        const float* Ac = As + cur * GSTG;
        const float* Wc = Ws + cur * GSTG;
        #pragma unroll
        for (int kc = 0; kc < 2; kc++) {
            const int kk = kc * 8;
            uint32_t af[4][4], bf[4][2];
            #pragma unroll
            for (int mi = 0; mi < 4; mi++) {
                int mb = wm * 64 + mi * 16;
                af[mi][0] = __float_as_uint(Ac[(mb + g    ) * GPAD + kk + tg]);
                af[mi][1] = __float_as_uint(Ac[(mb + g + 8) * GPAD + kk + tg]);
                af[mi][2] = __float_as_uint(Ac[(mb + g    ) * GPAD + kk + tg + 4]);
                af[mi][3] = __float_as_uint(Ac[(mb + g + 8) * GPAD + kk + tg + 4]);
            }
            #pragma unroll
            for (int ni = 0; ni < 4; ni++) {
                int nb = wn * 32 + ni * 8;
                bf[ni][0] = __float_as_uint(Wc[(nb + g) * GPAD + kk + tg]);
                bf[ni][1] = __float_as_uint(Wc[(nb + g) * GPAD + kk + tg + 4]);
            }
            #pragma unroll
            for (int mi = 0; mi < 4; mi++)
                #pragma unroll
                for (int ni = 0; ni < 4; ni++)
                    mma_tf32(acc[mi][ni], af[mi], bf[ni]);
        }
        cur++; if (cur == 3) cur = 0;
    }

    #pragma unroll
    for (int mi = 0; mi < 4; mi++) {
        int r = m0 + wm * 64 + mi * 16 + g;
        #pragma unroll
        for (int ni = 0; ni < 4; ni++) {
            int c = n0 + wn * 32 + ni * 8 + tg * 2;
            *(float2*)&Cout[(size_t)r * N + c] =
                make_float2(acc[mi][ni][0], acc[mi][ni][1]);
            *(float2*)&Cout[(size_t)(r + 8) * N + c] =
                make_float2(acc[mi][ni][2], acc[mi][ni][3]);
        }
    }
}

// ---------------------------------------------------------------------------
// RoPE (concat-half) + RMSnorm; emits tf32-rounded values.
// y==0: q (x 0.125 folded), y==1: k, y==2: v (round only).
// ---------------------------------------------------------------------------
__global__ __launch_bounds__(256) void rope_rms(
    float* __restrict__ q, float* __restrict__ k, float* __restrict__ v,
    const float* __restrict__ cs, const float* __restrict__ sn)
{
    const int row = blockIdx.x * 8 + (threadIdx.x >> 5);
    const int i = threadIdx.x & 31;

    if (blockIdx.y == 2) {
        float* p = v + (size_t)row * DD;
        p[i]      = to_tf32(p[i]);
        p[i + 32] = to_tf32(p[i + 32]);
        return;
    }

    const int t = (row / HH) % TT;
    float* p = (blockIdx.y == 0 ? q : k) + (size_t)row * DD;

    float x1 = p[i];
    float x2 = p[i + 32];
    float c = cs[t * 32 + i];
    float s = sn[t * 32 + i];
    float y1 = x1 * c + x2 * s;
    float y2 = -x1 * s + x2 * c;

    float ss = y1 * y1 + y2 * y2;
    #pragma unroll
    for (int o = 16; o; o >>= 1) ss += __shfl_xor_sync(0xffffffffu, ss, o);
    float r = rsqrtf(ss * (1.0f / 64.0f) + EPS);
    if (blockIdx.y == 0) r *= 0.125f;   // fold attention scale into q

    p[i]      = to_tf32(y1 * r);
    p[i + 32] = to_tf32(y2 * r);
}

// ---------------------------------------------------------------------------
// Flash attention, tf32 MMA. Br=128, Bc=64, D=64, 256 threads (8 warps).
// Ks and Vt double-buffered; ONE __syncthreads per j-tile.
// Inputs pre-rounded (q pre-scaled). Output y tf32-rounded.
// ---------------------------------------------------------------------------
#define FLD 68
#define NJT (TT / 64)

__global__ __launch_bounds__(256) void flash_tf32(
    const float* __restrict__ q, const float* __restrict__ kk,
    const float* __restrict__ vv, float* __restrict__ y)
{
    extern __shared__ float sm[];
    float* Qs = sm;                       // 128 x 68
    float* Ks = sm + 128 * FLD;           // 2 x 64 x 68
    float* Vt = sm + 256 * FLD;           // 2 x 64 x 68 (d-major)
    float* Ps = sm + 384 * FLD;           // 128 x 68

    const int tid = threadIdx.x;
    const int wid = tid >> 5;
    const int lane = tid & 31;
    const int g = lane >> 2, tg = lane & 3;

    const int bh = blockIdx.y;
    const size_t base = (size_t)(bh / HH) * TT * CC + (size_t)(bh % HH) * DD;
    const int q0 = blockIdx.x * 128;

    const int c4 = (tid & 15) << 2;   // 0..60
    const int rr = tid >> 4;          // 0..15

    const uint32_t sQ = (uint32_t)__cvta_generic_to_shared(Qs);
    const uint32_t sK = (uint32_t)__cvta_generic_to_shared(Ks);

    // Q tile + K tile 0 as one cp.async group
    #pragma unroll
    for (int t = 0; t < 8; t++) {
        int r = rr + t * 16;
        cp16(sQ + ((r * FLD + c4) * 4), &q[base + (size_t)(q0 + r) * CC + c4]);
    }
    #pragma unroll
    for (int t = 0; t < 4; t++) {
        int r = rr + t * 16;
        cp16(sK + ((r * FLD + c4) * 4), &kk[base + (size_t)r * CC + c4]);
    }
    cp_commit();

    // V tile 0 into registers
    float4 vr[4];
    #pragma unroll
    for (int t = 0; t < 4; t++)
        vr[t] = *(const float4*)&vv[base + (size_t)(rr + t * 16) * CC + c4];

    float mrow[2] = {-1e30f, -1e30f};
    float lrow[2] = {0.0f, 0.0f};
    float oacc[8][4] = {};
    const int mb = wid * 16;

    for (int jt = 0; jt < NJT; jt++) {
        const int cur = jt & 1;
        // store V regs transposed into Vt[cur] (buffer last read at jt-2: safe)
        float* Vc = Vt + cur * 64 * FLD;
        #pragma unroll
        for (int t = 0; t < 4; t++) {
            int r = rr + t * 16;
            Vc[(c4 + 0) * FLD + r] = vr[t].x;
            Vc[(c4 + 1) * FLD + r] = vr[t].y;
            Vc[(c4 + 2) * FLD + r] = vr[t].z;
            Vc[(c4 + 3) * FLD + r] = vr[t].w;
        }
        cp_wait<0>();      // K(jt) arrived (committed last iter / prologue)
        __syncthreads();   // Vt[cur] stores + K visible; all done with Ks[cur^1]

        // issue K(jt+1) into Ks[cur^1] (safe post-sync)
        if (jt + 1 < NJT) {
            const int j1 = (jt + 1) * 64;
            #pragma unroll
            for (int t = 0; t < 4; t++) {
                int r = rr + t * 16;
                cp16(sK + (((cur ^ 1) * 64 + r) * FLD + c4) * 4,
                     &kk[base + (size_t)(j1 + r) * CC + c4]);
            }
            cp_commit();
            // prefetch next V during compute
            #pragma unroll
            for (int t = 0; t < 4; t++)
                vr[t] = *(const float4*)&vv[base + (size_t)(j1 + rr + t * 16) * CC + c4];
        }

        // S = (Q*scale) K^T
        const float* Kc = Ks + cur * 64 * FLD;
        float sacc[8][4] = {};
        #pragma unroll
        for (int ks = 0; ks < 64; ks += 8) {
            uint32_t af[4];
            af[0] = __float_as_uint(Qs[(mb + g    ) * FLD + ks + tg]);
            af[1] = __float_as_uint(Qs[(mb + g + 8) * FLD + ks + tg]);
            af[2] = __float_as_uint(Qs[(mb + g    ) * FLD + ks + tg + 4]);
            af[3] = __float_as_uint(Qs[(mb + g + 8) * FLD + ks + tg + 4]);
            #pragma unroll
            for (int ni = 0; ni < 8; ni++) {
                const float* kbp = &Kc[(ni * 8 + g) * FLD + ks + tg];
                uint32_t bf[2];
                bf[0] = __float_as_uint(kbp[0]);
                bf[1] = __float_as_uint(kbp[4]);
                mma_tf32(sacc[ni], af, bf);
            }
        }

        // Online softmax
        float rmax[2] = {-1e30f, -1e30f};
        #pragma unroll
        for (int ni = 0; ni < 8; ni++) {
            rmax[0] = fmaxf(rmax[0], fmaxf(sacc[ni][0], sacc[ni][1]));
            rmax[1] = fmaxf(rmax[1], fmaxf(sacc[ni][2], sacc[ni][3]));
        }
        #pragma unroll
        for (int o = 1; o <= 2; o <<= 1) {
            rmax[0] = fmaxf(rmax[0], __shfl_xor_sync(0xffffffffu, rmax[0], o));
            rmax[1] = fmaxf(rmax[1], __shfl_xor_sync(0xffffffffu, rmax[1], o));
        }
        float nm0 = fmaxf(mrow[0], rmax[0]);
        float nm1 = fmaxf(mrow[1], rmax[1]);
        float alpha0 = __expf(mrow[0] - nm0);
        float alpha1 = __expf(mrow[1] - nm1);

        float rsum[2] = {0.0f, 0.0f};
        #pragma unroll
        for (int ni = 0; ni < 8; ni++) {
            float p0 = __expf(sacc[ni][0] - nm0);
            float p1 = __expf(sacc[ni][1] - nm0);
            float p2 = __expf(sacc[ni][2] - nm1);
            float p3 = __expf(sacc[ni][3] - nm1);
            rsum[0] += p0 + p1;
            rsum[1] += p2 + p3;
            int c = ni * 8 + tg * 2;
            Ps[(mb + g    ) * FLD + c]     = to_tf32(p0);
            Ps[(mb + g    ) * FLD + c + 1] = to_tf32(p1);
            Ps[(mb + g + 8) * FLD + c]     = to_tf32(p2);
            Ps[(mb + g + 8) * FLD + c + 1] = to_tf32(p3);
        }
        #pragma unroll
        for (int o = 1; o <= 2; o <<= 1) {
            rsum[0] += __shfl_xor_sync(0xffffffffu, rsum[0], o);
            rsum[1] += __shfl_xor_sync(0xffffffffu, rsum[1], o);
        }
        lrow[0] = lrow[0] * alpha0 + rsum[0];
        lrow[1] = lrow[1] * alpha1 + rsum[1];
        mrow[0] = nm0;
        mrow[1] = nm1;

        #pragma unroll
        for (int ni = 0; ni < 8; ni++) {
            oacc[ni][0] *= alpha0; oacc[ni][1] *= alpha0;
            oacc[ni][2] *= alpha1; oacc[ni][3] *= alpha1;
        }
        __syncwarp();   // Ps rows are warp-local

        // O += P V
        #pragma unroll
        for (int ks = 0; ks < 64; ks += 8) {
            uint32_t af[4];
            af[0] = __float_as_uint(Ps[(mb + g    ) * FLD + ks + tg]);
            af[1] = __float_as_uint(Ps[(mb + g + 8) * FLD + ks + tg]);
            af[2] = __float_as_uint(Ps[(mb + g    ) * FLD + ks + tg + 4]);
            af[3] = __float_as_uint(Ps[(mb + g + 8) * FLD + ks + tg + 4]);
            #pragma unroll
            for (int ni = 0; ni < 8; ni++) {
                const float* vbp = &Vc[(ni * 8 + g) * FLD + ks + tg];
                uint32_t bf[2];
                bf[0] = __float_as_uint(vbp[0]);
                bf[1] = __float_as_uint(vbp[4]);
                mma_tf32(oacc[ni], af, bf);
            }
        }
    }

    // Epilogue: normalize, round, write
    float inv0 = 1.0f / lrow[0];
    float inv1 = 1.0f / lrow[1];
    int r0 = q0 + mb + g;
    #pragma unroll
    for (int ni = 0; ni < 8; ni++) {
        int c = ni * 8 + tg * 2;
        *(float2*)&y[base + (size_t)r0 * CC + c] =
            make_float2(to_tf32(oacc[ni][0] * inv0), to_tf32(oacc[ni][1] * inv0));
        *(float2*)&y[base + (size_t)(r0 + 8) * CC + c] =
            make_float2(to_tf32(oacc[ni][2] * inv1), to_tf32(oacc[ni][3] * inv1));
    }
}

// ---------------------------------------------------------------------------
// Launch
// ---------------------------------------------------------------------------
extern "C" void kernel_launch(void* const* d_in, const int* in_sizes, int n_in,
                              void* d_out, int out_size)
{
    const float* x  = (const float*)d_in[0];
    const float* cs = (const float*)d_in[1];
    const float* sn = (const float*)d_in[2];
    const float* Wq = (const float*)d_in[3];
    const float* Wk = (const float*)d_in[4];
    const float* Wv = (const float*)d_in[5];
    const float* Wo = (const float*)d_in[6];
    float* out = (float*)d_out;

    float *qb, *kb, *vb, *yb, *xb, *wb;
    cudaGetSymbolAddress((void**)&qb, g_q);
    cudaGetSymbolAddress((void**)&kb, g_k);
    cudaGetSymbolAddress((void**)&vb, g_v);
    cudaGetSymbolAddress((void**)&yb, g_y);
    cudaGetSymbolAddress((void**)&xb, g_x);
    cudaGetSymbolAddress((void**)&wb, g_w);

    const int M = BB * TT, N = CC, K = CC;
    const int NX = BB * TT * CC;     // 8M
    const int NW = CC * CC;          // 1M

    // Pre-round inputs (rna) into scratch
    round_pass<<<NX / 1024, 256>>>(x, xb, NX);
    round_pass<<<NW / 1024, 256>>>(Wq, wb + 0 * NW, NW);
    round_pass<<<NW / 1024, 256>>>(Wk, wb + 1 * NW, NW);
    round_pass<<<NW / 1024, 256>>>(Wv, wb + 2 * NW, NW);
    round_pass<<<NW / 1024, 256>>>(Wo, wb + 3 * NW, NW);

    const int gsmem = 6 * GSTG * sizeof(float);   // 60 KB
    cudaFuncSetAttribute(gemm3_tf32, cudaFuncAttributeMaxDynamicSharedMemorySize, gsmem);

    // Fused QKV projections
    dim3 qkvgrid(N / GBN, M / GBM, 3);   // (8, 64, 3)
    gemm3_tf32<<<qkvgrid, 256, gsmem>>>(xb, wb, qb, kb, vb, M, N, K);

    // RoPE + RMSnorm (+v rounding)
    dim3 rgrid(BB * TT * HH / 8, 3);
    rope_rms<<<rgrid, 256>>>(qb, kb, vb, cs, sn);

    // Flash attention
    const int fsmem = (512 * FLD) * sizeof(float);   // ~136 KB
    cudaFuncSetAttribute(flash_tf32, cudaFuncAttributeMaxDynamicSharedMemorySize, fsmem);
    dim3 fgrid(TT / 128, BB * HH);   // (16, 64)
    flash_tf32<<<fgrid, 256, fsmem>>>(qb, kb, vb, yb);

    // Output projection
    dim3 ogrid(N / GBN, M / GBM, 1);
    gemm3_tf32<<<ogrid, 256, gsmem>>>(yb, wb + 3 * NW, out, out, out, M, N, K);
}

// round 7
// speedup vs baseline: 1.0983x; 1.0983x over previous
#include <cuda_runtime.h>
#include <cuda_bf16.h>
#include <math.h>
#include <stdint.h>

#define BB 4
#define TT 2048
#define CC 1024
#define HH 16
#define DD 64
#define EPS 1.1920929e-07f

// ---------------------------------------------------------------------------
// Scratch (allocation-free rule)
// ---------------------------------------------------------------------------
__device__ float g_q[BB * TT * CC];
__device__ float g_k[BB * TT * CC];
__device__ float g_v[BB * TT * CC];
__device__ float g_y[BB * TT * CC];
__device__ float g_x[BB * TT * CC];
__device__ float g_w[4 * CC * CC];

// ---------------------------------------------------------------------------
// helpers
// ---------------------------------------------------------------------------
__device__ __forceinline__ float to_tf32(float x) {
    uint32_t u;
    asm("cvt.rna.tf32.f32 %0, %1;" : "=r"(u) : "f"(x));
    return __uint_as_float(u);
}

__device__ __forceinline__ void mma_tf32(float* c, const uint32_t* a, const uint32_t* b) {
    asm volatile(
        "mma.sync.aligned.m16n8k8.row.col.f32.tf32.tf32.f32 "
        "{%0,%1,%2,%3}, {%4,%5,%6,%7}, {%8,%9}, {%0,%1,%2,%3};"
        : "+f"(c[0]), "+f"(c[1]), "+f"(c[2]), "+f"(c[3])
        : "r"(a[0]), "r"(a[1]), "r"(a[2]), "r"(a[3]), "r"(b[0]), "r"(b[1]));
}

// x4 ldmatrix: four 8x8 b16 (= 8x4 tf32) tiles, per-lane row address
__device__ __forceinline__ void ldsm4(uint32_t* r, uint32_t addr) {
    asm volatile(
        "ldmatrix.sync.aligned.m8n8.x4.shared.b16 {%0,%1,%2,%3}, [%4];"
        : "=r"(r[0]), "=r"(r[1]), "=r"(r[2]), "=r"(r[3]) : "r"(addr));
}

__device__ __forceinline__ void cp16(uint32_t dst, const void* src) {
    asm volatile("cp.async.ca.shared.global [%0], [%1], 16;" :: "r"(dst), "l"(src));
}
__device__ __forceinline__ void cp_commit() {
    asm volatile("cp.async.commit_group;");
}
template <int N>
__device__ __forceinline__ void cp_wait() {
    asm volatile("cp.async.wait_group %0;" :: "n"(N));
}

// ---------------------------------------------------------------------------
// Pre-pass: tf32-round (rna) src -> dst
// ---------------------------------------------------------------------------
__global__ __launch_bounds__(256) void round_pass(
    const float* __restrict__ src, float* __restrict__ dst, int n)
{
    int i = (blockIdx.x * 256 + threadIdx.x) * 4;
    if (i < n) {
        float4 v = *(const float4*)(src + i);
        *(float4*)(dst + i) =
            make_float4(to_tf32(v.x), to_tf32(v.y), to_tf32(v.z), to_tf32(v.w));
    }
}

// ---------------------------------------------------------------------------
// GEMM NT (tf32 MMA + ldmatrix): C[m,n] = sum_k A[m,k] * W[n,k].
// 128x128x16 tile, 256 threads (8 warps 2x4), warp tile 64x32.
// 3-stage cp.async pipeline, one __syncthreads per k-iter.
// ---------------------------------------------------------------------------
#define GBM 128
#define GBN 128
#define GBK 16
#define GPAD 20
#define GSTG (GBM * GPAD)

__global__ __launch_bounds__(256, 2) void gemm3_tf32(
    const float* __restrict__ A, const float* __restrict__ Wbase,
    float* __restrict__ C0, float* __restrict__ C1, float* __restrict__ C2,
    int M, int N, int K)
{
    extern __shared__ float sg[];
    float* As = sg;                 // 3 x 128 x 20
    float* Ws = sg + 3 * GSTG;      // 3 x 128 x 20

    const float* W = Wbase + (size_t)blockIdx.z * CC * CC;
    float* Cout    = blockIdx.z == 0 ? C0 : (blockIdx.z == 1 ? C1 : C2);

    const int tid = threadIdx.x;
    const int wid = tid >> 5;
    const int lane = tid & 31;
    const int wm = wid & 1;
    const int wn = wid >> 1;
    const int g = lane >> 2;
    const int tg = lane & 3;

    const int m0 = blockIdx.y * GBM;
    const int n0 = blockIdx.x * GBN;

    const int lr = tid >> 2;
    const int lc = (tid & 3) << 2;

    const float* a0 = &A[(size_t)(m0 + lr) * K + lc];
    const float* a1 = &A[(size_t)(m0 + lr + 64) * K + lc];
    const float* w0 = &W[(size_t)(n0 + lr) * K + lc];
    const float* w1 = &W[(size_t)(n0 + lr + 64) * K + lc];

    const uint32_t sA = (uint32_t)__cvta_generic_to_shared(As);
    const uint32_t sW = (uint32_t)__cvta_generic_to_shared(Ws);
    const uint32_t dA0 = sA + ((lr) * GPAD + lc) * 4;
    const uint32_t dA1 = sA + ((lr + 64) * GPAD + lc) * 4;
    const uint32_t dW0 = sW + ((lr) * GPAD + lc) * 4;
    const uint32_t dW1 = sW + ((lr + 64) * GPAD + lc) * 4;
    const uint32_t stgB = GSTG * 4;

    // ldmatrix per-lane row addresses
    // A x4: m0(rows g,k), m1(rows g+8,k), m2(rows g,k+4), m3(rows g+8,k+4)
    const uint32_t lmA = sA +
        (((wm * 64 + (lane & 7) + ((lane >> 3) & 1) * 8) * GPAD) + ((lane >> 4) & 1) * 4) * 4;
    // B x4: m0(n,k), m1(n,k+4), m2(n+8,k), m3(n+8,k+4)
    const uint32_t lmB = sW +
        (((wn * 32 + (lane & 7) + ((lane >> 4) & 1) * 8) * GPAD) + ((lane >> 3) & 1) * 4) * 4;

    float acc[4][4][4] = {};

    const int nt = K / GBK;   // 64
    #pragma unroll
    for (int s = 0; s < 2; s++) {
        const uint32_t off = s * stgB;
        const int kk = s * GBK;
        cp16(dA0 + off, a0 + kk); cp16(dA1 + off, a1 + kk);
        cp16(dW0 + off, w0 + kk); cp16(dW1 + off, w1 + kk);
        cp_commit();
    }

    int cur = 0;
    for (int kt = 0; kt < nt; kt++) {
        if (kt + 1 < nt) cp_wait<1>(); else cp_wait<0>();
        __syncthreads();

        if (kt + 2 < nt) {
            int nxt = cur + 2; if (nxt >= 3) nxt -= 3;
            const uint32_t off = nxt * stgB;
            const int kk = (kt + 2) * GBK;
            cp16(dA0 + off, a0 + kk); cp16(dA1 + off, a1 + kk);
            cp16(dW0 + off, w0 + kk); cp16(dW1 + off, w1 + kk);
            cp_commit();
        }

        const uint32_t aOff = lmA + cur * stgB;
        const uint32_t bOff = lmB + cur * stgB;
        #pragma unroll
        for (int kc = 0; kc < 2; kc++) {
            uint32_t af[4][4], bq[2][4];
            #pragma unroll
            for (int mi = 0; mi < 4; mi++)
                ldsm4(af[mi], aOff + mi * 16 * GPAD * 4 + kc * 32);
            #pragma unroll
            for (int nj = 0; nj < 2; nj++)
                ldsm4(bq[nj], bOff + nj * 16 * GPAD * 4 + kc * 32);
            #pragma unroll
            for (int mi = 0; mi < 4; mi++) {
                #pragma unroll
                for (int nj = 0; nj < 2; nj++) {
                    mma_tf32(acc[mi][nj * 2 + 0], af[mi], &bq[nj][0]);
                    mma_tf32(acc[mi][nj * 2 + 1], af[mi], &bq[nj][2]);
                }
            }
        }
        cur++; if (cur == 3) cur = 0;
    }

    #pragma unroll
    for (int mi = 0; mi < 4; mi++) {
        int r = m0 + wm * 64 + mi * 16 + g;
        #pragma unroll
        for (int ni = 0; ni < 4; ni++) {
            int c = n0 + wn * 32 + ni * 8 + tg * 2;
            *(float2*)&Cout[(size_t)r * N + c] =
                make_float2(acc[mi][ni][0], acc[mi][ni][1]);
            *(float2*)&Cout[(size_t)(r + 8) * N + c] =
                make_float2(acc[mi][ni][2], acc[mi][ni][3]);
        }
    }
}

// ---------------------------------------------------------------------------
// RoPE (concat-half) + RMSnorm; emits tf32-rounded values.
// ---------------------------------------------------------------------------
__global__ __launch_bounds__(256) void rope_rms(
    float* __restrict__ q, float* __restrict__ k, float* __restrict__ v,
    const float* __restrict__ cs, const float* __restrict__ sn)
{
    const int row = blockIdx.x * 8 + (threadIdx.x >> 5);
    const int i = threadIdx.x & 31;

    if (blockIdx.y == 2) {
        float* p = v + (size_t)row * DD;
        p[i]      = to_tf32(p[i]);
        p[i + 32] = to_tf32(p[i + 32]);
        return;
    }

    const int t = (row / HH) % TT;
    float* p = (blockIdx.y == 0 ? q : k) + (size_t)row * DD;

    float x1 = p[i];
    float x2 = p[i + 32];
    float c = cs[t * 32 + i];
    float s = sn[t * 32 + i];
    float y1 = x1 * c + x2 * s;
    float y2 = -x1 * s + x2 * c;

    float ss = y1 * y1 + y2 * y2;
    #pragma unroll
    for (int o = 16; o; o >>= 1) ss += __shfl_xor_sync(0xffffffffu, ss, o);
    float r = rsqrtf(ss * (1.0f / 64.0f) + EPS);
    if (blockIdx.y == 0) r *= 0.125f;

    p[i]      = to_tf32(y1 * r);
    p[i + 32] = to_tf32(y2 * r);
}

// ---------------------------------------------------------------------------
// Flash attention, tf32 MMA + ldmatrix. Br=128, Bc=64, D=64, 8 warps.
// ---------------------------------------------------------------------------
#define FLD 68
#define NJT (TT / 64)

__global__ __launch_bounds__(256) void flash_tf32(
    const float* __restrict__ q, const float* __restrict__ kk,
    const float* __restrict__ vv, float* __restrict__ y)
{
    extern __shared__ float sm[];
    float* Qs = sm;                       // 128 x 68
    float* Ks = sm + 128 * FLD;           // 2 x 64 x 68
    float* Vt = sm + 256 * FLD;           // 2 x 64 x 68 (d-major)
    float* Ps = sm + 384 * FLD;           // 128 x 68

    const int tid = threadIdx.x;
    const int wid = tid >> 5;
    const int lane = tid & 31;
    const int g = lane >> 2, tg = lane & 3;

    const int bh = blockIdx.y;
    const size_t base = (size_t)(bh / HH) * TT * CC + (size_t)(bh % HH) * DD;
    const int q0 = blockIdx.x * 128;

    const int c4 = (tid & 15) << 2;
    const int rr = tid >> 4;

    const uint32_t sQ = (uint32_t)__cvta_generic_to_shared(Qs);
    const uint32_t sK = (uint32_t)__cvta_generic_to_shared(Ks);
    const uint32_t sV = (uint32_t)__cvta_generic_to_shared(Vt);
    const uint32_t sP = (uint32_t)__cvta_generic_to_shared(Ps);

    const int mb = wid * 16;
    // ldmatrix per-lane addresses (A pattern for Q/P, B pattern for K/V)
    const uint32_t aRow = (lane & 7) + ((lane >> 3) & 1) * 8;
    const uint32_t aCol = ((lane >> 4) & 1) * 4;
    const uint32_t bRow = (lane & 7) + ((lane >> 4) & 1) * 8;
    const uint32_t bCol = ((lane >> 3) & 1) * 4;
    const uint32_t lmQ = sQ + (((mb + aRow) * FLD) + aCol) * 4;
    const uint32_t lmP = sP + (((mb + aRow) * FLD) + aCol) * 4;
    const uint32_t lmK = sK + ((bRow * FLD) + bCol) * 4;
    const uint32_t lmV = sV + ((bRow * FLD) + bCol) * 4;
    const uint32_t kBuf = 64 * FLD * 4;

    // Q tile + K tile 0
    #pragma unroll
    for (int t = 0; t < 8; t++) {
        int r = rr + t * 16;
        cp16(sQ + ((r * FLD + c4) * 4), &q[base + (size_t)(q0 + r) * CC + c4]);
    }
    #pragma unroll
    for (int t = 0; t < 4; t++) {
        int r = rr + t * 16;
        cp16(sK + ((r * FLD + c4) * 4), &kk[base + (size_t)r * CC + c4]);
    }
    cp_commit();

    float4 vr[4];
    #pragma unroll
    for (int t = 0; t < 4; t++)
        vr[t] = *(const float4*)&vv[base + (size_t)(rr + t * 16) * CC + c4];

    float mrow[2] = {-1e30f, -1e30f};
    float lrow[2] = {0.0f, 0.0f};
    float oacc[8][4] = {};

    for (int jt = 0; jt < NJT; jt++) {
        const int cur = jt & 1;
        float* Vc = Vt + cur * 64 * FLD;
        #pragma unroll
        for (int t = 0; t < 4; t++) {
            int r = rr + t * 16;
            Vc[(c4 + 0) * FLD + r] = vr[t].x;
            Vc[(c4 + 1) * FLD + r] = vr[t].y;
            Vc[(c4 + 2) * FLD + r] = vr[t].z;
            Vc[(c4 + 3) * FLD + r] = vr[t].w;
        }
        cp_wait<0>();
        __syncthreads();

        if (jt + 1 < NJT) {
            const int j1 = (jt + 1) * 64;
            #pragma unroll
            for (int t = 0; t < 4; t++) {
                int r = rr + t * 16;
                cp16(sK + (((cur ^ 1) * 64 + r) * FLD + c4) * 4,
                     &kk[base + (size_t)(j1 + r) * CC + c4]);
            }
            cp_commit();
            #pragma unroll
            for (int t = 0; t < 4; t++)
                vr[t] = *(const float4*)&vv[base + (size_t)(j1 + rr + t * 16) * CC + c4];
        }

        // S = (Q*scale) K^T
        const uint32_t kOff = lmK + cur * kBuf;
        float sacc[8][4] = {};
        #pragma unroll
        for (int kc = 0; kc < 8; kc++) {
            uint32_t af[4];
            ldsm4(af, lmQ + kc * 32);
            #pragma unroll
            for (int nj = 0; nj < 4; nj++) {
                uint32_t bq[4];
                ldsm4(bq, kOff + nj * 16 * FLD * 4 + kc * 32);
                mma_tf32(sacc[nj * 2 + 0], af, &bq[0]);
                mma_tf32(sacc[nj * 2 + 1], af, &bq[2]);
            }
        }

        // Online softmax
        float rmax[2] = {-1e30f, -1e30f};
        #pragma unroll
        for (int ni = 0; ni < 8; ni++) {
            rmax[0] = fmaxf(rmax[0], fmaxf(sacc[ni][0], sacc[ni][1]));
            rmax[1] = fmaxf(rmax[1], fmaxf(sacc[ni][2], sacc[ni][3]));
        }
        #pragma unroll
        for (int o = 1; o <= 2; o <<= 1) {
            rmax[0] = fmaxf(rmax[0], __shfl_xor_sync(0xffffffffu, rmax[0], o));
            rmax[1] = fmaxf(rmax[1], __shfl_xor_sync(0xffffffffu, rmax[1], o));
        }
        float nm0 = fmaxf(mrow[0], rmax[0]);
        float nm1 = fmaxf(mrow[1], rmax[1]);
        float alpha0 = __expf(mrow[0] - nm0);
        float alpha1 = __expf(mrow[1] - nm1);

        float rsum[2] = {0.0f, 0.0f};
        #pragma unroll
        for (int ni = 0; ni < 8; ni++) {
            float p0 = __expf(sacc[ni][0] - nm0);
            float p1 = __expf(sacc[ni][1] - nm0);
            float p2 = __expf(sacc[ni][2] - nm1);
            float p3 = __expf(sacc[ni][3] - nm1);
            rsum[0] += p0 + p1;
            rsum[1] += p2 + p3;
            int c = ni * 8 + tg * 2;
            Ps[(mb + g    ) * FLD + c]     = to_tf32(p0);
            Ps[(mb + g    ) * FLD + c + 1] = to_tf32(p1);
            Ps[(mb + g + 8) * FLD + c]     = to_tf32(p2);
            Ps[(mb + g + 8) * FLD + c + 1] = to_tf32(p3);
        }
        #pragma unroll
        for (int o = 1; o <= 2; o <<= 1) {
            rsum[0] += __shfl_xor_sync(0xffffffffu, rsum[0], o);
            rsum[1] += __shfl_xor_sync(0xffffffffu, rsum[1], o);
        }
        lrow[0] = lrow[0] * alpha0 + rsum[0];
        lrow[1] = lrow[1] * alpha1 + rsum[1];
        mrow[0] = nm0;
        mrow[1] = nm1;

        #pragma unroll
        for (int ni = 0; ni < 8; ni++) {
            oacc[ni][0] *= alpha0; oacc[ni][1] *= alpha0;
            oacc[ni][2] *= alpha1; oacc[ni][3] *= alpha1;
        }
        __syncwarp();   // Ps rows are warp-local

        // O += P V
        const uint32_t vOff = lmV + cur * kBuf;
        #pragma unroll
        for (int kc = 0; kc < 8; kc++) {
            uint32_t af[4];
            ldsm4(af, lmP + kc * 32);
            #pragma unroll
            for (int nj = 0; nj < 4; nj++) {
                uint32_t bq[4];
                ldsm4(bq, vOff + nj * 16 * FLD * 4 + kc * 32);
                mma_tf32(oacc[nj * 2 + 0], af, &bq[0]);
                mma_tf32(oacc[nj * 2 + 1], af, &bq[2]);
            }
        }
    }

    // Epilogue
    float inv0 = 1.0f / lrow[0];
    float inv1 = 1.0f / lrow[1];
    int r0 = q0 + mb + g;
    #pragma unroll
    for (int ni = 0; ni < 8; ni++) {
        int c = ni * 8 + tg * 2;
        *(float2*)&y[base + (size_t)r0 * CC + c] =
            make_float2(to_tf32(oacc[ni][0] * inv0), to_tf32(oacc[ni][1] * inv0));
        *(float2*)&y[base + (size_t)(r0 + 8) * CC + c] =
            make_float2(to_tf32(oacc[ni][2] * inv1), to_tf32(oacc[ni][3] * inv1));
    }
}

// ---------------------------------------------------------------------------
// Launch
// ---------------------------------------------------------------------------
extern "C" void kernel_launch(void* const* d_in, const int* in_sizes, int n_in,
                              void* d_out, int out_size)
{
    const float* x  = (const float*)d_in[0];
    const float* cs = (const float*)d_in[1];
    const float* sn = (const float*)d_in[2];
    const float* Wq = (const float*)d_in[3];
    const float* Wk = (const float*)d_in[4];
    const float* Wv = (const float*)d_in[5];
    const float* Wo = (const float*)d_in[6];
    float* out = (float*)d_out;

    float *qb, *kb, *vb, *yb, *xb, *wb;
    cudaGetSymbolAddress((void**)&qb, g_q);
    cudaGetSymbolAddress((void**)&kb, g_k);
    cudaGetSymbolAddress((void**)&vb, g_v);
    cudaGetSymbolAddress((void**)&yb, g_y);
    cudaGetSymbolAddress((void**)&xb, g_x);
    cudaGetSymbolAddress((void**)&wb, g_w);

    const int M = BB * TT, N = CC, K = CC;
    const int NX = BB * TT * CC;
    const int NW = CC * CC;

    round_pass<<<NX / 1024, 256>>>(x, xb, NX);
    round_pass<<<NW / 1024, 256>>>(Wq, wb + 0 * NW, NW);
    round_pass<<<NW / 1024, 256>>>(Wk, wb + 1 * NW, NW);
    round_pass<<<NW / 1024, 256>>>(Wv, wb + 2 * NW, NW);
    round_pass<<<NW / 1024, 256>>>(Wo, wb + 3 * NW, NW);

    const int gsmem = 6 * GSTG * sizeof(float);   // 60 KB
    cudaFuncSetAttribute(gemm3_tf32, cudaFuncAttributeMaxDynamicSharedMemorySize, gsmem);

    dim3 qkvgrid(N / GBN, M / GBM, 3);
    gemm3_tf32<<<qkvgrid, 256, gsmem>>>(xb, wb, qb, kb, vb, M, N, K);

    dim3 rgrid(BB * TT * HH / 8, 3);
    rope_rms<<<rgrid, 256>>>(qb, kb, vb, cs, sn);

    const int fsmem = (512 * FLD) * sizeof(float);   // ~136 KB
    cudaFuncSetAttribute(flash_tf32, cudaFuncAttributeMaxDynamicSharedMemorySize, fsmem);
    dim3 fgrid(TT / 128, BB * HH);
    flash_tf32<<<fgrid, 256, fsmem>>>(qb, kb, vb, yb);

    dim3 ogrid(N / GBN, M / GBM, 1);
    gemm3_tf32<<<ogrid, 256, gsmem>>>(yb, wb + 3 * NW, out, out, out, M, N, K);
}

// round 8
// speedup vs baseline: 1.1230x; 1.0224x over previous
#include <cuda_runtime.h>
#include <cuda_bf16.h>
#include <math.h>
#include <stdint.h>

#define BB 4
#define TT 2048
#define CC 1024
#define HH 16
#define DD 64
#define EPS 1.1920929e-07f

// ---------------------------------------------------------------------------
// Scratch (allocation-free rule)
// ---------------------------------------------------------------------------
__device__ float g_q[BB * TT * CC];
__device__ float g_k[BB * TT * CC];
__device__ float g_v[BB * TT * CC];
__device__ float g_y[BB * TT * CC];
__device__ float g_x[BB * TT * CC];
__device__ float g_w[4 * CC * CC];

// ---------------------------------------------------------------------------
// helpers
// ---------------------------------------------------------------------------
__device__ __forceinline__ float to_tf32(float x) {
    uint32_t u;
    asm("cvt.rna.tf32.f32 %0, %1;" : "=r"(u) : "f"(x));
    return __uint_as_float(u);
}

__device__ __forceinline__ void mma_tf32(float* c, const uint32_t* a, const uint32_t* b) {
    asm volatile(
        "mma.sync.aligned.m16n8k8.row.col.f32.tf32.tf32.f32 "
        "{%0,%1,%2,%3}, {%4,%5,%6,%7}, {%8,%9}, {%0,%1,%2,%3};"
        : "+f"(c[0]), "+f"(c[1]), "+f"(c[2]), "+f"(c[3])
        : "r"(a[0]), "r"(a[1]), "r"(a[2]), "r"(a[3]), "r"(b[0]), "r"(b[1]));
}

__device__ __forceinline__ void ldsm4(uint32_t* r, uint32_t addr) {
    asm volatile(
        "ldmatrix.sync.aligned.m8n8.x4.shared.b16 {%0,%1,%2,%3}, [%4];"
        : "=r"(r[0]), "=r"(r[1]), "=r"(r[2]), "=r"(r[3]) : "r"(addr));
}

__device__ __forceinline__ void cp16(uint32_t dst, const void* src) {
    asm volatile("cp.async.ca.shared.global [%0], [%1], 16;" :: "r"(dst), "l"(src));
}
__device__ __forceinline__ void cp_commit() {
    asm volatile("cp.async.commit_group;");
}
template <int N>
__device__ __forceinline__ void cp_wait() {
    asm volatile("cp.async.wait_group %0;" :: "n"(N));
}

// ---------------------------------------------------------------------------
// Pre-pass: tf32-round (rna) src -> dst
// ---------------------------------------------------------------------------
__global__ __launch_bounds__(256) void round_pass(
    const float* __restrict__ src, float* __restrict__ dst, int n)
{
    int i = (blockIdx.x * 256 + threadIdx.x) * 4;
    if (i < n) {
        float4 v = *(const float4*)(src + i);
        *(float4*)(dst + i) =
            make_float4(to_tf32(v.x), to_tf32(v.y), to_tf32(v.z), to_tf32(v.w));
    }
}

// ---------------------------------------------------------------------------
// GEMM NT (tf32 MMA + ldmatrix): C[m,n] = sum_k A[m,k] * W[n,k].
// 128x128x16 tile, 256 threads (8 warps 2x4), warp tile 64x32.
// 3-stage cp.async pipeline, one __syncthreads per k-iter.
// z==2 (v projection): tf32-round output at store.
// ---------------------------------------------------------------------------
#define GBM 128
#define GBN 128
#define GBK 16
#define GPAD 20
#define GSTG (GBM * GPAD)

__global__ __launch_bounds__(256, 2) void gemm3_tf32(
    const float* __restrict__ A, const float* __restrict__ Wbase,
    float* __restrict__ C0, float* __restrict__ C1, float* __restrict__ C2,
    int M, int N, int K, int roundZ)
{
    extern __shared__ float sg[];
    float* As = sg;
    float* Ws = sg + 3 * GSTG;

    const float* W = Wbase + (size_t)blockIdx.z * CC * CC;
    float* Cout    = blockIdx.z == 0 ? C0 : (blockIdx.z == 1 ? C1 : C2);
    const bool doRound = ((int)blockIdx.z == roundZ);

    const int tid = threadIdx.x;
    const int wid = tid >> 5;
    const int lane = tid & 31;
    const int wm = wid & 1;
    const int wn = wid >> 1;
    const int g = lane >> 2;
    const int tg = lane & 3;

    const int m0 = blockIdx.y * GBM;
    const int n0 = blockIdx.x * GBN;

    const int lr = tid >> 2;
    const int lc = (tid & 3) << 2;

    const float* a0 = &A[(size_t)(m0 + lr) * K + lc];
    const float* a1 = &A[(size_t)(m0 + lr + 64) * K + lc];
    const float* w0 = &W[(size_t)(n0 + lr) * K + lc];
    const float* w1 = &W[(size_t)(n0 + lr + 64) * K + lc];

    const uint32_t sA = (uint32_t)__cvta_generic_to_shared(As);
    const uint32_t sW = (uint32_t)__cvta_generic_to_shared(Ws);
    const uint32_t dA0 = sA + ((lr) * GPAD + lc) * 4;
    const uint32_t dA1 = sA + ((lr + 64) * GPAD + lc) * 4;
    const uint32_t dW0 = sW + ((lr) * GPAD + lc) * 4;
    const uint32_t dW1 = sW + ((lr + 64) * GPAD + lc) * 4;
    const uint32_t stgB = GSTG * 4;

    const uint32_t lmA = sA +
        (((wm * 64 + (lane & 7) + ((lane >> 3) & 1) * 8) * GPAD) + ((lane >> 4) & 1) * 4) * 4;
    const uint32_t lmB = sW +
        (((wn * 32 + (lane & 7) + ((lane >> 4) & 1) * 8) * GPAD) + ((lane >> 3) & 1) * 4) * 4;

    float acc[4][4][4] = {};

    const int nt = K / GBK;
    #pragma unroll
    for (int s = 0; s < 2; s++) {
        const uint32_t off = s * stgB;
        const int kk = s * GBK;
        cp16(dA0 + off, a0 + kk); cp16(dA1 + off, a1 + kk);
        cp16(dW0 + off, w0 + kk); cp16(dW1 + off, w1 + kk);
        cp_commit();
    }

    int cur = 0;
    for (int kt = 0; kt < nt; kt++) {
        if (kt + 1 < nt) cp_wait<1>(); else cp_wait<0>();
        __syncthreads();

        if (kt + 2 < nt) {
            int nxt = cur + 2; if (nxt >= 3) nxt -= 3;
            const uint32_t off = nxt * stgB;
            const int kk = (kt + 2) * GBK;
            cp16(dA0 + off, a0 + kk); cp16(dA1 + off, a1 + kk);
            cp16(dW0 + off, w0 + kk); cp16(dW1 + off, w1 + kk);
            cp_commit();
        }

        const uint32_t aOff = lmA + cur * stgB;
        const uint32_t bOff = lmB + cur * stgB;
        #pragma unroll
        for (int kc = 0; kc < 2; kc++) {
            uint32_t af[4][4], bq[2][4];
            #pragma unroll
            for (int mi = 0; mi < 4; mi++)
                ldsm4(af[mi], aOff + mi * 16 * GPAD * 4 + kc * 32);
            #pragma unroll
            for (int nj = 0; nj < 2; nj++)
                ldsm4(bq[nj], bOff + nj * 16 * GPAD * 4 + kc * 32);
            #pragma unroll
            for (int mi = 0; mi < 4; mi++) {
                #pragma unroll
                for (int nj = 0; nj < 2; nj++) {
                    mma_tf32(acc[mi][nj * 2 + 0], af[mi], &bq[nj][0]);
                    mma_tf32(acc[mi][nj * 2 + 1], af[mi], &bq[nj][2]);
                }
            }
        }
        cur++; if (cur == 3) cur = 0;
    }

    #pragma unroll
    for (int mi = 0; mi < 4; mi++) {
        int r = m0 + wm * 64 + mi * 16 + g;
        #pragma unroll
        for (int ni = 0; ni < 4; ni++) {
            int c = n0 + wn * 32 + ni * 8 + tg * 2;
            float v0 = acc[mi][ni][0], v1 = acc[mi][ni][1];
            float v2 = acc[mi][ni][2], v3 = acc[mi][ni][3];
            if (doRound) {
                v0 = to_tf32(v0); v1 = to_tf32(v1);
                v2 = to_tf32(v2); v3 = to_tf32(v3);
            }
            *(float2*)&Cout[(size_t)r * N + c]       = make_float2(v0, v1);
            *(float2*)&Cout[(size_t)(r + 8) * N + c] = make_float2(v2, v3);
        }
    }
}

// ---------------------------------------------------------------------------
// RoPE (concat-half) + RMSnorm; emits tf32-rounded values. q: 0.125 folded.
// ---------------------------------------------------------------------------
__global__ __launch_bounds__(256) void rope_rms(
    float* __restrict__ q, float* __restrict__ k,
    const float* __restrict__ cs, const float* __restrict__ sn)
{
    const int row = blockIdx.x * 8 + (threadIdx.x >> 5);
    const int i = threadIdx.x & 31;
    const int t = (row / HH) % TT;
    float* p = (blockIdx.y == 0 ? q : k) + (size_t)row * DD;

    float x1 = p[i];
    float x2 = p[i + 32];
    float c = cs[t * 32 + i];
    float s = sn[t * 32 + i];
    float y1 = x1 * c + x2 * s;
    float y2 = -x1 * s + x2 * c;

    float ss = y1 * y1 + y2 * y2;
    #pragma unroll
    for (int o = 16; o; o >>= 1) ss += __shfl_xor_sync(0xffffffffu, ss, o);
    float r = rsqrtf(ss * (1.0f / 64.0f) + EPS);
    if (blockIdx.y == 0) r *= 0.125f;

    p[i]      = to_tf32(y1 * r);
    p[i + 32] = to_tf32(y2 * r);
}

// ---------------------------------------------------------------------------
// Flash attention, tf32 MMA + ldmatrix. Br=128, Bc=64, D=64, 8 warps.
// Single-buffered K/V tiles, 104 KB smem -> 2 CTAs/SM.
// ---------------------------------------------------------------------------
#define FLD 68
#define NJT (TT / 64)

__global__ __launch_bounds__(256, 2) void flash_tf32(
    const float* __restrict__ q, const float* __restrict__ kk,
    const float* __restrict__ vv, float* __restrict__ y)
{
    extern __shared__ float sm[];
    float* Qs = sm;                       // 128 x 68
    float* Ks = sm + 128 * FLD;           // 64 x 68
    float* Vt = sm + 192 * FLD;           // 64 x 68 (d-major)
    float* Ps = sm + 256 * FLD;           // 128 x 68

    const int tid = threadIdx.x;
    const int wid = tid >> 5;
    const int lane = tid & 31;
    const int g = lane >> 2, tg = lane & 3;

    const int bh = blockIdx.y;
    const size_t base = (size_t)(bh / HH) * TT * CC + (size_t)(bh % HH) * DD;
    const int q0 = blockIdx.x * 128;

    const int c4 = (tid & 15) << 2;
    const int rr = tid >> 4;

    const uint32_t sQ = (uint32_t)__cvta_generic_to_shared(Qs);
    const uint32_t sK = (uint32_t)__cvta_generic_to_shared(Ks);
    const uint32_t sV = (uint32_t)__cvta_generic_to_shared(Vt);
    const uint32_t sP = (uint32_t)__cvta_generic_to_shared(Ps);

    const int mb = wid * 16;
    const uint32_t aRow = (lane & 7) + ((lane >> 3) & 1) * 8;
    const uint32_t aCol = ((lane >> 4) & 1) * 4;
    const uint32_t bRow = (lane & 7) + ((lane >> 4) & 1) * 8;
    const uint32_t bCol = ((lane >> 3) & 1) * 4;
    const uint32_t lmQ = sQ + (((mb + aRow) * FLD) + aCol) * 4;
    const uint32_t lmP = sP + (((mb + aRow) * FLD) + aCol) * 4;
    const uint32_t lmK = sK + ((bRow * FLD) + bCol) * 4;
    const uint32_t lmV = sV + ((bRow * FLD) + bCol) * 4;

    // Q tile + K tile 0 via cp.async (one group)
    #pragma unroll
    for (int t = 0; t < 8; t++) {
        int r = rr + t * 16;
        cp16(sQ + ((r * FLD + c4) * 4), &q[base + (size_t)(q0 + r) * CC + c4]);
    }
    #pragma unroll
    for (int t = 0; t < 4; t++) {
        int r = rr + t * 16;
        cp16(sK + ((r * FLD + c4) * 4), &kk[base + (size_t)r * CC + c4]);
    }
    cp_commit();

    // V tile 0 into registers
    float4 vr[4];
    #pragma unroll
    for (int t = 0; t < 4; t++)
        vr[t] = *(const float4*)&vv[base + (size_t)(rr + t * 16) * CC + c4];

    float mrow[2] = {-1e30f, -1e30f};
    float lrow[2] = {0.0f, 0.0f};
    float oacc[8][4] = {};

    for (int jt = 0; jt < NJT; jt++) {
        // store V regs transposed into Vt (all readers finished at prev end-sync)
        #pragma unroll
        for (int t = 0; t < 4; t++) {
            int r = rr + t * 16;
            Vt[(c4 + 0) * FLD + r] = vr[t].x;
            Vt[(c4 + 1) * FLD + r] = vr[t].y;
            Vt[(c4 + 2) * FLD + r] = vr[t].z;
            Vt[(c4 + 3) * FLD + r] = vr[t].w;
        }
        cp_wait<0>();      // K(jt) arrived
        __syncthreads();   // K + Vt visible to all

        // S = (Q*scale) K^T
        float sacc[8][4] = {};
        #pragma unroll
        for (int kc = 0; kc < 8; kc++) {
            uint32_t af[4];
            ldsm4(af, lmQ + kc * 32);
            #pragma unroll
            for (int nj = 0; nj < 4; nj++) {
                uint32_t bq[4];
                ldsm4(bq, lmK + nj * 16 * FLD * 4 + kc * 32);
                mma_tf32(sacc[nj * 2 + 0], af, &bq[0]);
                mma_tf32(sacc[nj * 2 + 1], af, &bq[2]);
            }
        }

        // Online softmax
        float rmax[2] = {-1e30f, -1e30f};
        #pragma unroll
        for (int ni = 0; ni < 8; ni++) {
            rmax[0] = fmaxf(rmax[0], fmaxf(sacc[ni][0], sacc[ni][1]));
            rmax[1] = fmaxf(rmax[1], fmaxf(sacc[ni][2], sacc[ni][3]));
        }
        #pragma unroll
        for (int o = 1; o <= 2; o <<= 1) {
            rmax[0] = fmaxf(rmax[0], __shfl_xor_sync(0xffffffffu, rmax[0], o));
            rmax[1] = fmaxf(rmax[1], __shfl_xor_sync(0xffffffffu, rmax[1], o));
        }
        float nm0 = fmaxf(mrow[0], rmax[0]);
        float nm1 = fmaxf(mrow[1], rmax[1]);
        float alpha0 = __expf(mrow[0] - nm0);
        float alpha1 = __expf(mrow[1] - nm1);

        float rsum[2] = {0.0f, 0.0f};
        #pragma unroll
        for (int ni = 0; ni < 8; ni++) {
            float p0 = __expf(sacc[ni][0] - nm0);
            float p1 = __expf(sacc[ni][1] - nm0);
            float p2 = __expf(sacc[ni][2] - nm1);
            float p3 = __expf(sacc[ni][3] - nm1);
            rsum[0] += p0 + p1;
            rsum[1] += p2 + p3;
            int c = ni * 8 + tg * 2;
            Ps[(mb + g    ) * FLD + c]     = to_tf32(p0);
            Ps[(mb + g    ) * FLD + c + 1] = to_tf32(p1);
            Ps[(mb + g + 8) * FLD + c]     = to_tf32(p2);
            Ps[(mb + g + 8) * FLD + c + 1] = to_tf32(p3);
        }
        #pragma unroll
        for (int o = 1; o <= 2; o <<= 1) {
            rsum[0] += __shfl_xor_sync(0xffffffffu, rsum[0], o);
            rsum[1] += __shfl_xor_sync(0xffffffffu, rsum[1], o);
        }
        lrow[0] = lrow[0] * alpha0 + rsum[0];
        lrow[1] = lrow[1] * alpha1 + rsum[1];
        mrow[0] = nm0;
        mrow[1] = nm1;

        #pragma unroll
        for (int ni = 0; ni < 8; ni++) {
            oacc[ni][0] *= alpha0; oacc[ni][1] *= alpha0;
            oacc[ni][2] *= alpha1; oacc[ni][3] *= alpha1;
        }
        __syncwarp();   // Ps rows are warp-local

        // O += P V
        #pragma unroll
        for (int kc = 0; kc < 8; kc++) {
            uint32_t af[4];
            ldsm4(af, lmP + kc * 32);
            #pragma unroll
            for (int nj = 0; nj < 4; nj++) {
                uint32_t bq[4];
                ldsm4(bq, lmV + nj * 16 * FLD * 4 + kc * 32);
                mma_tf32(oacc[nj * 2 + 0], af, &bq[0]);
                mma_tf32(oacc[nj * 2 + 1], af, &bq[2]);
            }
        }

        __syncthreads();   // all warps done reading Ks/Vt
        if (jt + 1 < NJT) {
            const int j1 = (jt + 1) * 64;
            #pragma unroll
            for (int t = 0; t < 4; t++) {
                int r = rr + t * 16;
                cp16(sK + ((r * FLD + c4) * 4),
                     &kk[base + (size_t)(j1 + r) * CC + c4]);
            }
            cp_commit();
            #pragma unroll
            for (int t = 0; t < 4; t++)
                vr[t] = *(const float4*)&vv[base + (size_t)(j1 + rr + t * 16) * CC + c4];
        }
    }

    // Epilogue
    float inv0 = 1.0f / lrow[0];
    float inv1 = 1.0f / lrow[1];
    int r0 = q0 + mb + g;
    #pragma unroll
    for (int ni = 0; ni < 8; ni++) {
        int c = ni * 8 + tg * 2;
        *(float2*)&y[base + (size_t)r0 * CC + c] =
            make_float2(to_tf32(oacc[ni][0] * inv0), to_tf32(oacc[ni][1] * inv0));
        *(float2*)&y[base + (size_t)(r0 + 8) * CC + c] =
            make_float2(to_tf32(oacc[ni][2] * inv1), to_tf32(oacc[ni][3] * inv1));
    }
}

// ---------------------------------------------------------------------------
// Launch
// ---------------------------------------------------------------------------
extern "C" void kernel_launch(void* const* d_in, const int* in_sizes, int n_in,
                              void* d_out, int out_size)
{
    const float* x  = (const float*)d_in[0];
    const float* cs = (const float*)d_in[1];
    const float* sn = (const float*)d_in[2];
    const float* Wq = (const float*)d_in[3];
    const float* Wk = (const float*)d_in[4];
    const float* Wv = (const float*)d_in[5];
    const float* Wo = (const float*)d_in[6];
    float* out = (float*)d_out;

    float *qb, *kb, *vb, *yb, *xb, *wb;
    cudaGetSymbolAddress((void**)&qb, g_q);
    cudaGetSymbolAddress((void**)&kb, g_k);
    cudaGetSymbolAddress((void**)&vb, g_v);
    cudaGetSymbolAddress((void**)&yb, g_y);
    cudaGetSymbolAddress((void**)&xb, g_x);
    cudaGetSymbolAddress((void**)&wb, g_w);

    const int M = BB * TT, N = CC, K = CC;
    const int NX = BB * TT * CC;
    const int NW = CC * CC;

    round_pass<<<NX / 1024, 256>>>(x, xb, NX);
    round_pass<<<NW / 1024, 256>>>(Wq, wb + 0 * NW, NW);
    round_pass<<<NW / 1024, 256>>>(Wk, wb + 1 * NW, NW);
    round_pass<<<NW / 1024, 256>>>(Wv, wb + 2 * NW, NW);
    round_pass<<<NW / 1024, 256>>>(Wo, wb + 3 * NW, NW);

    const int gsmem = 6 * GSTG * sizeof(float);   // 60 KB
    cudaFuncSetAttribute(gemm3_tf32, cudaFuncAttributeMaxDynamicSharedMemorySize, gsmem);

    // QKV: round v (z==2) at epilogue
    dim3 qkvgrid(N / GBN, M / GBM, 3);
    gemm3_tf32<<<qkvgrid, 256, gsmem>>>(xb, wb, qb, kb, vb, M, N, K, 2);

    dim3 rgrid(BB * TT * HH / 8, 2);
    rope_rms<<<rgrid, 256>>>(qb, kb, cs, sn);

    const int fsmem = (384 * FLD) * sizeof(float);   // ~104.4 KB
    cudaFuncSetAttribute(flash_tf32, cudaFuncAttributeMaxDynamicSharedMemorySize, fsmem);
    dim3 fgrid(TT / 128, BB * HH);
    flash_tf32<<<fgrid, 256, fsmem>>>(qb, kb, vb, yb);

    dim3 ogrid(N / GBN, M / GBM, 1);
    gemm3_tf32<<<ogrid, 256, gsmem>>>(yb, wb + 3 * NW, out, out, out, M, N, K, -1);
}

// round 10
// speedup vs baseline: 2.0276x; 1.8056x over previous
#include <cuda_runtime.h>
#include <cuda_fp16.h>
#include <math.h>
#include <stdint.h>

#define BB 4
#define TT 2048
#define CC 1024
#define HH 16
#define DD 64
#define EPS 1.1920929e-07f

// ---------------------------------------------------------------------------
// Scratch (allocation-free rule)
// ---------------------------------------------------------------------------
__device__ float  g_qf[BB * TT * CC];     // gemm q output (fp32, pre-rope)
__device__ float  g_kf[BB * TT * CC];     // gemm k output (fp32, pre-rope)
__device__ __half h_x[BB * TT * CC];      // fp16 x
__device__ __half h_w[4 * CC * CC];       // fp16 weights
__device__ __half h_q[BB * TT * CC];      // fp16 q (post rope, x0.125)
__device__ __half h_k[BB * TT * CC];      // fp16 k (post rope)
__device__ __half h_v[BB * TT * CC];      // fp16 v
__device__ __half h_y[BB * TT * CC];      // fp16 attention output

// ---------------------------------------------------------------------------
// helpers
// ---------------------------------------------------------------------------
__device__ __forceinline__ void mma_f16(float* c, const uint32_t* a, const uint32_t* b) {
    asm volatile(
        "mma.sync.aligned.m16n8k16.row.col.f32.f16.f16.f32 "
        "{%0,%1,%2,%3}, {%4,%5,%6,%7}, {%8,%9}, {%0,%1,%2,%3};"
        : "+f"(c[0]), "+f"(c[1]), "+f"(c[2]), "+f"(c[3])
        : "r"(a[0]), "r"(a[1]), "r"(a[2]), "r"(a[3]), "r"(b[0]), "r"(b[1]));
}

__device__ __forceinline__ void ldsm4(uint32_t* r, uint32_t addr) {
    asm volatile(
        "ldmatrix.sync.aligned.m8n8.x4.shared.b16 {%0,%1,%2,%3}, [%4];"
        : "=r"(r[0]), "=r"(r[1]), "=r"(r[2]), "=r"(r[3]) : "r"(addr));
}
__device__ __forceinline__ void ldsm4t(uint32_t* r, uint32_t addr) {
    asm volatile(
        "ldmatrix.sync.aligned.m8n8.x4.trans.shared.b16 {%0,%1,%2,%3}, [%4];"
        : "=r"(r[0]), "=r"(r[1]), "=r"(r[2]), "=r"(r[3]) : "r"(addr));
}

__device__ __forceinline__ void cp16(uint32_t dst, const void* src) {
    asm volatile("cp.async.ca.shared.global [%0], [%1], 16;" :: "r"(dst), "l"(src));
}
__device__ __forceinline__ void cp_commit() {
    asm volatile("cp.async.commit_group;");
}
template <int N>
__device__ __forceinline__ void cp_wait() {
    asm volatile("cp.async.wait_group %0;" :: "n"(N));
}

// ---------------------------------------------------------------------------
// Pre-pass: fp32 -> fp16 (rn)
// ---------------------------------------------------------------------------
__global__ __launch_bounds__(256) void cvt_pass(
    const float* __restrict__ src, __half* __restrict__ dst, int n)
{
    int i = (blockIdx.x * 256 + threadIdx.x) * 4;
    if (i < n) {
        float4 v = *(const float4*)(src + i);
        *(__half2*)(dst + i)     = __floats2half2_rn(v.x, v.y);
        *(__half2*)(dst + i + 2) = __floats2half2_rn(v.z, v.w);
    }
}

// ---------------------------------------------------------------------------
// GEMM NT (fp16 MMA m16n8k16 + ldmatrix): C[m,n] = sum_k A[m,k]*W[n,k].
// 128x128 tile, K-chunks of 32 halves, 256 threads (8 warps 2x4),
// warp tile 64x32, 3-stage cp.async pipeline.
// z==0 -> Cf0 (fp32), z==1 -> Cf1 (fp32), z==2 -> Ch2 (fp16, v path).
// ---------------------------------------------------------------------------
#define GCH 32                 // K halves per chunk
#define NCH (CC / GCH)         // 32
#define GPADH 40               // halves per smem row (32 + 8 pad)
#define HSTG_B (128 * GPADH * 2)   // 10240 bytes per operand stage

__global__ __launch_bounds__(256, 2) void gemm_f16(
    const __half* __restrict__ A, const __half* __restrict__ Wbase,
    float* __restrict__ Cf0, float* __restrict__ Cf1, __half* __restrict__ Ch2)
{
    extern __shared__ __half sg[];
    const uint32_t sA = (uint32_t)__cvta_generic_to_shared(sg);
    const uint32_t sW = sA + 3 * HSTG_B;

    const int z = blockIdx.z;
    const __half* W = Wbase + (size_t)z * CC * CC;

    const int tid = threadIdx.x;
    const int wid = tid >> 5;
    const int lane = tid & 31;
    const int wm = wid & 1;
    const int wn = wid >> 1;
    const int g = lane >> 2;
    const int tg = lane & 3;

    const int m0 = blockIdx.y * 128;
    const int n0 = blockIdx.x * 128;

    const __half* Arow = A + (size_t)m0 * CC;
    const __half* Wrow = W + (size_t)n0 * CC;

    // ldmatrix per-lane bases (A pattern / B pattern), byte addresses
    const uint32_t aRow = (lane & 7) + ((lane >> 3) & 1) * 8;
    const uint32_t aCol = ((lane >> 4) & 1) * 8;          // halves
    const uint32_t bRow = (lane & 7) + ((lane >> 4) & 1) * 8;
    const uint32_t bCol = ((lane >> 3) & 1) * 8;
    const uint32_t lmA = sA + ((wm * 64 + aRow) * GPADH + aCol) * 2;
    const uint32_t lmB = sW + ((wn * 32 + bRow) * GPADH + bCol) * 2;

    float acc[4][4][4] = {};

    // staging: per thread 2 cp16 for A + 2 for W per stage
    const int r0s = (tid * 2) >> 2;          // row (0..127)
    const int u0s = (tid * 2) & 3;           // unit (0 or 2)

    auto stage = [&](int chunk, int buf) {
        const int col = chunk * GCH;
        #pragma unroll
        for (int t = 0; t < 2; t++) {
            const int u = u0s + t;
            const uint32_t d = (uint32_t)buf * HSTG_B + (uint32_t)(r0s * GPADH + u * 8) * 2;
            cp16(sA + d, Arow + (size_t)r0s * CC + col + u * 8);
            cp16(sW + d, Wrow + (size_t)r0s * CC + col + u * 8);
        }
        cp_commit();
    };

    stage(0, 0);
    stage(1, 1);

    int cur = 0;
    for (int i = 0; i < NCH; i++) {
        if (i + 1 < NCH) cp_wait<1>(); else cp_wait<0>();
        __syncthreads();

        if (i + 2 < NCH) {
            int nxt = cur + 2; if (nxt >= 3) nxt -= 3;
            stage(i + 2, nxt);
        }

        const uint32_t aOff = lmA + (uint32_t)cur * HSTG_B;
        const uint32_t bOff = lmB + (uint32_t)cur * HSTG_B;
        #pragma unroll
        for (int kc = 0; kc < 2; kc++) {     // two k16 steps per 32-half chunk
            uint32_t af[4][4], bq[2][4];
            #pragma unroll
            for (int mi = 0; mi < 4; mi++)
                ldsm4(af[mi], aOff + mi * 16 * GPADH * 2 + kc * 32);
            #pragma unroll
            for (int nj = 0; nj < 2; nj++)
                ldsm4(bq[nj], bOff + nj * 16 * GPADH * 2 + kc * 32);
            #pragma unroll
            for (int mi = 0; mi < 4; mi++) {
                #pragma unroll
                for (int nj = 0; nj < 2; nj++) {
                    mma_f16(acc[mi][nj * 2 + 0], af[mi], &bq[nj][0]);
                    mma_f16(acc[mi][nj * 2 + 1], af[mi], &bq[nj][2]);
                }
            }
        }
        cur++; if (cur == 3) cur = 0;
    }

    #pragma unroll
    for (int mi = 0; mi < 4; mi++) {
        int r = m0 + wm * 64 + mi * 16 + g;
        #pragma unroll
        for (int ni = 0; ni < 4; ni++) {
            int c = n0 + wn * 32 + ni * 8 + tg * 2;
            if (z == 2) {
                *(__half2*)&Ch2[(size_t)r * CC + c] =
                    __floats2half2_rn(acc[mi][ni][0], acc[mi][ni][1]);
                *(__half2*)&Ch2[(size_t)(r + 8) * CC + c] =
                    __floats2half2_rn(acc[mi][ni][2], acc[mi][ni][3]);
            } else {
                float* Cf = (z == 0) ? Cf0 : Cf1;
                *(float2*)&Cf[(size_t)r * CC + c] =
                    make_float2(acc[mi][ni][0], acc[mi][ni][1]);
                *(float2*)&Cf[(size_t)(r + 8) * CC + c] =
                    make_float2(acc[mi][ni][2], acc[mi][ni][3]);
            }
        }
    }
}

// ---------------------------------------------------------------------------
// RoPE (concat-half) + RMSnorm; fp32 in -> fp16 out. q: 0.125 folded.
// ---------------------------------------------------------------------------
__global__ __launch_bounds__(256) void rope_rms(
    const float* __restrict__ qf, const float* __restrict__ kf,
    __half* __restrict__ qh, __half* __restrict__ kh,
    const float* __restrict__ cs, const float* __restrict__ sn)
{
    const int row = blockIdx.x * 8 + (threadIdx.x >> 5);
    const int i = threadIdx.x & 31;
    const int t = (row / HH) % TT;
    const float* p = (blockIdx.y == 0 ? qf : kf) + (size_t)row * DD;
    __half* o      = (blockIdx.y == 0 ? qh : kh) + (size_t)row * DD;

    float x1 = p[i];
    float x2 = p[i + 32];
    float c = cs[t * 32 + i];
    float s = sn[t * 32 + i];
    float y1 = x1 * c + x2 * s;
    float y2 = -x1 * s + x2 * c;

    float ss = y1 * y1 + y2 * y2;
    #pragma unroll
    for (int off = 16; off; off >>= 1) ss += __shfl_xor_sync(0xffffffffu, ss, off);
    float r = rsqrtf(ss * (1.0f / 64.0f) + EPS);
    if (blockIdx.y == 0) r *= 0.125f;

    o[i]      = __float2half_rn(y1 * r);
    o[i + 32] = __float2half_rn(y2 * r);
}

// ---------------------------------------------------------------------------
// Flash attention, fp16 MMA + ldmatrix(.trans for V). Br=128, Bc=64, D=64.
// 8 warps, single-buffered K/V, ~54 KB smem -> 2 CTAs/SM.
// ---------------------------------------------------------------------------
#define FLDH 72                // halves per smem row (64 + 8 pad)
#define NJT (TT / 64)

__global__ __launch_bounds__(256, 2) void flash_f16(
    const __half* __restrict__ q, const __half* __restrict__ kk,
    const __half* __restrict__ vv, __half* __restrict__ y)
{
    extern __shared__ __half smh[];
    __half* Qs = smh;                      // 128 x 72
    __half* Ks = smh + 128 * FLDH;         // 64 x 72
    __half* Vs = smh + 192 * FLDH;         // 64 x 72 ([s][d] natural)
    __half* Ps = smh + 256 * FLDH;         // 128 x 72

    const int tid = threadIdx.x;
    const int wid = tid >> 5;
    const int lane = tid & 31;
    const int g = lane >> 2, tg = lane & 3;

    const int bh = blockIdx.y;
    const size_t base = (size_t)(bh / HH) * TT * CC + (size_t)(bh % HH) * DD;
    const int q0 = blockIdx.x * 128;

    const uint32_t sQ = (uint32_t)__cvta_generic_to_shared(Qs);
    const uint32_t sK = (uint32_t)__cvta_generic_to_shared(Ks);
    const uint32_t sV = (uint32_t)__cvta_generic_to_shared(Vs);
    const uint32_t sP = (uint32_t)__cvta_generic_to_shared(Ps);

    const int mb = wid * 16;
    const uint32_t aRow = (lane & 7) + ((lane >> 3) & 1) * 8;
    const uint32_t aCol = ((lane >> 4) & 1) * 8;
    const uint32_t bRow = (lane & 7) + ((lane >> 4) & 1) * 8;
    const uint32_t bCol = ((lane >> 3) & 1) * 8;
    const uint32_t vRow = (lane & 7) + ((lane >> 3) & 1) * 8;   // s within tile
    const uint32_t vCol = ((lane >> 4) & 1) * 8;                // d within pair
    const uint32_t lmQ = sQ + ((mb + aRow) * FLDH + aCol) * 2;
    const uint32_t lmP = sP + ((mb + aRow) * FLDH + aCol) * 2;
    const uint32_t lmK = sK + (bRow * FLDH + bCol) * 2;
    const uint32_t lmV = sV + (vRow * FLDH + vCol) * 2;

    // staging: Q (128x8 units) 4/thread; K,V (64x8 units) 2/thread each
    {
        #pragma unroll
        for (int t = 0; t < 4; t++) {
            int idx = tid + t * 256;
            int r = idx >> 3, u = idx & 7;
            cp16(sQ + (uint32_t)(r * FLDH + u * 8) * 2,
                 q + base + (size_t)(q0 + r) * CC + u * 8);
        }
        #pragma unroll
        for (int t = 0; t < 2; t++) {
            int idx = tid + t * 256;
            int r = idx >> 3, u = idx & 7;
            cp16(sK + (uint32_t)(r * FLDH + u * 8) * 2,
                 kk + base + (size_t)r * CC + u * 8);
            cp16(sV + (uint32_t)(r * FLDH + u * 8) * 2,
                 vv + base + (size_t)r * CC + u * 8);
        }
        cp_commit();
    }

    float mrow[2] = {-1e30f, -1e30f};
    float lrow[2] = {0.0f, 0.0f};
    float oacc[8][4] = {};

    for (int jt = 0; jt < NJT; jt++) {
        cp_wait<0>();
        __syncthreads();

        // S = (Q*scale) K^T   (K as B, non-trans)
        float sacc[8][4] = {};
        #pragma unroll
        for (int kc = 0; kc < 4; kc++) {
            uint32_t af[4];
            ldsm4(af, lmQ + kc * 32);
            #pragma unroll
            for (int nj = 0; nj < 4; nj++) {
                uint32_t bq[4];
                ldsm4(bq, lmK + nj * 16 * FLDH * 2 + kc * 32);
                mma_f16(sacc[nj * 2 + 0], af, &bq[0]);
                mma_f16(sacc[nj * 2 + 1], af, &bq[2]);
            }
        }

        // Online softmax
        float rmax[2] = {-1e30f, -1e30f};
        #pragma unroll
        for (int ni = 0; ni < 8; ni++) {
            rmax[0] = fmaxf(rmax[0], fmaxf(sacc[ni][0], sacc[ni][1]));
            rmax[1] = fmaxf(rmax[1], fmaxf(sacc[ni][2], sacc[ni][3]));
        }
        #pragma unroll
        for (int o = 1; o <= 2; o <<= 1) {
            rmax[0] = fmaxf(rmax[0], __shfl_xor_sync(0xffffffffu, rmax[0], o));
            rmax[1] = fmaxf(rmax[1], __shfl_xor_sync(0xffffffffu, rmax[1], o));
        }
        float nm0 = fmaxf(mrow[0], rmax[0]);
        float nm1 = fmaxf(mrow[1], rmax[1]);
        float alpha0 = __expf(mrow[0] - nm0);
        float alpha1 = __expf(mrow[1] - nm1);

        float rsum[2] = {0.0f, 0.0f};
        #pragma unroll
        for (int ni = 0; ni < 8; ni++) {
            float p0 = __expf(sacc[ni][0] - nm0);
            float p1 = __expf(sacc[ni][1] - nm0);
            float p2 = __expf(sacc[ni][2] - nm1);
            float p3 = __expf(sacc[ni][3] - nm1);
            rsum[0] += p0 + p1;
            rsum[1] += p2 + p3;
            int c = ni * 8 + tg * 2;
            *(__half2*)&Ps[(mb + g    ) * FLDH + c] = __floats2half2_rn(p0, p1);
            *(__half2*)&Ps[(mb + g + 8) * FLDH + c] = __floats2half2_rn(p2, p3);
        }
        #pragma unroll
        for (int o = 1; o <= 2; o <<= 1) {
            rsum[0] += __shfl_xor_sync(0xffffffffu, rsum[0], o);
            rsum[1] += __shfl_xor_sync(0xffffffffu, rsum[1], o);
        }
        lrow[0] = lrow[0] * alpha0 + rsum[0];
        lrow[1] = lrow[1] * alpha1 + rsum[1];
        mrow[0] = nm0;
        mrow[1] = nm1;

        #pragma unroll
        for (int ni = 0; ni < 8; ni++) {
            oacc[ni][0] *= alpha0; oacc[ni][1] *= alpha0;
            oacc[ni][2] *= alpha1; oacc[ni][3] *= alpha1;
        }
        __syncwarp();   // Ps rows are warp-local

        // O += P V   (V as B via ldmatrix.trans on [s][d])
        #pragma unroll
        for (int kc = 0; kc < 4; kc++) {
            uint32_t af[4];
            ldsm4(af, lmP + kc * 32);
            #pragma unroll
            for (int nj = 0; nj < 4; nj++) {
                uint32_t bq[4];
                ldsm4t(bq, lmV + kc * 16 * FLDH * 2 + nj * 32);
                mma_f16(oacc[nj * 2 + 0], af, &bq[0]);
                mma_f16(oacc[nj * 2 + 1], af, &bq[2]);
            }
        }

        __syncthreads();   // all warps done reading Ks/Vs
        if (jt + 1 < NJT) {
            const int j1 = (jt + 1) * 64;
            #pragma unroll
            for (int t = 0; t < 2; t++) {
                int idx = tid + t * 256;
                int r = idx >> 3, u = idx & 7;
                cp16(sK + (uint32_t)(r * FLDH + u * 8) * 2,
                     kk + base + (size_t)(j1 + r) * CC + u * 8);
                cp16(sV + (uint32_t)(r * FLDH + u * 8) * 2,
                     vv + base + (size_t)(j1 + r) * CC + u * 8);
            }
            cp_commit();
        }
    }

    // Epilogue: normalize, convert to fp16, write
    float inv0 = 1.0f / lrow[0];
    float inv1 = 1.0f / lrow[1];
    int r0 = q0 + mb + g;
    #pragma unroll
    for (int ni = 0; ni < 8; ni++) {
        int c = ni * 8 + tg * 2;
        *(__half2*)&y[base + (size_t)r0 * CC + c] =
            __floats2half2_rn(oacc[ni][0] * inv0, oacc[ni][1] * inv0);
        *(__half2*)&y[base + (size_t)(r0 + 8) * CC + c] =
            __floats2half2_rn(oacc[ni][2] * inv1, oacc[ni][3] * inv1);
    }
}

// ---------------------------------------------------------------------------
// Launch
// ---------------------------------------------------------------------------
extern "C" void kernel_launch(void* const* d_in, const int* in_sizes, int n_in,
                              void* d_out, int out_size)
{
    const float* x  = (const float*)d_in[0];
    const float* cs = (const float*)d_in[1];
    const float* sn = (const float*)d_in[2];
    const float* Wq = (const float*)d_in[3];
    const float* Wk = (const float*)d_in[4];
    const float* Wv = (const float*)d_in[5];
    const float* Wo = (const float*)d_in[6];
    float* out = (float*)d_out;

    float *qf, *kf;
    __half *xh, *wh, *qh, *kh, *vh, *yh;
    cudaGetSymbolAddress((void**)&qf, g_qf);
    cudaGetSymbolAddress((void**)&kf, g_kf);
    cudaGetSymbolAddress((void**)&xh, h_x);
    cudaGetSymbolAddress((void**)&wh, h_w);
    cudaGetSymbolAddress((void**)&qh, h_q);
    cudaGetSymbolAddress((void**)&kh, h_k);
    cudaGetSymbolAddress((void**)&vh, h_v);
    cudaGetSymbolAddress((void**)&yh, h_y);

    const int NX = BB * TT * CC;
    const int NW = CC * CC;

    cvt_pass<<<NX / 1024, 256>>>(x, xh, NX);
    cvt_pass<<<NW / 1024, 256>>>(Wq, wh + 0 * NW, NW);
    cvt_pass<<<NW / 1024, 256>>>(Wk, wh + 1 * NW, NW);
    cvt_pass<<<NW / 1024, 256>>>(Wv, wh + 2 * NW, NW);
    cvt_pass<<<NW / 1024, 256>>>(Wo, wh + 3 * NW, NW);

    const int gsmem = 6 * HSTG_B;   // 61440 B
    cudaFuncSetAttribute(gemm_f16, cudaFuncAttributeMaxDynamicSharedMemorySize, gsmem);

    // Fused QKV projections: z0->qf(f32), z1->kf(f32), z2->vh(f16)
    dim3 qkvgrid(CC / 128, (BB * TT) / 128, 3);
    gemm_f16<<<qkvgrid, 256, gsmem>>>(xh, wh, qf, kf, vh);

    dim3 rgrid(BB * TT * HH / 8, 2);
    rope_rms<<<rgrid, 256>>>(qf, kf, qh, kh, cs, sn);

    const int fsmem = 384 * FLDH * 2;   // 55296 B
    cudaFuncSetAttribute(flash_f16, cudaFuncAttributeMaxDynamicSharedMemorySize, fsmem);
    dim3 fgrid(TT / 128, BB * HH);
    flash_f16<<<fgrid, 256, fsmem>>>(qh, kh, vh, yh);

    // Output projection: z0 -> out (fp32)
    dim3 ogrid(CC / 128, (BB * TT) / 128, 1);
    gemm_f16<<<ogrid, 256, gsmem>>>(yh, wh + 3 * NW, out, out, (__half*)yh);
}

// round 11
// speedup vs baseline: 2.3561x; 1.1620x over previous
#include <cuda_runtime.h>
#include <cuda_fp16.h>
#include <math.h>
#include <stdint.h>

#define BB 4
#define TT 2048
#define CC 1024
#define HH 16
#define DD 64
#define EPS 1.1920929e-07f

// ---------------------------------------------------------------------------
// Scratch (allocation-free rule)
// ---------------------------------------------------------------------------
__device__ float  g_qf[BB * TT * CC];     // gemm q output (fp32, pre-rope)
__device__ float  g_kf[BB * TT * CC];     // gemm k output (fp32, pre-rope)
__device__ __half h_x[BB * TT * CC];      // fp16 x
__device__ __half h_w[4 * CC * CC];       // fp16 weights
__device__ __half h_q[BB * TT * CC];      // fp16 q (post rope, x0.125)
__device__ __half h_k[BB * TT * CC];      // fp16 k (post rope)
__device__ __half h_v[BB * TT * CC];      // fp16 v
__device__ __half h_y[BB * TT * CC];      // fp16 attention output

// ---------------------------------------------------------------------------
// helpers
// ---------------------------------------------------------------------------
__device__ __forceinline__ void mma_f16(float* c, const uint32_t* a, const uint32_t* b) {
    asm volatile(
        "mma.sync.aligned.m16n8k16.row.col.f32.f16.f16.f32 "
        "{%0,%1,%2,%3}, {%4,%5,%6,%7}, {%8,%9}, {%0,%1,%2,%3};"
        : "+f"(c[0]), "+f"(c[1]), "+f"(c[2]), "+f"(c[3])
        : "r"(a[0]), "r"(a[1]), "r"(a[2]), "r"(a[3]), "r"(b[0]), "r"(b[1]));
}

__device__ __forceinline__ void ldsm4(uint32_t* r, uint32_t addr) {
    asm volatile(
        "ldmatrix.sync.aligned.m8n8.x4.shared.b16 {%0,%1,%2,%3}, [%4];"
        : "=r"(r[0]), "=r"(r[1]), "=r"(r[2]), "=r"(r[3]) : "r"(addr));
}
__device__ __forceinline__ void ldsm4t(uint32_t* r, uint32_t addr) {
    asm volatile(
        "ldmatrix.sync.aligned.m8n8.x4.trans.shared.b16 {%0,%1,%2,%3}, [%4];"
        : "=r"(r[0]), "=r"(r[1]), "=r"(r[2]), "=r"(r[3]) : "r"(addr));
}

__device__ __forceinline__ void cp16(uint32_t dst, const void* src) {
    asm volatile("cp.async.ca.shared.global [%0], [%1], 16;" :: "r"(dst), "l"(src));
}
__device__ __forceinline__ void cp_commit() {
    asm volatile("cp.async.commit_group;");
}
template <int N>
__device__ __forceinline__ void cp_wait() {
    asm volatile("cp.async.wait_group %0;" :: "n"(N));
}

// ---------------------------------------------------------------------------
// Pre-pass: fp32 -> fp16 (rn). cvt_w: grid.y selects one of 4 weights.
// ---------------------------------------------------------------------------
__global__ __launch_bounds__(256) void cvt_pass(
    const float* __restrict__ src, __half* __restrict__ dst, int n)
{
    int i = (blockIdx.x * 256 + threadIdx.x) * 4;
    if (i < n) {
        float4 v = *(const float4*)(src + i);
        *(__half2*)(dst + i)     = __floats2half2_rn(v.x, v.y);
        *(__half2*)(dst + i + 2) = __floats2half2_rn(v.z, v.w);
    }
}

__global__ __launch_bounds__(256) void cvt_w4(
    const float* __restrict__ w0, const float* __restrict__ w1,
    const float* __restrict__ w2, const float* __restrict__ w3,
    __half* __restrict__ dst)
{
    const float* src = blockIdx.y == 0 ? w0 : (blockIdx.y == 1 ? w1 :
                       (blockIdx.y == 2 ? w2 : w3));
    __half* d = dst + (size_t)blockIdx.y * CC * CC;
    int i = (blockIdx.x * 256 + threadIdx.x) * 4;
    float4 v = *(const float4*)(src + i);
    *(__half2*)(d + i)     = __floats2half2_rn(v.x, v.y);
    *(__half2*)(d + i + 2) = __floats2half2_rn(v.z, v.w);
}

// ---------------------------------------------------------------------------
// GEMM NT (fp16 MMA m16n8k16 + ldmatrix): C[m,n] = sum_k A[m,k]*W[n,k].
// 128x128 tile, K-chunks of 64 halves (4 k16 steps), 256 threads (8 warps
// 2x4), warp tile 64x32, 3-stage cp.async pipeline, 16 barriers total.
// z==0 -> Cf0 (fp32), z==1 -> Cf1 (fp32), z==2 -> Ch2 (fp16, v path).
// ---------------------------------------------------------------------------
#define GCH 64                 // K halves per chunk
#define NCH (CC / GCH)         // 16
#define GPADH 72               // halves per smem row (64 + 8 pad)
#define HSTG_B (128 * GPADH * 2)   // 18432 bytes per operand stage

__global__ __launch_bounds__(256, 2) void gemm_f16(
    const __half* __restrict__ A, const __half* __restrict__ Wbase,
    float* __restrict__ Cf0, float* __restrict__ Cf1, __half* __restrict__ Ch2)
{
    extern __shared__ __half sg[];
    const uint32_t sA = (uint32_t)__cvta_generic_to_shared(sg);
    const uint32_t sW = sA + 3 * HSTG_B;

    const int z = blockIdx.z;
    const __half* W = Wbase + (size_t)z * CC * CC;

    const int tid = threadIdx.x;
    const int wid = tid >> 5;
    const int lane = tid & 31;
    const int wm = wid & 1;
    const int wn = wid >> 1;
    const int g = lane >> 2;
    const int tg = lane & 3;

    const int m0 = blockIdx.y * 128;
    const int n0 = blockIdx.x * 128;

    const __half* Arow = A + (size_t)m0 * CC;
    const __half* Wrow = W + (size_t)n0 * CC;

    // ldmatrix per-lane bases
    const uint32_t aRow = (lane & 7) + ((lane >> 3) & 1) * 8;
    const uint32_t aCol = ((lane >> 4) & 1) * 8;
    const uint32_t bRow = (lane & 7) + ((lane >> 4) & 1) * 8;
    const uint32_t bCol = ((lane >> 3) & 1) * 8;
    const uint32_t lmA = sA + ((wm * 64 + aRow) * GPADH + aCol) * 2;
    const uint32_t lmB = sW + ((wn * 32 + bRow) * GPADH + bCol) * 2;

    float acc[4][4][4] = {};

    // staging: 128 rows x 8 units (16B) per operand -> 4 cp16/thread/operand
    auto stage = [&](int chunk, int buf) {
        const int col = chunk * GCH;
        #pragma unroll
        for (int t = 0; t < 4; t++) {
            int idx = tid + t * 256;
            int r = idx >> 3, u = idx & 7;
            const uint32_t d = (uint32_t)buf * HSTG_B + (uint32_t)(r * GPADH + u * 8) * 2;
            cp16(sA + d, Arow + (size_t)r * CC + col + u * 8);
            cp16(sW + d, Wrow + (size_t)r * CC + col + u * 8);
        }
        cp_commit();
    };

    stage(0, 0);
    stage(1, 1);

    int cur = 0;
    for (int i = 0; i < NCH; i++) {
        if (i + 1 < NCH) cp_wait<1>(); else cp_wait<0>();
        __syncthreads();

        if (i + 2 < NCH) {
            int nxt = cur + 2; if (nxt >= 3) nxt -= 3;
            stage(i + 2, nxt);
        }

        const uint32_t aOff = lmA + (uint32_t)cur * HSTG_B;
        const uint32_t bOff = lmB + (uint32_t)cur * HSTG_B;
        #pragma unroll
        for (int kc = 0; kc < 4; kc++) {     // four k16 steps per 64-half chunk
            uint32_t af[4][4], bq[2][4];
            #pragma unroll
            for (int mi = 0; mi < 4; mi++)
                ldsm4(af[mi], aOff + mi * 16 * GPADH * 2 + kc * 32);
            #pragma unroll
            for (int nj = 0; nj < 2; nj++)
                ldsm4(bq[nj], bOff + nj * 16 * GPADH * 2 + kc * 32);
            #pragma unroll
            for (int mi = 0; mi < 4; mi++) {
                #pragma unroll
                for (int nj = 0; nj < 2; nj++) {
                    mma_f16(acc[mi][nj * 2 + 0], af[mi], &bq[nj][0]);
                    mma_f16(acc[mi][nj * 2 + 1], af[mi], &bq[nj][2]);
                }
            }
        }
        cur++; if (cur == 3) cur = 0;
    }

    #pragma unroll
    for (int mi = 0; mi < 4; mi++) {
        int r = m0 + wm * 64 + mi * 16 + g;
        #pragma unroll
        for (int ni = 0; ni < 4; ni++) {
            int c = n0 + wn * 32 + ni * 8 + tg * 2;
            if (z == 2) {
                *(__half2*)&Ch2[(size_t)r * CC + c] =
                    __floats2half2_rn(acc[mi][ni][0], acc[mi][ni][1]);
                *(__half2*)&Ch2[(size_t)(r + 8) * CC + c] =
                    __floats2half2_rn(acc[mi][ni][2], acc[mi][ni][3]);
            } else {
                float* Cf = (z == 0) ? Cf0 : Cf1;
                *(float2*)&Cf[(size_t)r * CC + c] =
                    make_float2(acc[mi][ni][0], acc[mi][ni][1]);
                *(float2*)&Cf[(size_t)(r + 8) * CC + c] =
                    make_float2(acc[mi][ni][2], acc[mi][ni][3]);
            }
        }
    }
}

// ---------------------------------------------------------------------------
// RoPE (concat-half) + RMSnorm; fp32 in -> fp16 out. q: 0.125 folded.
// ---------------------------------------------------------------------------
__global__ __launch_bounds__(256) void rope_rms(
    const float* __restrict__ qf, const float* __restrict__ kf,
    __half* __restrict__ qh, __half* __restrict__ kh,
    const float* __restrict__ cs, const float* __restrict__ sn)
{
    const int row = blockIdx.x * 8 + (threadIdx.x >> 5);
    const int i = threadIdx.x & 31;
    const int t = (row / HH) % TT;
    const float* p = (blockIdx.y == 0 ? qf : kf) + (size_t)row * DD;
    __half* o      = (blockIdx.y == 0 ? qh : kh) + (size_t)row * DD;

    float x1 = p[i];
    float x2 = p[i + 32];
    float c = cs[t * 32 + i];
    float s = sn[t * 32 + i];
    float y1 = x1 * c + x2 * s;
    float y2 = -x1 * s + x2 * c;

    float ss = y1 * y1 + y2 * y2;
    #pragma unroll
    for (int off = 16; off; off >>= 1) ss += __shfl_xor_sync(0xffffffffu, ss, off);
    float r = rsqrtf(ss * (1.0f / 64.0f) + EPS);
    if (blockIdx.y == 0) r *= 0.125f;

    o[i]      = __float2half_rn(y1 * r);
    o[i + 32] = __float2half_rn(y2 * r);
}

// ---------------------------------------------------------------------------
// Flash attention, fp16 MMA + ldmatrix(.trans for V). Br=128, Bc=64, D=64.
// 8 warps. K/V double-buffered, ONE barrier per j-tile, loads overlap
// compute. 72 KB smem -> 2 CTAs/SM.
// ---------------------------------------------------------------------------
#define FLDH 72                // halves per smem row (64 + 8 pad)
#define NJT (TT / 64)
#define KVBUF_B (64 * FLDH * 2)

__global__ __launch_bounds__(256, 2) void flash_f16(
    const __half* __restrict__ q, const __half* __restrict__ kk,
    const __half* __restrict__ vv, __half* __restrict__ y)
{
    extern __shared__ __half smh[];
    __half* Qs = smh;                      // 128 x 72
    __half* Ks = smh + 128 * FLDH;         // 2 x 64 x 72
    __half* Vs = smh + 256 * FLDH;         // 2 x 64 x 72 ([s][d] natural)
    __half* Ps = smh + 384 * FLDH;         // 128 x 72

    const int tid = threadIdx.x;
    const int wid = tid >> 5;
    const int lane = tid & 31;
    const int g = lane >> 2, tg = lane & 3;

    const int bh = blockIdx.y;
    const size_t base = (size_t)(bh / HH) * TT * CC + (size_t)(bh % HH) * DD;
    const int q0 = blockIdx.x * 128;

    const uint32_t sQ = (uint32_t)__cvta_generic_to_shared(Qs);
    const uint32_t sK = (uint32_t)__cvta_generic_to_shared(Ks);
    const uint32_t sV = (uint32_t)__cvta_generic_to_shared(Vs);
    const uint32_t sP = (uint32_t)__cvta_generic_to_shared(Ps);

    const int mb = wid * 16;
    const uint32_t aRow = (lane & 7) + ((lane >> 3) & 1) * 8;
    const uint32_t aCol = ((lane >> 4) & 1) * 8;
    const uint32_t bRow = (lane & 7) + ((lane >> 4) & 1) * 8;
    const uint32_t bCol = ((lane >> 3) & 1) * 8;
    const uint32_t vRow = (lane & 7) + ((lane >> 3) & 1) * 8;
    const uint32_t vCol = ((lane >> 4) & 1) * 8;
    const uint32_t lmQ = sQ + ((mb + aRow) * FLDH + aCol) * 2;
    const uint32_t lmP = sP + ((mb + aRow) * FLDH + aCol) * 2;
    const uint32_t lmK = sK + (bRow * FLDH + bCol) * 2;
    const uint32_t lmV = sV + (vRow * FLDH + vCol) * 2;

    // stage K/V tile jt into buffer buf
    auto stageKV = [&](int jt, int buf) {
        const int j0 = jt * 64;
        #pragma unroll
        for (int t = 0; t < 2; t++) {
            int idx = tid + t * 256;
            int r = idx >> 3, u = idx & 7;
            const uint32_t d = (uint32_t)buf * KVBUF_B + (uint32_t)(r * FLDH + u * 8) * 2;
            cp16(sK + d, kk + base + (size_t)(j0 + r) * CC + u * 8);
            cp16(sV + d, vv + base + (size_t)(j0 + r) * CC + u * 8);
        }
        cp_commit();
    };

    // prologue: Q + K/V tile 0 (single group)
    #pragma unroll
    for (int t = 0; t < 4; t++) {
        int idx = tid + t * 256;
        int r = idx >> 3, u = idx & 7;
        cp16(sQ + (uint32_t)(r * FLDH + u * 8) * 2,
             q + base + (size_t)(q0 + r) * CC + u * 8);
    }
    stageKV(0, 0);

    float mrow[2] = {-1e30f, -1e30f};
    float lrow[2] = {0.0f, 0.0f};
    float oacc[8][4] = {};

    for (int jt = 0; jt < NJT; jt++) {
        const int cur = jt & 1;
        cp_wait<0>();      // K/V(jt) arrived (single group in flight)
        __syncthreads();   // visible to all; all warps done reading buf cur^1

        if (jt + 1 < NJT) stageKV(jt + 1, cur ^ 1);   // overlaps compute below

        // S = (Q*scale) K^T
        const uint32_t kOff = lmK + (uint32_t)cur * KVBUF_B;
        float sacc[8][4] = {};
        #pragma unroll
        for (int kc = 0; kc < 4; kc++) {
            uint32_t af[4];
            ldsm4(af, lmQ + kc * 32);
            #pragma unroll
            for (int nj = 0; nj < 4; nj++) {
                uint32_t bq[4];
                ldsm4(bq, kOff + nj * 16 * FLDH * 2 + kc * 32);
                mma_f16(sacc[nj * 2 + 0], af, &bq[0]);
                mma_f16(sacc[nj * 2 + 1], af, &bq[2]);
            }
        }

        // Online softmax
        float rmax[2] = {-1e30f, -1e30f};
        #pragma unroll
        for (int ni = 0; ni < 8; ni++) {
            rmax[0] = fmaxf(rmax[0], fmaxf(sacc[ni][0], sacc[ni][1]));
            rmax[1] = fmaxf(rmax[1], fmaxf(sacc[ni][2], sacc[ni][3]));
        }
        #pragma unroll
        for (int o = 1; o <= 2; o <<= 1) {
            rmax[0] = fmaxf(rmax[0], __shfl_xor_sync(0xffffffffu, rmax[0], o));
            rmax[1] = fmaxf(rmax[1], __shfl_xor_sync(0xffffffffu, rmax[1], o));
        }
        float nm0 = fmaxf(mrow[0], rmax[0]);
        float nm1 = fmaxf(mrow[1], rmax[1]);
        float alpha0 = __expf(mrow[0] - nm0);
        float alpha1 = __expf(mrow[1] - nm1);

        float rsum[2] = {0.0f, 0.0f};
        #pragma unroll
        for (int ni = 0; ni < 8; ni++) {
            float p0 = __expf(sacc[ni][0] - nm0);
            float p1 = __expf(sacc[ni][1] - nm0);
            float p2 = __expf(sacc[ni][2] - nm1);
            float p3 = __expf(sacc[ni][3] - nm1);
            rsum[0] += p0 + p1;
            rsum[1] += p2 + p3;
            int c = ni * 8 + tg * 2;
            *(__half2*)&Ps[(mb + g    ) * FLDH + c] = __floats2half2_rn(p0, p1);
            *(__half2*)&Ps[(mb + g + 8) * FLDH + c] = __floats2half2_rn(p2, p3);
        }
        #pragma unroll
        for (int o = 1; o <= 2; o <<= 1) {
            rsum[0] += __shfl_xor_sync(0xffffffffu, rsum[0], o);
            rsum[1] += __shfl_xor_sync(0xffffffffu, rsum[1], o);
        }
        lrow[0] = lrow[0] * alpha0 + rsum[0];
        lrow[1] = lrow[1] * alpha1 + rsum[1];
        mrow[0] = nm0;
        mrow[1] = nm1;

        #pragma unroll
        for (int ni = 0; ni < 8; ni++) {
            oacc[ni][0] *= alpha0; oacc[ni][1] *= alpha0;
            oacc[ni][2] *= alpha1; oacc[ni][3] *= alpha1;
        }
        __syncwarp();   // Ps rows are warp-local

        // O += P V   (V as B via ldmatrix.trans on [s][d])
        const uint32_t vOff = lmV + (uint32_t)cur * KVBUF_B;
        #pragma unroll
        for (int kc = 0; kc < 4; kc++) {
            uint32_t af[4];
            ldsm4(af, lmP + kc * 32);
            #pragma unroll
            for (int nj = 0; nj < 4; nj++) {
                uint32_t bq[4];
                ldsm4t(bq, vOff + kc * 16 * FLDH * 2 + nj * 32);
                mma_f16(oacc[nj * 2 + 0], af, &bq[0]);
                mma_f16(oacc[nj * 2 + 1], af, &bq[2]);
            }
        }
        // no end barrier: next iter's top barrier protects buf reuse
    }

    // Epilogue: normalize, convert to fp16, write
    float inv0 = 1.0f / lrow[0];
    float inv1 = 1.0f / lrow[1];
    int r0 = q0 + mb + g;
    #pragma unroll
    for (int ni = 0; ni < 8; ni++) {
        int c = ni * 8 + tg * 2;
        *(__half2*)&y[base + (size_t)r0 * CC + c] =
            __floats2half2_rn(oacc[ni][0] * inv0, oacc[ni][1] * inv0);
        *(__half2*)&y[base + (size_t)(r0 + 8) * CC + c] =
            __floats2half2_rn(oacc[ni][2] * inv1, oacc[ni][3] * inv1);
    }
}

// ---------------------------------------------------------------------------
// Launch
// ---------------------------------------------------------------------------
extern "C" void kernel_launch(void* const* d_in, const int* in_sizes, int n_in,
                              void* d_out, int out_size)
{
    const float* x  = (const float*)d_in[0];
    const float* cs = (const float*)d_in[1];
    const float* sn = (const float*)d_in[2];
    const float* Wq = (const float*)d_in[3];
    const float* Wk = (const float*)d_in[4];
    const float* Wv = (const float*)d_in[5];
    const float* Wo = (const float*)d_in[6];
    float* out = (float*)d_out;

    float *qf, *kf;
    __half *xh, *wh, *qh, *kh, *vh, *yh;
    cudaGetSymbolAddress((void**)&qf, g_qf);
    cudaGetSymbolAddress((void**)&kf, g_kf);
    cudaGetSymbolAddress((void**)&xh, h_x);
    cudaGetSymbolAddress((void**)&wh, h_w);
    cudaGetSymbolAddress((void**)&qh, h_q);
    cudaGetSymbolAddress((void**)&kh, h_k);
    cudaGetSymbolAddress((void**)&vh, h_v);
    cudaGetSymbolAddress((void**)&yh, h_y);

    const int NX = BB * TT * CC;
    const int NW = CC * CC;

    cvt_pass<<<NX / 1024, 256>>>(x, xh, NX);
    dim3 wgrid(NW / 1024, 4);
    cvt_w4<<<wgrid, 256>>>(Wq, Wk, Wv, Wo, wh);

    const int gsmem = 6 * HSTG_B;   // 110592 B
    cudaFuncSetAttribute(gemm_f16, cudaFuncAttributeMaxDynamicSharedMemorySize, gsmem);

    // Fused QKV projections: z0->qf(f32), z1->kf(f32), z2->vh(f16)
    dim3 qkvgrid(CC / 128, (BB * TT) / 128, 3);
    gemm_f16<<<qkvgrid, 256, gsmem>>>(xh, wh, qf, kf, vh);

    dim3 rgrid(BB * TT * HH / 8, 2);
    rope_rms<<<rgrid, 256>>>(qf, kf, qh, kh, cs, sn);

    const int fsmem = 512 * FLDH * 2;   // 73728 B
    cudaFuncSetAttribute(flash_f16, cudaFuncAttributeMaxDynamicSharedMemorySize, fsmem);
    dim3 fgrid(TT / 128, BB * HH);
    flash_f16<<<fgrid, 256, fsmem>>>(qh, kh, vh, yh);

    // Output projection: z0 -> out (fp32)
    dim3 ogrid(CC / 128, (BB * TT) / 128, 1);
    gemm_f16<<<ogrid, 256, gsmem>>>(yh, wh + 3 * NW, out, out, (__half*)yh);
}

// round 12
// speedup vs baseline: 2.4223x; 1.0281x over previous
#include <cuda_runtime.h>
#include <cuda_fp16.h>
#include <math.h>
#include <stdint.h>

#define BB 4
#define TT 2048
#define CC 1024
#define HH 16
#define DD 64
#define EPS 1.1920929e-07f

// ---------------------------------------------------------------------------
// Scratch (allocation-free rule)
// ---------------------------------------------------------------------------
__device__ float  g_qf[BB * TT * CC];     // gemm q output (fp32, pre-rope)
__device__ float  g_kf[BB * TT * CC];     // gemm k output (fp32, pre-rope)
__device__ __half h_x[BB * TT * CC];      // fp16 x
__device__ __half h_w[4 * CC * CC];       // fp16 weights
__device__ __half h_q[BB * TT * CC];      // fp16 q (post rope, x0.125)
__device__ __half h_k[BB * TT * CC];      // fp16 k (post rope)
__device__ __half h_v[BB * TT * CC];      // fp16 v
__device__ __half h_y[BB * TT * CC];      // fp16 attention output

// ---------------------------------------------------------------------------
// helpers
// ---------------------------------------------------------------------------
__device__ __forceinline__ void mma_f16(float* c, const uint32_t* a, const uint32_t* b) {
    asm volatile(
        "mma.sync.aligned.m16n8k16.row.col.f32.f16.f16.f32 "
        "{%0,%1,%2,%3}, {%4,%5,%6,%7}, {%8,%9}, {%0,%1,%2,%3};"
        : "+f"(c[0]), "+f"(c[1]), "+f"(c[2]), "+f"(c[3])
        : "r"(a[0]), "r"(a[1]), "r"(a[2]), "r"(a[3]), "r"(b[0]), "r"(b[1]));
}

__device__ __forceinline__ void ldsm4(uint32_t* r, uint32_t addr) {
    asm volatile(
        "ldmatrix.sync.aligned.m8n8.x4.shared.b16 {%0,%1,%2,%3}, [%4];"
        : "=r"(r[0]), "=r"(r[1]), "=r"(r[2]), "=r"(r[3]) : "r"(addr));
}
__device__ __forceinline__ void ldsm4t(uint32_t* r, uint32_t addr) {
    asm volatile(
        "ldmatrix.sync.aligned.m8n8.x4.trans.shared.b16 {%0,%1,%2,%3}, [%4];"
        : "=r"(r[0]), "=r"(r[1]), "=r"(r[2]), "=r"(r[3]) : "r"(addr));
}

__device__ __forceinline__ void cp16(uint32_t dst, const void* src) {
    asm volatile("cp.async.ca.shared.global [%0], [%1], 16;" :: "r"(dst), "l"(src));
}
__device__ __forceinline__ void cp_commit() {
    asm volatile("cp.async.commit_group;");
}
template <int N>
__device__ __forceinline__ void cp_wait() {
    asm volatile("cp.async.wait_group %0;" :: "n"(N));
}

// ---------------------------------------------------------------------------
// Pre-pass: fp32 -> fp16 (rn). cvt_w4: grid.y selects one of 4 weights.
// ---------------------------------------------------------------------------
__global__ __launch_bounds__(256) void cvt_pass(
    const float* __restrict__ src, __half* __restrict__ dst, int n)
{
    int i = (blockIdx.x * 256 + threadIdx.x) * 4;
    if (i < n) {
        float4 v = *(const float4*)(src + i);
        *(__half2*)(dst + i)     = __floats2half2_rn(v.x, v.y);
        *(__half2*)(dst + i + 2) = __floats2half2_rn(v.z, v.w);
    }
}

__global__ __launch_bounds__(256) void cvt_w4(
    const float* __restrict__ w0, const float* __restrict__ w1,
    const float* __restrict__ w2, const float* __restrict__ w3,
    __half* __restrict__ dst)
{
    const float* src = blockIdx.y == 0 ? w0 : (blockIdx.y == 1 ? w1 :
                       (blockIdx.y == 2 ? w2 : w3));
    __half* d = dst + (size_t)blockIdx.y * CC * CC;
    int i = (blockIdx.x * 256 + threadIdx.x) * 4;
    float4 v = *(const float4*)(src + i);
    *(__half2*)(d + i)     = __floats2half2_rn(v.x, v.y);
    *(__half2*)(d + i + 2) = __floats2half2_rn(v.z, v.w);
}

// ---------------------------------------------------------------------------
// GEMM NT (fp16 MMA m16n8k16 + ldmatrix): C[m,n] = sum_k A[m,k]*W[n,k].
// 128x128 CTA tile, 128 threads (4 warps as 2x2), warp tile 64x64.
// Per k16 step/warp: 8 LDSM.x4 + 32 MMA (80% MMA issue fraction).
// K-chunks of 64 halves, 3-stage cp.async pipeline. 2 CTAs/SM.
// z==0 -> Cf0 (fp32), z==1 -> Cf1 (fp32), z==2 -> Ch2 (fp16, v path).
// ---------------------------------------------------------------------------
#define GCH 64                 // K halves per chunk
#define NCH (CC / GCH)         // 16
#define GPADH 72               // halves per smem row (64 + 8 pad)
#define HSTG_B (128 * GPADH * 2)   // 18432 bytes per operand stage

__global__ __launch_bounds__(128, 2) void gemm_f16(
    const __half* __restrict__ A, const __half* __restrict__ Wbase,
    float* __restrict__ Cf0, float* __restrict__ Cf1, __half* __restrict__ Ch2)
{
    extern __shared__ __half sg[];
    const uint32_t sA = (uint32_t)__cvta_generic_to_shared(sg);
    const uint32_t sW = sA + 3 * HSTG_B;

    const int z = blockIdx.z;
    const __half* W = Wbase + (size_t)z * CC * CC;

    const int tid = threadIdx.x;
    const int wid = tid >> 5;
    const int lane = tid & 31;
    const int wm = wid & 1;        // 2x2 warp grid
    const int wn = wid >> 1;
    const int g = lane >> 2;
    const int tg = lane & 3;

    const int m0 = blockIdx.y * 128;
    const int n0 = blockIdx.x * 128;

    const __half* Arow = A + (size_t)m0 * CC;
    const __half* Wrow = W + (size_t)n0 * CC;

    // ldmatrix per-lane bases
    const uint32_t aRow = (lane & 7) + ((lane >> 3) & 1) * 8;
    const uint32_t aCol = ((lane >> 4) & 1) * 8;
    const uint32_t bRow = (lane & 7) + ((lane >> 4) & 1) * 8;
    const uint32_t bCol = ((lane >> 3) & 1) * 8;
    const uint32_t lmA = sA + ((wm * 64 + aRow) * GPADH + aCol) * 2;
    const uint32_t lmB = sW + ((wn * 64 + bRow) * GPADH + bCol) * 2;

    float acc[4][8][4] = {};

    // staging: 128 rows x 8 units (16B) per operand -> 8 cp16/thread/operand
    auto stage = [&](int chunk, int buf) {
        const int col = chunk * GCH;
        #pragma unroll
        for (int t = 0; t < 8; t++) {
            int idx = tid + t * 128;
            int r = idx >> 3, u = idx & 7;
            const uint32_t d = (uint32_t)buf * HSTG_B + (uint32_t)(r * GPADH + u * 8) * 2;
            cp16(sA + d, Arow + (size_t)r * CC + col + u * 8);
            cp16(sW + d, Wrow + (size_t)r * CC + col + u * 8);
        }
        cp_commit();
    };

    stage(0, 0);
    stage(1, 1);

    int cur = 0;
    for (int i = 0; i < NCH; i++) {
        if (i + 1 < NCH) cp_wait<1>(); else cp_wait<0>();
        __syncthreads();

        if (i + 2 < NCH) {
            int nxt = cur + 2; if (nxt >= 3) nxt -= 3;
            stage(i + 2, nxt);
        }

        const uint32_t aOff = lmA + (uint32_t)cur * HSTG_B;
        const uint32_t bOff = lmB + (uint32_t)cur * HSTG_B;
        #pragma unroll
        for (int kc = 0; kc < 4; kc++) {     // four k16 steps per 64-half chunk
            uint32_t af[4][4], bq[4][4];
            #pragma unroll
            for (int mi = 0; mi < 4; mi++)
                ldsm4(af[mi], aOff + mi * 16 * GPADH * 2 + kc * 32);
            #pragma unroll
            for (int nj = 0; nj < 4; nj++)
                ldsm4(bq[nj], bOff + nj * 16 * GPADH * 2 + kc * 32);
            #pragma unroll
            for (int mi = 0; mi < 4; mi++) {
                #pragma unroll
                for (int nj = 0; nj < 4; nj++) {
                    mma_f16(acc[mi][nj * 2 + 0], af[mi], &bq[nj][0]);
                    mma_f16(acc[mi][nj * 2 + 1], af[mi], &bq[nj][2]);
                }
            }
        }
        cur++; if (cur == 3) cur = 0;
    }

    #pragma unroll
    for (int mi = 0; mi < 4; mi++) {
        int r = m0 + wm * 64 + mi * 16 + g;
        #pragma unroll
        for (int nj = 0; nj < 8; nj++) {
            int c = n0 + wn * 64 + nj * 8 + tg * 2;
            if (z == 2) {
                *(__half2*)&Ch2[(size_t)r * CC + c] =
                    __floats2half2_rn(acc[mi][nj][0], acc[mi][nj][1]);
                *(__half2*)&Ch2[(size_t)(r + 8) * CC + c] =
                    __floats2half2_rn(acc[mi][nj][2], acc[mi][nj][3]);
            } else {
                float* Cf = (z == 0) ? Cf0 : Cf1;
                *(float2*)&Cf[(size_t)r * CC + c] =
                    make_float2(acc[mi][nj][0], acc[mi][nj][1]);
                *(float2*)&Cf[(size_t)(r + 8) * CC + c] =
                    make_float2(acc[mi][nj][2], acc[mi][nj][3]);
            }
        }
    }
}

// ---------------------------------------------------------------------------
// RoPE (concat-half) + RMSnorm; fp32 in -> fp16 out. q: 0.125 folded.
// ---------------------------------------------------------------------------
__global__ __launch_bounds__(256) void rope_rms(
    const float* __restrict__ qf, const float* __restrict__ kf,
    __half* __restrict__ qh, __half* __restrict__ kh,
    const float* __restrict__ cs, const float* __restrict__ sn)
{
    const int row = blockIdx.x * 8 + (threadIdx.x >> 5);
    const int i = threadIdx.x & 31;
    const int t = (row / HH) % TT;
    const float* p = (blockIdx.y == 0 ? qf : kf) + (size_t)row * DD;
    __half* o      = (blockIdx.y == 0 ? qh : kh) + (size_t)row * DD;

    float x1 = p[i];
    float x2 = p[i + 32];
    float c = cs[t * 32 + i];
    float s = sn[t * 32 + i];
    float y1 = x1 * c + x2 * s;
    float y2 = -x1 * s + x2 * c;

    float ss = y1 * y1 + y2 * y2;
    #pragma unroll
    for (int off = 16; off; off >>= 1) ss += __shfl_xor_sync(0xffffffffu, ss, off);
    float r = rsqrtf(ss * (1.0f / 64.0f) + EPS);
    if (blockIdx.y == 0) r *= 0.125f;

    o[i]      = __float2half_rn(y1 * r);
    o[i + 32] = __float2half_rn(y2 * r);
}

// ---------------------------------------------------------------------------
// Flash attention, fp16 MMA + ldmatrix(.trans for V). Br=128, Bc=64, D=64.
// 8 warps. K/V double-buffered, ONE barrier per j-tile, loads overlap
// compute. Q fragments hoisted to registers. 72 KB smem -> 2 CTAs/SM.
// ---------------------------------------------------------------------------
#define FLDH 72                // halves per smem row (64 + 8 pad)
#define NJT (TT / 64)
#define KVBUF_B (64 * FLDH * 2)

__global__ __launch_bounds__(256, 2) void flash_f16(
    const __half* __restrict__ q, const __half* __restrict__ kk,
    const __half* __restrict__ vv, __half* __restrict__ y)
{
    extern __shared__ __half smh[];
    __half* Qs = smh;                      // 128 x 72
    __half* Ks = smh + 128 * FLDH;         // 2 x 64 x 72
    __half* Vs = smh + 256 * FLDH;         // 2 x 64 x 72 ([s][d] natural)
    __half* Ps = smh + 384 * FLDH;         // 128 x 72

    const int tid = threadIdx.x;
    const int wid = tid >> 5;
    const int lane = tid & 31;
    const int g = lane >> 2, tg = lane & 3;

    const int bh = blockIdx.y;
    const size_t base = (size_t)(bh / HH) * TT * CC + (size_t)(bh % HH) * DD;
    const int q0 = blockIdx.x * 128;

    const uint32_t sQ = (uint32_t)__cvta_generic_to_shared(Qs);
    const uint32_t sK = (uint32_t)__cvta_generic_to_shared(Ks);
    const uint32_t sV = (uint32_t)__cvta_generic_to_shared(Vs);
    const uint32_t sP = (uint32_t)__cvta_generic_to_shared(Ps);

    const int mb = wid * 16;
    const uint32_t aRow = (lane & 7) + ((lane >> 3) & 1) * 8;
    const uint32_t aCol = ((lane >> 4) & 1) * 8;
    const uint32_t bRow = (lane & 7) + ((lane >> 4) & 1) * 8;
    const uint32_t bCol = ((lane >> 3) & 1) * 8;
    const uint32_t vRow = (lane & 7) + ((lane >> 3) & 1) * 8;
    const uint32_t vCol = ((lane >> 4) & 1) * 8;
    const uint32_t lmQ = sQ + ((mb + aRow) * FLDH + aCol) * 2;
    const uint32_t lmP = sP + ((mb + aRow) * FLDH + aCol) * 2;
    const uint32_t lmK = sK + (bRow * FLDH + bCol) * 2;
    const uint32_t lmV = sV + (vRow * FLDH + vCol) * 2;

    // stage K/V tile jt into buffer buf
    auto stageKV = [&](int jt, int buf) {
        const int j0 = jt * 64;
        #pragma unroll
        for (int t = 0; t < 2; t++) {
            int idx = tid + t * 256;
            int r = idx >> 3, u = idx & 7;
            const uint32_t d = (uint32_t)buf * KVBUF_B + (uint32_t)(r * FLDH + u * 8) * 2;
            cp16(sK + d, kk + base + (size_t)(j0 + r) * CC + u * 8);
            cp16(sV + d, vv + base + (size_t)(j0 + r) * CC + u * 8);
        }
        cp_commit();
    };

    // prologue: Q + K/V tile 0 (single group)
    #pragma unroll
    for (int t = 0; t < 4; t++) {
        int idx = tid + t * 256;
        int r = idx >> 3, u = idx & 7;
        cp16(sQ + (uint32_t)(r * FLDH + u * 8) * 2,
             q + base + (size_t)(q0 + r) * CC + u * 8);
    }
    stageKV(0, 0);

    float mrow[2] = {-1e30f, -1e30f};
    float lrow[2] = {0.0f, 0.0f};
    float oacc[8][4] = {};
    uint32_t qfrag[4][4];   // hoisted Q fragments (all 4 k16 steps)

    for (int jt = 0; jt < NJT; jt++) {
        const int cur = jt & 1;
        cp_wait<0>();      // K/V(jt) arrived (single group in flight)
        __syncthreads();   // visible to all; all warps done reading buf cur^1

        if (jt == 0) {
            #pragma unroll
            for (int kc = 0; kc < 4; kc++)
                ldsm4(qfrag[kc], lmQ + kc * 32);
        }

        if (jt + 1 < NJT) stageKV(jt + 1, cur ^ 1);   // overlaps compute below

        // S = (Q*scale) K^T
        const uint32_t kOff = lmK + (uint32_t)cur * KVBUF_B;
        float sacc[8][4] = {};
        #pragma unroll
        for (int kc = 0; kc < 4; kc++) {
            #pragma unroll
            for (int nj = 0; nj < 4; nj++) {
                uint32_t bq[4];
                ldsm4(bq, kOff + nj * 16 * FLDH * 2 + kc * 32);
                mma_f16(sacc[nj * 2 + 0], qfrag[kc], &bq[0]);
                mma_f16(sacc[nj * 2 + 1], qfrag[kc], &bq[2]);
            }
        }

        // Online softmax
        float rmax[2] = {-1e30f, -1e30f};
        #pragma unroll
        for (int ni = 0; ni < 8; ni++) {
            rmax[0] = fmaxf(rmax[0], fmaxf(sacc[ni][0], sacc[ni][1]));
            rmax[1] = fmaxf(rmax[1], fmaxf(sacc[ni][2], sacc[ni][3]));
        }
        #pragma unroll
        for (int o = 1; o <= 2; o <<= 1) {
            rmax[0] = fmaxf(rmax[0], __shfl_xor_sync(0xffffffffu, rmax[0], o));
            rmax[1] = fmaxf(rmax[1], __shfl_xor_sync(0xffffffffu, rmax[1], o));
        }
        float nm0 = fmaxf(mrow[0], rmax[0]);
        float nm1 = fmaxf(mrow[1], rmax[1]);
        float alpha0 = __expf(mrow[0] - nm0);
        float alpha1 = __expf(mrow[1] - nm1);

        float rsum[2] = {0.0f, 0.0f};
        #pragma unroll
        for (int ni = 0; ni < 8; ni++) {
            float p0 = __expf(sacc[ni][0] - nm0);
            float p1 = __expf(sacc[ni][1] - nm0);
            float p2 = __expf(sacc[ni][2] - nm1);
            float p3 = __expf(sacc[ni][3] - nm1);
            rsum[0] += p0 + p1;
            rsum[1] += p2 + p3;
            int c = ni * 8 + tg * 2;
            *(__half2*)&Ps[(mb + g    ) * FLDH + c] = __floats2half2_rn(p0, p1);
            *(__half2*)&Ps[(mb + g + 8) * FLDH + c] = __floats2half2_rn(p2, p3);
        }
        #pragma unroll
        for (int o = 1; o <= 2; o <<= 1) {
            rsum[0] += __shfl_xor_sync(0xffffffffu, rsum[0], o);
            rsum[1] += __shfl_xor_sync(0xffffffffu, rsum[1], o);
        }
        lrow[0] = lrow[0] * alpha0 + rsum[0];
        lrow[1] = lrow[1] * alpha1 + rsum[1];
        mrow[0] = nm0;
        mrow[1] = nm1;

        #pragma unroll
        for (int ni = 0; ni < 8; ni++) {
            oacc[ni][0] *= alpha0; oacc[ni][1] *= alpha0;
            oacc[ni][2] *= alpha1; oacc[ni][3] *= alpha1;
        }
        __syncwarp();   // Ps rows are warp-local

        // O += P V   (V as B via ldmatrix.trans on [s][d])
        const uint32_t vOff = lmV + (uint32_t)cur * KVBUF_B;
        #pragma unroll
        for (int kc = 0; kc < 4; kc++) {
            uint32_t af[4];
            ldsm4(af, lmP + kc * 32);
            #pragma unroll
            for (int nj = 0; nj < 4; nj++) {
                uint32_t bq[4];
                ldsm4t(bq, vOff + kc * 16 * FLDH * 2 + nj * 32);
                mma_f16(oacc[nj * 2 + 0], af, &bq[0]);
                mma_f16(oacc[nj * 2 + 1], af, &bq[2]);
            }
        }
        // no end barrier: next iter's top barrier protects buf reuse
    }

    // Epilogue: normalize, convert to fp16, write
    float inv0 = 1.0f / lrow[0];
    float inv1 = 1.0f / lrow[1];
    int r0 = q0 + mb + g;
    #pragma unroll
    for (int ni = 0; ni < 8; ni++) {
        int c = ni * 8 + tg * 2;
        *(__half2*)&y[base + (size_t)r0 * CC + c] =
            __floats2half2_rn(oacc[ni][0] * inv0, oacc[ni][1] * inv0);
        *(__half2*)&y[base + (size_t)(r0 + 8) * CC + c] =
            __floats2half2_rn(oacc[ni][2] * inv1, oacc[ni][3] * inv1);
    }
}

// ---------------------------------------------------------------------------
// Launch
// ---------------------------------------------------------------------------
extern "C" void kernel_launch(void* const* d_in, const int* in_sizes, int n_in,
                              void* d_out, int out_size)
{
    const float* x  = (const float*)d_in[0];
    const float* cs = (const float*)d_in[1];
    const float* sn = (const float*)d_in[2];
    const float* Wq = (const float*)d_in[3];
    const float* Wk = (const float*)d_in[4];
    const float* Wv = (const float*)d_in[5];
    const float* Wo = (const float*)d_in[6];
    float* out = (float*)d_out;

    float *qf, *kf;
    __half *xh, *wh, *qh, *kh, *vh, *yh;
    cudaGetSymbolAddress((void**)&qf, g_qf);
    cudaGetSymbolAddress((void**)&kf, g_kf);
    cudaGetSymbolAddress((void**)&xh, h_x);
    cudaGetSymbolAddress((void**)&wh, h_w);
    cudaGetSymbolAddress((void**)&qh, h_q);
    cudaGetSymbolAddress((void**)&kh, h_k);
    cudaGetSymbolAddress((void**)&vh, h_v);
    cudaGetSymbolAddress((void**)&yh, h_y);

    const int NX = BB * TT * CC;
    const int NW = CC * CC;

    cvt_pass<<<NX / 1024, 256>>>(x, xh, NX);
    dim3 wgrid(NW / 1024, 4);
    cvt_w4<<<wgrid, 256>>>(Wq, Wk, Wv, Wo, wh);

    const int gsmem = 6 * HSTG_B;   // 110592 B
    cudaFuncSetAttribute(gemm_f16, cudaFuncAttributeMaxDynamicSharedMemorySize, gsmem);

    // Fused QKV projections: z0->qf(f32), z1->kf(f32), z2->vh(f16)
    dim3 qkvgrid(CC / 128, (BB * TT) / 128, 3);
    gemm_f16<<<qkvgrid, 128, gsmem>>>(xh, wh, qf, kf, vh);

    dim3 rgrid(BB * TT * HH / 8, 2);
    rope_rms<<<rgrid, 256>>>(qf, kf, qh, kh, cs, sn);

    const int fsmem = 512 * FLDH * 2;   // 73728 B
    cudaFuncSetAttribute(flash_f16, cudaFuncAttributeMaxDynamicSharedMemorySize, fsmem);
    dim3 fgrid(TT / 128, BB * HH);
    flash_f16<<<fgrid, 256, fsmem>>>(qh, kh, vh, yh);

    // Output projection: z0 -> out (fp32)
    dim3 ogrid(CC / 128, (BB * TT) / 128, 1);
    gemm_f16<<<ogrid, 128, gsmem>>>(yh, wh + 3 * NW, out, out, (__half*)yh);
}

// round 13
// speedup vs baseline: 2.5093x; 1.0359x over previous
#include <cuda_runtime.h>
#include <cuda_fp16.h>
#include <math.h>
#include <stdint.h>

#define BB 4
#define TT 2048
#define CC 1024
#define HH 16
#define DD 64
#define EPS 1.1920929e-07f

// ---------------------------------------------------------------------------
// Scratch (allocation-free rule)
// ---------------------------------------------------------------------------
__device__ __half h_x[BB * TT * CC];      // fp16 x
__device__ __half h_w[4 * CC * CC];       // fp16 weights
__device__ __half h_q[BB * TT * CC];      // fp16 q (post rope, x0.125)
__device__ __half h_k[BB * TT * CC];      // fp16 k (post rope)
__device__ __half h_v[BB * TT * CC];      // fp16 v
__device__ __half h_y[BB * TT * CC];      // fp16 attention output

// ---------------------------------------------------------------------------
// helpers
// ---------------------------------------------------------------------------
__device__ __forceinline__ void mma_f16(float* c, const uint32_t* a, const uint32_t* b) {
    asm volatile(
        "mma.sync.aligned.m16n8k16.row.col.f32.f16.f16.f32 "
        "{%0,%1,%2,%3}, {%4,%5,%6,%7}, {%8,%9}, {%0,%1,%2,%3};"
        : "+f"(c[0]), "+f"(c[1]), "+f"(c[2]), "+f"(c[3])
        : "r"(a[0]), "r"(a[1]), "r"(a[2]), "r"(a[3]), "r"(b[0]), "r"(b[1]));
}

__device__ __forceinline__ void ldsm4(uint32_t* r, uint32_t addr) {
    asm volatile(
        "ldmatrix.sync.aligned.m8n8.x4.shared.b16 {%0,%1,%2,%3}, [%4];"
        : "=r"(r[0]), "=r"(r[1]), "=r"(r[2]), "=r"(r[3]) : "r"(addr));
}
__device__ __forceinline__ void ldsm4t(uint32_t* r, uint32_t addr) {
    asm volatile(
        "ldmatrix.sync.aligned.m8n8.x4.trans.shared.b16 {%0,%1,%2,%3}, [%4];"
        : "=r"(r[0]), "=r"(r[1]), "=r"(r[2]), "=r"(r[3]) : "r"(addr));
}

__device__ __forceinline__ void cp16(uint32_t dst, const void* src) {
    asm volatile("cp.async.ca.shared.global [%0], [%1], 16;" :: "r"(dst), "l"(src));
}
__device__ __forceinline__ void cp_commit() {
    asm volatile("cp.async.commit_group;");
}
template <int N>
__device__ __forceinline__ void cp_wait() {
    asm volatile("cp.async.wait_group %0;" :: "n"(N));
}

// ---------------------------------------------------------------------------
// Pre-pass: fp32 -> fp16 (rn). cvt_w4: grid.y selects one of 4 weights.
// ---------------------------------------------------------------------------
__global__ __launch_bounds__(256) void cvt_pass(
    const float* __restrict__ src, __half* __restrict__ dst, int n)
{
    int i = (blockIdx.x * 256 + threadIdx.x) * 4;
    if (i < n) {
        float4 v = *(const float4*)(src + i);
        *(__half2*)(dst + i)     = __floats2half2_rn(v.x, v.y);
        *(__half2*)(dst + i + 2) = __floats2half2_rn(v.z, v.w);
    }
}

__global__ __launch_bounds__(256) void cvt_w4(
    const float* __restrict__ w0, const float* __restrict__ w1,
    const float* __restrict__ w2, const float* __restrict__ w3,
    __half* __restrict__ dst)
{
    const float* src = blockIdx.y == 0 ? w0 : (blockIdx.y == 1 ? w1 :
                       (blockIdx.y == 2 ? w2 : w3));
    __half* d = dst + (size_t)blockIdx.y * CC * CC;
    int i = (blockIdx.x * 256 + threadIdx.x) * 4;
    float4 v = *(const float4*)(src + i);
    *(__half2*)(d + i)     = __floats2half2_rn(v.x, v.y);
    *(__half2*)(d + i + 2) = __floats2half2_rn(v.z, v.w);
}

// ---------------------------------------------------------------------------
// GEMM NT (fp16 MMA m16n8k16 + ldmatrix): C[m,n] = sum_k A[m,k]*W[n,k].
// 128x128 CTA tile, 128 threads (4 warps as 2x2), warp tile 64x64.
// K-chunks of 64 halves, 3-stage cp.async pipeline, 2 CTAs/SM.
// mode = modeBase + blockIdx.z:
//   0: RoPE+RMSnorm fused epilogue -> Hq (fp16, 0.125 folded)
//   1: RoPE+RMSnorm fused epilogue -> Hk (fp16)
//   2: fp16 convert -> Hv
//   3: fp32 -> Cf (output projection)
// Warp layout luck: a warp's 64 cols = exactly one head; RoPE pair (i,i+32)
// = accumulators nj and nj+4 in the SAME lane; rmsnorm = quad shuffle.
// ---------------------------------------------------------------------------
#define GCH 64                 // K halves per chunk
#define NCH (CC / GCH)         // 16
#define GPADH 72               // halves per smem row (64 + 8 pad)
#define HSTG_B (128 * GPADH * 2)   // 18432 bytes per operand stage

__global__ __launch_bounds__(128, 2) void gemm_f16(
    const __half* __restrict__ A, const __half* __restrict__ Wbase,
    __half* __restrict__ Hq, __half* __restrict__ Hk, __half* __restrict__ Hv,
    float* __restrict__ Cf,
    const float* __restrict__ cs, const float* __restrict__ sn,
    int modeBase)
{
    extern __shared__ __half sg[];
    const uint32_t sA = (uint32_t)__cvta_generic_to_shared(sg);
    const uint32_t sW = sA + 3 * HSTG_B;

    const int mode = modeBase + blockIdx.z;
    const __half* W = Wbase + (size_t)blockIdx.z * CC * CC + (size_t)(modeBase == 3 ? 3 : 0) * CC * CC;

    const int tid = threadIdx.x;
    const int wid = tid >> 5;
    const int lane = tid & 31;
    const int wm = wid & 1;        // 2x2 warp grid
    const int wn = wid >> 1;
    const int g = lane >> 2;
    const int tg = lane & 3;

    const int m0 = blockIdx.y * 128;
    const int n0 = blockIdx.x * 128;

    const __half* Arow = A + (size_t)m0 * CC;
    const __half* Wrow = W + (size_t)n0 * CC;

    // ldmatrix per-lane bases
    const uint32_t aRow = (lane & 7) + ((lane >> 3) & 1) * 8;
    const uint32_t aCol = ((lane >> 4) & 1) * 8;
    const uint32_t bRow = (lane & 7) + ((lane >> 4) & 1) * 8;
    const uint32_t bCol = ((lane >> 3) & 1) * 8;
    const uint32_t lmA = sA + ((wm * 64 + aRow) * GPADH + aCol) * 2;
    const uint32_t lmB = sW + ((wn * 64 + bRow) * GPADH + bCol) * 2;

    float acc[4][8][4] = {};

    // staging: 128 rows x 8 units (16B) per operand -> 8 cp16/thread/operand
    auto stage = [&](int chunk, int buf) {
        const int col = chunk * GCH;
        #pragma unroll
        for (int t = 0; t < 8; t++) {
            int idx = tid + t * 128;
            int r = idx >> 3, u = idx & 7;
            const uint32_t d = (uint32_t)buf * HSTG_B + (uint32_t)(r * GPADH + u * 8) * 2;
            cp16(sA + d, Arow + (size_t)r * CC + col + u * 8);
            cp16(sW + d, Wrow + (size_t)r * CC + col + u * 8);
        }
        cp_commit();
    };

    stage(0, 0);
    stage(1, 1);

    int cur = 0;
    for (int i = 0; i < NCH; i++) {
        if (i + 1 < NCH) cp_wait<1>(); else cp_wait<0>();
        __syncthreads();

        if (i + 2 < NCH) {
            int nxt = cur + 2; if (nxt >= 3) nxt -= 3;
            stage(i + 2, nxt);
        }

        const uint32_t aOff = lmA + (uint32_t)cur * HSTG_B;
        const uint32_t bOff = lmB + (uint32_t)cur * HSTG_B;
        #pragma unroll
        for (int kc = 0; kc < 4; kc++) {
            uint32_t af[4][4], bq[4][4];
            #pragma unroll
            for (int mi = 0; mi < 4; mi++)
                ldsm4(af[mi], aOff + mi * 16 * GPADH * 2 + kc * 32);
            #pragma unroll
            for (int nj = 0; nj < 4; nj++)
                ldsm4(bq[nj], bOff + nj * 16 * GPADH * 2 + kc * 32);
            #pragma unroll
            for (int mi = 0; mi < 4; mi++) {
                #pragma unroll
                for (int nj = 0; nj < 4; nj++) {
                    mma_f16(acc[mi][nj * 2 + 0], af[mi], &bq[nj][0]);
                    mma_f16(acc[mi][nj * 2 + 1], af[mi], &bq[nj][2]);
                }
            }
        }
        cur++; if (cur == 3) cur = 0;
    }

    // ------------------------- epilogue -------------------------
    if (mode <= 1) {
        // RoPE + RMSnorm fused; output fp16 (q: fold 0.125)
        __half* Hout = (mode == 0) ? Hq : Hk;
        #pragma unroll
        for (int mi = 0; mi < 4; mi++) {
            #pragma unroll
            for (int half = 0; half < 2; half++) {
                const int row = m0 + wm * 64 + mi * 16 + g + half * 8;
                const int t = row & (TT - 1);
                const float* ct = cs + t * 32;
                const float* st = sn + t * 32;
                float y1v[4][2], y2v[4][2];
                float ss = 0.0f;
                #pragma unroll
                for (int nj = 0; nj < 4; nj++) {
                    #pragma unroll
                    for (int e = 0; e < 2; e++) {
                        const int i2 = nj * 8 + tg * 2 + e;   // 0..31
                        float x1 = acc[mi][nj    ][half * 2 + e];
                        float x2 = acc[mi][nj + 4][half * 2 + e];
                        float c = ct[i2], s = st[i2];
                        float y1 = x1 * c + x2 * s;
                        float y2 = -x1 * s + x2 * c;
                        ss += y1 * y1 + y2 * y2;
                        y1v[nj][e] = y1;
                        y2v[nj][e] = y2;
                    }
                }
                ss += __shfl_xor_sync(0xffffffffu, ss, 1);
                ss += __shfl_xor_sync(0xffffffffu, ss, 2);
                float r = rsqrtf(ss * (1.0f / 64.0f) + EPS);
                if (mode == 0) r *= 0.125f;
                __half* dst = Hout + (size_t)row * CC + n0 + wn * 64 + tg * 2;
                #pragma unroll
                for (int nj = 0; nj < 4; nj++) {
                    *(__half2*)(dst + nj * 8) =
                        __floats2half2_rn(y1v[nj][0] * r, y1v[nj][1] * r);
                    *(__half2*)(dst + (nj + 4) * 8) =
                        __floats2half2_rn(y2v[nj][0] * r, y2v[nj][1] * r);
                }
            }
        }
    } else {
        #pragma unroll
        for (int mi = 0; mi < 4; mi++) {
            int r = m0 + wm * 64 + mi * 16 + g;
            #pragma unroll
            for (int nj = 0; nj < 8; nj++) {
                int c = n0 + wn * 64 + nj * 8 + tg * 2;
                if (mode == 2) {
                    *(__half2*)&Hv[(size_t)r * CC + c] =
                        __floats2half2_rn(acc[mi][nj][0], acc[mi][nj][1]);
                    *(__half2*)&Hv[(size_t)(r + 8) * CC + c] =
                        __floats2half2_rn(acc[mi][nj][2], acc[mi][nj][3]);
                } else {
                    *(float2*)&Cf[(size_t)r * CC + c] =
                        make_float2(acc[mi][nj][0], acc[mi][nj][1]);
                    *(float2*)&Cf[(size_t)(r + 8) * CC + c] =
                        make_float2(acc[mi][nj][2], acc[mi][nj][3]);
                }
            }
        }
    }
}

// ---------------------------------------------------------------------------
// Flash attention, fp16 MMA + ldmatrix(.trans for V). Br=128, Bc=64, D=64.
// 8 warps. K/V double-buffered, ONE barrier per j-tile, loads overlap
// compute. Q fragments hoisted to registers. 72 KB smem -> 2 CTAs/SM.
// ---------------------------------------------------------------------------
#define FLDH 72                // halves per smem row (64 + 8 pad)
#define NJT (TT / 64)
#define KVBUF_B (64 * FLDH * 2)

__global__ __launch_bounds__(256, 2) void flash_f16(
    const __half* __restrict__ q, const __half* __restrict__ kk,
    const __half* __restrict__ vv, __half* __restrict__ y)
{
    extern __shared__ __half smh[];
    __half* Qs = smh;                      // 128 x 72
    __half* Ks = smh + 128 * FLDH;         // 2 x 64 x 72
    __half* Vs = smh + 256 * FLDH;         // 2 x 64 x 72 ([s][d] natural)
    __half* Ps = smh + 384 * FLDH;         // 128 x 72

    const int tid = threadIdx.x;
    const int wid = tid >> 5;
    const int lane = tid & 31;
    const int g = lane >> 2, tg = lane & 3;

    const int bh = blockIdx.y;
    const size_t base = (size_t)(bh / HH) * TT * CC + (size_t)(bh % HH) * DD;
    const int q0 = blockIdx.x * 128;

    const uint32_t sQ = (uint32_t)__cvta_generic_to_shared(Qs);
    const uint32_t sK = (uint32_t)__cvta_generic_to_shared(Ks);
    const uint32_t sV = (uint32_t)__cvta_generic_to_shared(Vs);
    const uint32_t sP = (uint32_t)__cvta_generic_to_shared(Ps);

    const int mb = wid * 16;
    const uint32_t aRow = (lane & 7) + ((lane >> 3) & 1) * 8;
    const uint32_t aCol = ((lane >> 4) & 1) * 8;
    const uint32_t bRow = (lane & 7) + ((lane >> 4) & 1) * 8;
    const uint32_t bCol = ((lane >> 3) & 1) * 8;
    const uint32_t vRow = (lane & 7) + ((lane >> 3) & 1) * 8;
    const uint32_t vCol = ((lane >> 4) & 1) * 8;
    const uint32_t lmQ = sQ + ((mb + aRow) * FLDH + aCol) * 2;
    const uint32_t lmP = sP + ((mb + aRow) * FLDH + aCol) * 2;
    const uint32_t lmK = sK + (bRow * FLDH + bCol) * 2;
    const uint32_t lmV = sV + (vRow * FLDH + vCol) * 2;

    auto stageKV = [&](int jt, int buf) {
        const int j0 = jt * 64;
        #pragma unroll
        for (int t = 0; t < 2; t++) {
            int idx = tid + t * 256;
            int r = idx >> 3, u = idx & 7;
            const uint32_t d = (uint32_t)buf * KVBUF_B + (uint32_t)(r * FLDH + u * 8) * 2;
            cp16(sK + d, kk + base + (size_t)(j0 + r) * CC + u * 8);
            cp16(sV + d, vv + base + (size_t)(j0 + r) * CC + u * 8);
        }
        cp_commit();
    };

    #pragma unroll
    for (int t = 0; t < 4; t++) {
        int idx = tid + t * 256;
        int r = idx >> 3, u = idx & 7;
        cp16(sQ + (uint32_t)(r * FLDH + u * 8) * 2,
             q + base + (size_t)(q0 + r) * CC + u * 8);
    }
    stageKV(0, 0);

    float mrow[2] = {-1e30f, -1e30f};
    float lrow[2] = {0.0f, 0.0f};
    float oacc[8][4] = {};
    uint32_t qfrag[4][4];

    for (int jt = 0; jt < NJT; jt++) {
        const int cur = jt & 1;
        cp_wait<0>();
        __syncthreads();

        if (jt == 0) {
            #pragma unroll
            for (int kc = 0; kc < 4; kc++)
                ldsm4(qfrag[kc], lmQ + kc * 32);
        }

        if (jt + 1 < NJT) stageKV(jt + 1, cur ^ 1);

        // S = (Q*scale) K^T
        const uint32_t kOff = lmK + (uint32_t)cur * KVBUF_B;
        float sacc[8][4] = {};
        #pragma unroll
        for (int kc = 0; kc < 4; kc++) {
            #pragma unroll
            for (int nj = 0; nj < 4; nj++) {
                uint32_t bq[4];
                ldsm4(bq, kOff + nj * 16 * FLDH * 2 + kc * 32);
                mma_f16(sacc[nj * 2 + 0], qfrag[kc], &bq[0]);
                mma_f16(sacc[nj * 2 + 1], qfrag[kc], &bq[2]);
            }
        }

        // Online softmax
        float rmax[2] = {-1e30f, -1e30f};
        #pragma unroll
        for (int ni = 0; ni < 8; ni++) {
            rmax[0] = fmaxf(rmax[0], fmaxf(sacc[ni][0], sacc[ni][1]));
            rmax[1] = fmaxf(rmax[1], fmaxf(sacc[ni][2], sacc[ni][3]));
        }
        #pragma unroll
        for (int o = 1; o <= 2; o <<= 1) {
            rmax[0] = fmaxf(rmax[0], __shfl_xor_sync(0xffffffffu, rmax[0], o));
            rmax[1] = fmaxf(rmax[1], __shfl_xor_sync(0xffffffffu, rmax[1], o));
        }
        float nm0 = fmaxf(mrow[0], rmax[0]);
        float nm1 = fmaxf(mrow[1], rmax[1]);
        float alpha0 = __expf(mrow[0] - nm0);
        float alpha1 = __expf(mrow[1] - nm1);

        float rsum[2] = {0.0f, 0.0f};
        #pragma unroll
        for (int ni = 0; ni < 8; ni++) {
            float p0 = __expf(sacc[ni][0] - nm0);
            float p1 = __expf(sacc[ni][1] - nm0);
            float p2 = __expf(sacc[ni][2] - nm1);
            float p3 = __expf(sacc[ni][3] - nm1);
            rsum[0] += p0 + p1;
            rsum[1] += p2 + p3;
            int c = ni * 8 + tg * 2;
            *(__half2*)&Ps[(mb + g    ) * FLDH + c] = __floats2half2_rn(p0, p1);
            *(__half2*)&Ps[(mb + g + 8) * FLDH + c] = __floats2half2_rn(p2, p3);
        }
        #pragma unroll
        for (int o = 1; o <= 2; o <<= 1) {
            rsum[0] += __shfl_xor_sync(0xffffffffu, rsum[0], o);
            rsum[1] += __shfl_xor_sync(0xffffffffu, rsum[1], o);
        }
        lrow[0] = lrow[0] * alpha0 + rsum[0];
        lrow[1] = lrow[1] * alpha1 + rsum[1];
        mrow[0] = nm0;
        mrow[1] = nm1;

        #pragma unroll
        for (int ni = 0; ni < 8; ni++) {
            oacc[ni][0] *= alpha0; oacc[ni][1] *= alpha0;
            oacc[ni][2] *= alpha1; oacc[ni][3] *= alpha1;
        }
        __syncwarp();

        // O += P V
        const uint32_t vOff = lmV + (uint32_t)cur * KVBUF_B;
        #pragma unroll
        for (int kc = 0; kc < 4; kc++) {
            uint32_t af[4];
            ldsm4(af, lmP + kc * 32);
            #pragma unroll
            for (int nj = 0; nj < 4; nj++) {
                uint32_t bq[4];
                ldsm4t(bq, vOff + kc * 16 * FLDH * 2 + nj * 32);
                mma_f16(oacc[nj * 2 + 0], af, &bq[0]);
                mma_f16(oacc[nj * 2 + 1], af, &bq[2]);
            }
        }
    }

    // Epilogue
    float inv0 = 1.0f / lrow[0];
    float inv1 = 1.0f / lrow[1];
    int r0 = q0 + mb + g;
    #pragma unroll
    for (int ni = 0; ni < 8; ni++) {
        int c = ni * 8 + tg * 2;
        *(__half2*)&y[base + (size_t)r0 * CC + c] =
            __floats2half2_rn(oacc[ni][0] * inv0, oacc[ni][1] * inv0);
        *(__half2*)&y[base + (size_t)(r0 + 8) * CC + c] =
            __floats2half2_rn(oacc[ni][2] * inv1, oacc[ni][3] * inv1);
    }
}

// ---------------------------------------------------------------------------
// Launch
// ---------------------------------------------------------------------------
extern "C" void kernel_launch(void* const* d_in, const int* in_sizes, int n_in,
                              void* d_out, int out_size)
{
    const float* x  = (const float*)d_in[0];
    const float* cs = (const float*)d_in[1];
    const float* sn = (const float*)d_in[2];
    const float* Wq = (const float*)d_in[3];
    const float* Wk = (const float*)d_in[4];
    const float* Wv = (const float*)d_in[5];
    const float* Wo = (const float*)d_in[6];
    float* out = (float*)d_out;

    __half *xh, *wh, *qh, *kh, *vh, *yh;
    cudaGetSymbolAddress((void**)&xh, h_x);
    cudaGetSymbolAddress((void**)&wh, h_w);
    cudaGetSymbolAddress((void**)&qh, h_q);
    cudaGetSymbolAddress((void**)&kh, h_k);
    cudaGetSymbolAddress((void**)&vh, h_v);
    cudaGetSymbolAddress((void**)&yh, h_y);

    const int NX = BB * TT * CC;
    const int NW = CC * CC;

    cvt_pass<<<NX / 1024, 256>>>(x, xh, NX);
    dim3 wgrid(NW / 1024, 4);
    cvt_w4<<<wgrid, 256>>>(Wq, Wk, Wv, Wo, wh);

    const int gsmem = 6 * HSTG_B;   // 110592 B
    cudaFuncSetAttribute(gemm_f16, cudaFuncAttributeMaxDynamicSharedMemorySize, gsmem);

    // Fused QKV projections with rope/rms epilogues (modes 0,1,2)
    dim3 qkvgrid(CC / 128, (BB * TT) / 128, 3);
    gemm_f16<<<qkvgrid, 128, gsmem>>>(xh, wh, qh, kh, vh, nullptr, cs, sn, 0);

    const int fsmem = 512 * FLDH * 2;   // 73728 B
    cudaFuncSetAttribute(flash_f16, cudaFuncAttributeMaxDynamicSharedMemorySize, fsmem);
    dim3 fgrid(TT / 128, BB * HH);
    flash_f16<<<fgrid, 256, fsmem>>>(qh, kh, vh, yh);

    // Output projection (mode 3, fp32 out)
    dim3 ogrid(CC / 128, (BB * TT) / 128, 1);
    gemm_f16<<<ogrid, 128, gsmem>>>(yh, wh, nullptr, nullptr, nullptr, out, cs, sn, 3);
}

// round 15
// speedup vs baseline: 2.6337x; 1.0496x over previous
#include <cuda_runtime.h>
#include <cuda_fp16.h>
#include <math.h>
#include <stdint.h>
#include <string.h>

#define BB 4
#define TT 2048
#define CC 1024
#define HH 16
#define DD 64
#define EPS 1.1920929e-07f

// ---------------------------------------------------------------------------
// Scratch (allocation-free rule)
// ---------------------------------------------------------------------------
__device__ __half h_x[BB * TT * CC];      // fp16 x
__device__ __half h_w[4 * CC * CC];       // fp16 weights
__device__ __half h_q[BB * TT * CC];      // fp16 q (post rope, x0.125)
__device__ __half h_k[BB * TT * CC];      // fp16 k (post rope)
__device__ __half h_v[BB * TT * CC];      // fp16 v
__device__ __half h_y[BB * TT * CC];      // fp16 attention output

// ---------------------------------------------------------------------------
// helpers
// ---------------------------------------------------------------------------
__device__ __forceinline__ uint32_t h2_as_u32(__half2 h) {
    uint32_t u;
    memcpy(&u, &h, 4);
    return u;
}

__device__ __forceinline__ void mma_f16(float* c, const uint32_t* a, const uint32_t* b) {
    asm volatile(
        "mma.sync.aligned.m16n8k16.row.col.f32.f16.f16.f32 "
        "{%0,%1,%2,%3}, {%4,%5,%6,%7}, {%8,%9}, {%0,%1,%2,%3};"
        : "+f"(c[0]), "+f"(c[1]), "+f"(c[2]), "+f"(c[3])
        : "r"(a[0]), "r"(a[1]), "r"(a[2]), "r"(a[3]), "r"(b[0]), "r"(b[1]));
}

__device__ __forceinline__ void ldsm4(uint32_t* r, uint32_t addr) {
    asm volatile(
        "ldmatrix.sync.aligned.m8n8.x4.shared.b16 {%0,%1,%2,%3}, [%4];"
        : "=r"(r[0]), "=r"(r[1]), "=r"(r[2]), "=r"(r[3]) : "r"(addr));
}
__device__ __forceinline__ void ldsm4t(uint32_t* r, uint32_t addr) {
    asm volatile(
        "ldmatrix.sync.aligned.m8n8.x4.trans.shared.b16 {%0,%1,%2,%3}, [%4];"
        : "=r"(r[0]), "=r"(r[1]), "=r"(r[2]), "=r"(r[3]) : "r"(addr));
}

__device__ __forceinline__ void cp16(uint32_t dst, const void* src) {
    asm volatile("cp.async.ca.shared.global [%0], [%1], 16;" :: "r"(dst), "l"(src));
}
__device__ __forceinline__ void cp_commit() {
    asm volatile("cp.async.commit_group;");
}
template <int N>
__device__ __forceinline__ void cp_wait() {
    asm volatile("cp.async.wait_group %0;" :: "n"(N));
}

// ---------------------------------------------------------------------------
// Pre-pass: fp32 -> fp16 (rn). cvt_w4: grid.y selects one of 4 weights.
// ---------------------------------------------------------------------------
__global__ __launch_bounds__(256) void cvt_pass(
    const float* __restrict__ src, __half* __restrict__ dst, int n)
{
    int i = (blockIdx.x * 256 + threadIdx.x) * 4;
    if (i < n) {
        float4 v = *(const float4*)(src + i);
        *(__half2*)(dst + i)     = __floats2half2_rn(v.x, v.y);
        *(__half2*)(dst + i + 2) = __floats2half2_rn(v.z, v.w);
    }
}

__global__ __launch_bounds__(256) void cvt_w4(
    const float* __restrict__ w0, const float* __restrict__ w1,
    const float* __restrict__ w2, const float* __restrict__ w3,
    __half* __restrict__ dst)
{
    const float* src = blockIdx.y == 0 ? w0 : (blockIdx.y == 1 ? w1 :
                       (blockIdx.y == 2 ? w2 : w3));
    __half* d = dst + (size_t)blockIdx.y * CC * CC;
    int i = (blockIdx.x * 256 + threadIdx.x) * 4;
    float4 v = *(const float4*)(src + i);
    *(__half2*)(d + i)     = __floats2half2_rn(v.x, v.y);
    *(__half2*)(d + i + 2) = __floats2half2_rn(v.z, v.w);
}

// ---------------------------------------------------------------------------
// GEMM NT (fp16 MMA m16n8k16 + ldmatrix): C[m,n] = sum_k A[m,k]*W[n,k].
// 128x128 CTA tile, 128 threads (4 warps as 2x2), warp tile 64x64.
// K-chunks of 64 halves, 3-stage cp.async pipeline, 2 CTAs/SM.
// mode = modeBase + blockIdx.z:
//   0: RoPE+RMSnorm fused epilogue -> Hq (fp16, 0.125 folded)
//   1: RoPE+RMSnorm fused epilogue -> Hk (fp16)
//   2: fp16 convert -> Hv
//   3: fp32 -> Cf (output projection)
// ---------------------------------------------------------------------------
#define GCH 64                 // K halves per chunk
#define NCH (CC / GCH)         // 16
#define GPADH 72               // halves per smem row (64 + 8 pad)
#define HSTG_B (128 * GPADH * 2)   // 18432 bytes per operand stage

__global__ __launch_bounds__(128, 2) void gemm_f16(
    const __half* __restrict__ A, const __half* __restrict__ Wbase,
    __half* __restrict__ Hq, __half* __restrict__ Hk, __half* __restrict__ Hv,
    float* __restrict__ Cf,
    const float* __restrict__ cs, const float* __restrict__ sn,
    int modeBase)
{
    extern __shared__ __half sg[];
    const uint32_t sA = (uint32_t)__cvta_generic_to_shared(sg);
    const uint32_t sW = sA + 3 * HSTG_B;

    const int mode = modeBase + blockIdx.z;
    const __half* W = Wbase + (size_t)blockIdx.z * CC * CC + (size_t)(modeBase == 3 ? 3 : 0) * CC * CC;

    const int tid = threadIdx.x;
    const int wid = tid >> 5;
    const int lane = tid & 31;
    const int wm = wid & 1;        // 2x2 warp grid
    const int wn = wid >> 1;
    const int g = lane >> 2;
    const int tg = lane & 3;

    const int m0 = blockIdx.y * 128;
    const int n0 = blockIdx.x * 128;

    const __half* Arow = A + (size_t)m0 * CC;
    const __half* Wrow = W + (size_t)n0 * CC;

    const uint32_t aRow = (lane & 7) + ((lane >> 3) & 1) * 8;
    const uint32_t aCol = ((lane >> 4) & 1) * 8;
    const uint32_t bRow = (lane & 7) + ((lane >> 4) & 1) * 8;
    const uint32_t bCol = ((lane >> 3) & 1) * 8;
    const uint32_t lmA = sA + ((wm * 64 + aRow) * GPADH + aCol) * 2;
    const uint32_t lmB = sW + ((wn * 64 + bRow) * GPADH + bCol) * 2;

    float acc[4][8][4] = {};

    auto stage = [&](int chunk, int buf) {
        const int col = chunk * GCH;
        #pragma unroll
        for (int t = 0; t < 8; t++) {
            int idx = tid + t * 128;
            int r = idx >> 3, u = idx & 7;
            const uint32_t d = (uint32_t)buf * HSTG_B + (uint32_t)(r * GPADH + u * 8) * 2;
            cp16(sA + d, Arow + (size_t)r * CC + col + u * 8);
            cp16(sW + d, Wrow + (size_t)r * CC + col + u * 8);
        }
        cp_commit();
    };

    stage(0, 0);
    stage(1, 1);

    int cur = 0;
    for (int i = 0; i < NCH; i++) {
        if (i + 1 < NCH) cp_wait<1>(); else cp_wait<0>();
        __syncthreads();

        if (i + 2 < NCH) {
            int nxt = cur + 2; if (nxt >= 3) nxt -= 3;
            stage(i + 2, nxt);
        }

        const uint32_t aOff = lmA + (uint32_t)cur * HSTG_B;
        const uint32_t bOff = lmB + (uint32_t)cur * HSTG_B;
        #pragma unroll
        for (int kc = 0; kc < 4; kc++) {
            uint32_t af[4][4], bq[4][4];
            #pragma unroll
            for (int mi = 0; mi < 4; mi++)
                ldsm4(af[mi], aOff + mi * 16 * GPADH * 2 + kc * 32);
            #pragma unroll
            for (int nj = 0; nj < 4; nj++)
                ldsm4(bq[nj], bOff + nj * 16 * GPADH * 2 + kc * 32);
            #pragma unroll
            for (int mi = 0; mi < 4; mi++) {
                #pragma unroll
                for (int nj = 0; nj < 4; nj++) {
                    mma_f16(acc[mi][nj * 2 + 0], af[mi], &bq[nj][0]);
                    mma_f16(acc[mi][nj * 2 + 1], af[mi], &bq[nj][2]);
                }
            }
        }
        cur++; if (cur == 3) cur = 0;
    }

    // ------------------------- epilogue -------------------------
    if (mode <= 1) {
        __half* Hout = (mode == 0) ? Hq : Hk;
        #pragma unroll
        for (int mi = 0; mi < 4; mi++) {
            #pragma unroll
            for (int half = 0; half < 2; half++) {
                const int row = m0 + wm * 64 + mi * 16 + g + half * 8;
                const int t = row & (TT - 1);
                const float* ct = cs + t * 32;
                const float* st = sn + t * 32;
                float y1v[4][2], y2v[4][2];
                float ss = 0.0f;
                #pragma unroll
                for (int nj = 0; nj < 4; nj++) {
                    #pragma unroll
                    for (int e = 0; e < 2; e++) {
                        const int i2 = nj * 8 + tg * 2 + e;
                        float x1 = acc[mi][nj    ][half * 2 + e];
                        float x2 = acc[mi][nj + 4][half * 2 + e];
                        float c = ct[i2], s = st[i2];
                        float y1 = x1 * c + x2 * s;
                        float y2 = -x1 * s + x2 * c;
                        ss += y1 * y1 + y2 * y2;
                        y1v[nj][e] = y1;
                        y2v[nj][e] = y2;
                    }
                }
                ss += __shfl_xor_sync(0xffffffffu, ss, 1);
                ss += __shfl_xor_sync(0xffffffffu, ss, 2);
                float r = rsqrtf(ss * (1.0f / 64.0f) + EPS);
                if (mode == 0) r *= 0.125f;
                __half* dst = Hout + (size_t)row * CC + n0 + wn * 64 + tg * 2;
                #pragma unroll
                for (int nj = 0; nj < 4; nj++) {
                    *(__half2*)(dst + nj * 8) =
                        __floats2half2_rn(y1v[nj][0] * r, y1v[nj][1] * r);
                    *(__half2*)(dst + (nj + 4) * 8) =
                        __floats2half2_rn(y2v[nj][0] * r, y2v[nj][1] * r);
                }
            }
        }
    } else {
        #pragma unroll
        for (int mi = 0; mi < 4; mi++) {
            int r = m0 + wm * 64 + mi * 16 + g;
            #pragma unroll
            for (int nj = 0; nj < 8; nj++) {
                int c = n0 + wn * 64 + nj * 8 + tg * 2;
                if (mode == 2) {
                    *(__half2*)&Hv[(size_t)r * CC + c] =
                        __floats2half2_rn(acc[mi][nj][0], acc[mi][nj][1]);
                    *(__half2*)&Hv[(size_t)(r + 8) * CC + c] =
                        __floats2half2_rn(acc[mi][nj][2], acc[mi][nj][3]);
                } else {
                    *(float2*)&Cf[(size_t)r * CC + c] =
                        make_float2(acc[mi][nj][0], acc[mi][nj][1]);
                    *(float2*)&Cf[(size_t)(r + 8) * CC + c] =
                        make_float2(acc[mi][nj][2], acc[mi][nj][3]);
                }
            }
        }
    }
}

// ---------------------------------------------------------------------------
// Flash attention, fp16 MMA + ldmatrix(.trans for V). Br=128, Bc=64, D=64.
// 8 warps. K/V double-buffered, ONE barrier per j-tile, loads overlap
// compute. Q fragments hoisted. P packed to A-fragments IN REGISTERS
// (C-frag of S == A-frag layout of P) -> no P smem round-trip.
// 55 KB smem -> 2 CTAs/SM.
// ---------------------------------------------------------------------------
#define FLDH 72                // halves per smem row (64 + 8 pad)
#define NJT (TT / 64)
#define KVBUF_B (64 * FLDH * 2)

__global__ __launch_bounds__(256, 2) void flash_f16(
    const __half* __restrict__ q, const __half* __restrict__ kk,
    const __half* __restrict__ vv, __half* __restrict__ y)
{
    extern __shared__ __half smh[];
    __half* Qs = smh;                      // 128 x 72
    __half* Ks = smh + 128 * FLDH;         // 2 x 64 x 72
    __half* Vs = smh + 256 * FLDH;         // 2 x 64 x 72 ([s][d] natural)

    const int tid = threadIdx.x;
    const int wid = tid >> 5;
    const int lane = tid & 31;
    const int g = lane >> 2, tg = lane & 3;

    const int bh = blockIdx.y;
    const size_t base = (size_t)(bh / HH) * TT * CC + (size_t)(bh % HH) * DD;
    const int q0 = blockIdx.x * 128;

    const uint32_t sQ = (uint32_t)__cvta_generic_to_shared(Qs);
    const uint32_t sK = (uint32_t)__cvta_generic_to_shared(Ks);
    const uint32_t sV = (uint32_t)__cvta_generic_to_shared(Vs);

    const int mb = wid * 16;
    const uint32_t aRow = (lane & 7) + ((lane >> 3) & 1) * 8;
    const uint32_t aCol = ((lane >> 4) & 1) * 8;
    const uint32_t bRow = (lane & 7) + ((lane >> 4) & 1) * 8;
    const uint32_t bCol = ((lane >> 3) & 1) * 8;
    const uint32_t vRow = (lane & 7) + ((lane >> 3) & 1) * 8;
    const uint32_t vCol = ((lane >> 4) & 1) * 8;
    const uint32_t lmQ = sQ + ((mb + aRow) * FLDH + aCol) * 2;
    const uint32_t lmK = sK + (bRow * FLDH + bCol) * 2;
    const uint32_t lmV = sV + (vRow * FLDH + vCol) * 2;

    auto stageKV = [&](int jt, int buf) {
        const int j0 = jt * 64;
        #pragma unroll
        for (int t = 0; t < 2; t++) {
            int idx = tid + t * 256;
            int r = idx >> 3, u = idx & 7;
            const uint32_t d = (uint32_t)buf * KVBUF_B + (uint32_t)(r * FLDH + u * 8) * 2;
            cp16(sK + d, kk + base + (size_t)(j0 + r) * CC + u * 8);
            cp16(sV + d, vv + base + (size_t)(j0 + r) * CC + u * 8);
        }
        cp_commit();
    };

    #pragma unroll
    for (int t = 0; t < 4; t++) {
        int idx = tid + t * 256;
        int r = idx >> 3, u = idx & 7;
        cp16(sQ + (uint32_t)(r * FLDH + u * 8) * 2,
             q + base + (size_t)(q0 + r) * CC + u * 8);
    }
    stageKV(0, 0);

    float mrow[2] = {-1e30f, -1e30f};
    float lrow[2] = {0.0f, 0.0f};
    float oacc[8][4] = {};
    uint32_t qfrag[4][4];

    for (int jt = 0; jt < NJT; jt++) {
        const int cur = jt & 1;
        cp_wait<0>();
        __syncthreads();

        if (jt == 0) {
            #pragma unroll
            for (int kc = 0; kc < 4; kc++)
                ldsm4(qfrag[kc], lmQ + kc * 32);
        }

        if (jt + 1 < NJT) stageKV(jt + 1, cur ^ 1);

        // S = (Q*scale) K^T
        const uint32_t kOff = lmK + (uint32_t)cur * KVBUF_B;
        float sacc[8][4] = {};
        #pragma unroll
        for (int kc = 0; kc < 4; kc++) {
            #pragma unroll
            for (int nj = 0; nj < 4; nj++) {
                uint32_t bq[4];
                ldsm4(bq, kOff + nj * 16 * FLDH * 2 + kc * 32);
                mma_f16(sacc[nj * 2 + 0], qfrag[kc], &bq[0]);
                mma_f16(sacc[nj * 2 + 1], qfrag[kc], &bq[2]);
            }
        }

        // Online softmax
        float rmax[2] = {-1e30f, -1e30f};
        #pragma unroll
        for (int ni = 0; ni < 8; ni++) {
            rmax[0] = fmaxf(rmax[0], fmaxf(sacc[ni][0], sacc[ni][1]));
            rmax[1] = fmaxf(rmax[1], fmaxf(sacc[ni][2], sacc[ni][3]));
        }
        #pragma unroll
        for (int o = 1; o <= 2; o <<= 1) {
            rmax[0] = fmaxf(rmax[0], __shfl_xor_sync(0xffffffffu, rmax[0], o));
            rmax[1] = fmaxf(rmax[1], __shfl_xor_sync(0xffffffffu, rmax[1], o));
        }
        float nm0 = fmaxf(mrow[0], rmax[0]);
        float nm1 = fmaxf(mrow[1], rmax[1]);
        float alpha0 = __expf(mrow[0] - nm0);
        float alpha1 = __expf(mrow[1] - nm1);

        // exp + pack P into A-fragment registers (C-frag == A-frag layout)
        uint32_t pf[8][2];   // pf[ni][0]=rows g, pf[ni][1]=rows g+8
        float rsum[2] = {0.0f, 0.0f};
        #pragma unroll
        for (int ni = 0; ni < 8; ni++) {
            float p0 = __expf(sacc[ni][0] - nm0);
            float p1 = __expf(sacc[ni][1] - nm0);
            float p2 = __expf(sacc[ni][2] - nm1);
            float p3 = __expf(sacc[ni][3] - nm1);
            rsum[0] += p0 + p1;
            rsum[1] += p2 + p3;
            pf[ni][0] = h2_as_u32(__floats2half2_rn(p0, p1));
            pf[ni][1] = h2_as_u32(__floats2half2_rn(p2, p3));
        }
        #pragma unroll
        for (int o = 1; o <= 2; o <<= 1) {
            rsum[0] += __shfl_xor_sync(0xffffffffu, rsum[0], o);
            rsum[1] += __shfl_xor_sync(0xffffffffu, rsum[1], o);
        }
        lrow[0] = lrow[0] * alpha0 + rsum[0];
        lrow[1] = lrow[1] * alpha1 + rsum[1];
        mrow[0] = nm0;
        mrow[1] = nm1;

        #pragma unroll
        for (int ni = 0; ni < 8; ni++) {
            oacc[ni][0] *= alpha0; oacc[ni][1] *= alpha0;
            oacc[ni][2] *= alpha1; oacc[ni][3] *= alpha1;
        }

        // O += P V   (P A-frags from registers; V via ldmatrix.trans)
        const uint32_t vOff = lmV + (uint32_t)cur * KVBUF_B;
        #pragma unroll
        for (int kc = 0; kc < 4; kc++) {
            uint32_t af[4] = { pf[2 * kc][0], pf[2 * kc][1],
                               pf[2 * kc + 1][0], pf[2 * kc + 1][1] };
            #pragma unroll
            for (int nj = 0; nj < 4; nj++) {
                uint32_t bq[4];
                ldsm4t(bq, vOff + kc * 16 * FLDH * 2 + nj * 32);
                mma_f16(oacc[nj * 2 + 0], af, &bq[0]);
                mma_f16(oacc[nj * 2 + 1], af, &bq[2]);
            }
        }
    }

    // Epilogue
    float inv0 = 1.0f / lrow[0];
    float inv1 = 1.0f / lrow[1];
    int r0 = q0 + mb + g;
    #pragma unroll
    for (int ni = 0; ni < 8; ni++) {
        int c = ni * 8 + tg * 2;
        *(__half2*)&y[base + (size_t)r0 * CC + c] =
            __floats2half2_rn(oacc[ni][0] * inv0, oacc[ni][1] * inv0);
        *(__half2*)&y[base + (size_t)(r0 + 8) * CC + c] =
            __floats2half2_rn(oacc[ni][2] * inv1, oacc[ni][3] * inv1);
    }
}

// ---------------------------------------------------------------------------
// Launch
// ---------------------------------------------------------------------------
extern "C" void kernel_launch(void* const* d_in, const int* in_sizes, int n_in,
                              void* d_out, int out_size)
{
    const float* x  = (const float*)d_in[0];
    const float* cs = (const float*)d_in[1];
    const float* sn = (const float*)d_in[2];
    const float* Wq = (const float*)d_in[3];
    const float* Wk = (const float*)d_in[4];
    const float* Wv = (const float*)d_in[5];
    const float* Wo = (const float*)d_in[6];
    float* out = (float*)d_out;

    __half *xh, *wh, *qh, *kh, *vh, *yh;
    cudaGetSymbolAddress((void**)&xh, h_x);
    cudaGetSymbolAddress((void**)&wh, h_w);
    cudaGetSymbolAddress((void**)&qh, h_q);
    cudaGetSymbolAddress((void**)&kh, h_k);
    cudaGetSymbolAddress((void**)&vh, h_v);
    cudaGetSymbolAddress((void**)&yh, h_y);

    const int NX = BB * TT * CC;
    const int NW = CC * CC;

    cvt_pass<<<NX / 1024, 256>>>(x, xh, NX);
    dim3 wgrid(NW / 1024, 4);
    cvt_w4<<<wgrid, 256>>>(Wq, Wk, Wv, Wo, wh);

    const int gsmem = 6 * HSTG_B;   // 110592 B
    cudaFuncSetAttribute(gemm_f16, cudaFuncAttributeMaxDynamicSharedMemorySize, gsmem);

    // Fused QKV projections with rope/rms epilogues (modes 0,1,2)
    dim3 qkvgrid(CC / 128, (BB * TT) / 128, 3);
    gemm_f16<<<qkvgrid, 128, gsmem>>>(xh, wh, qh, kh, vh, nullptr, cs, sn, 0);

    const int fsmem = 384 * FLDH * 2;   // 55296 B
    cudaFuncSetAttribute(flash_f16, cudaFuncAttributeMaxDynamicSharedMemorySize, fsmem);
    dim3 fgrid(TT / 128, BB * HH);
    flash_f16<<<fgrid, 256, fsmem>>>(qh, kh, vh, yh);

    // Output projection (mode 3, fp32 out)
    dim3 ogrid(CC / 128, (BB * TT) / 128, 1);
    gemm_f16<<<ogrid, 128, gsmem>>>(yh, wh, nullptr, nullptr, nullptr, out, cs, sn, 3);
}

// round 16
// speedup vs baseline: 2.6961x; 1.0237x over previous
#include <cuda_runtime.h>
#include <cuda_fp16.h>
#include <math.h>
#include <stdint.h>
#include <string.h>

#define BB 4
#define TT 2048
#define CC 1024
#define HH 16
#define DD 64
#define EPS 1.1920929e-07f
#define LOG2E 1.44269504088896340736f

// ---------------------------------------------------------------------------
// Scratch (allocation-free rule)
// ---------------------------------------------------------------------------
__device__ __half h_x[BB * TT * CC];      // fp16 x
__device__ __half h_w[4 * CC * CC];       // fp16 weights
__device__ __half h_q[BB * TT * CC];      // fp16 q (post rope, x 0.125*log2e)
__device__ __half h_k[BB * TT * CC];      // fp16 k (post rope)
__device__ __half h_v[BB * TT * CC];      // fp16 v
__device__ __half h_y[BB * TT * CC];      // fp16 attention output

// ---------------------------------------------------------------------------
// helpers
// ---------------------------------------------------------------------------
__device__ __forceinline__ uint32_t h2_as_u32(__half2 h) {
    uint32_t u;
    memcpy(&u, &h, 4);
    return u;
}

__device__ __forceinline__ void mma_f16(float* c, const uint32_t* a, const uint32_t* b) {
    asm volatile(
        "mma.sync.aligned.m16n8k16.row.col.f32.f16.f16.f32 "
        "{%0,%1,%2,%3}, {%4,%5,%6,%7}, {%8,%9}, {%0,%1,%2,%3};"
        : "+f"(c[0]), "+f"(c[1]), "+f"(c[2]), "+f"(c[3])
        : "r"(a[0]), "r"(a[1]), "r"(a[2]), "r"(a[3]), "r"(b[0]), "r"(b[1]));
}

__device__ __forceinline__ void ldsm4(uint32_t* r, uint32_t addr) {
    asm volatile(
        "ldmatrix.sync.aligned.m8n8.x4.shared.b16 {%0,%1,%2,%3}, [%4];"
        : "=r"(r[0]), "=r"(r[1]), "=r"(r[2]), "=r"(r[3]) : "r"(addr));
}
__device__ __forceinline__ void ldsm4t(uint32_t* r, uint32_t addr) {
    asm volatile(
        "ldmatrix.sync.aligned.m8n8.x4.trans.shared.b16 {%0,%1,%2,%3}, [%4];"
        : "=r"(r[0]), "=r"(r[1]), "=r"(r[2]), "=r"(r[3]) : "r"(addr));
}

__device__ __forceinline__ void cp16(uint32_t dst, const void* src) {
    asm volatile("cp.async.ca.shared.global [%0], [%1], 16;" :: "r"(dst), "l"(src));
}
__device__ __forceinline__ void cp_commit() {
    asm volatile("cp.async.commit_group;");
}
template <int N>
__device__ __forceinline__ void cp_wait() {
    asm volatile("cp.async.wait_group %0;" :: "n"(N));
}

// ---------------------------------------------------------------------------
// Fused pre-pass: fp32 -> fp16 (rn) for 4 weights + x, one launch.
// grid.y: 0..3 -> weights (1M elems each), 4..11 -> x chunks (1M each).
// ---------------------------------------------------------------------------
__global__ __launch_bounds__(256) void cvt_all(
    const float* __restrict__ x,
    const float* __restrict__ w0, const float* __restrict__ w1,
    const float* __restrict__ w2, const float* __restrict__ w3,
    __half* __restrict__ dw, __half* __restrict__ dx)
{
    const int seg = blockIdx.y;
    const float* src;
    __half* dst;
    if (seg < 4) {
        src = seg == 0 ? w0 : (seg == 1 ? w1 : (seg == 2 ? w2 : w3));
        dst = dw + (size_t)seg * CC * CC;
    } else {
        src = x + (size_t)(seg - 4) * CC * CC;
        dst = dx + (size_t)(seg - 4) * CC * CC;
    }
    int i = (blockIdx.x * 256 + threadIdx.x) * 4;
    float4 v = *(const float4*)(src + i);
    *(__half2*)(dst + i)     = __floats2half2_rn(v.x, v.y);
    *(__half2*)(dst + i + 2) = __floats2half2_rn(v.z, v.w);
}

// ---------------------------------------------------------------------------
// GEMM NT (fp16 MMA m16n8k16 + ldmatrix): C[m,n] = sum_k A[m,k]*W[n,k].
// 128x128 CTA tile, 128 threads (4 warps as 2x2), warp tile 64x64.
// K-chunks of 64 halves, 3-stage cp.async pipeline, 2 CTAs/SM.
// mode = modeBase + blockIdx.z:
//   0: RoPE+RMSnorm fused epilogue -> Hq (fp16, 0.125*log2e folded)
//   1: RoPE+RMSnorm fused epilogue -> Hk (fp16)
//   2: fp16 convert -> Hv
//   3: fp32 -> Cf (output projection)
// ---------------------------------------------------------------------------
#define GCH 64                 // K halves per chunk
#define NCH (CC / GCH)         // 16
#define GPADH 72               // halves per smem row (64 + 8 pad)
#define HSTG_B (128 * GPADH * 2)   // 18432 bytes per operand stage

__global__ __launch_bounds__(128, 2) void gemm_f16(
    const __half* __restrict__ A, const __half* __restrict__ Wbase,
    __half* __restrict__ Hq, __half* __restrict__ Hk, __half* __restrict__ Hv,
    float* __restrict__ Cf,
    const float* __restrict__ cs, const float* __restrict__ sn,
    int modeBase)
{
    extern __shared__ __half sg[];
    const uint32_t sA = (uint32_t)__cvta_generic_to_shared(sg);
    const uint32_t sW = sA + 3 * HSTG_B;

    const int mode = modeBase + blockIdx.z;
    const __half* W = Wbase + (size_t)blockIdx.z * CC * CC + (size_t)(modeBase == 3 ? 3 : 0) * CC * CC;

    const int tid = threadIdx.x;
    const int wid = tid >> 5;
    const int lane = tid & 31;
    const int wm = wid & 1;        // 2x2 warp grid
    const int wn = wid >> 1;
    const int g = lane >> 2;
    const int tg = lane & 3;

    const int m0 = blockIdx.y * 128;
    const int n0 = blockIdx.x * 128;

    const __half* Arow = A + (size_t)m0 * CC;
    const __half* Wrow = W + (size_t)n0 * CC;

    const uint32_t aRow = (lane & 7) + ((lane >> 3) & 1) * 8;
    const uint32_t aCol = ((lane >> 4) & 1) * 8;
    const uint32_t bRow = (lane & 7) + ((lane >> 4) & 1) * 8;
    const uint32_t bCol = ((lane >> 3) & 1) * 8;
    const uint32_t lmA = sA + ((wm * 64 + aRow) * GPADH + aCol) * 2;
    const uint32_t lmB = sW + ((wn * 64 + bRow) * GPADH + bCol) * 2;

    float acc[4][8][4] = {};

    auto stage = [&](int chunk, int buf) {
        const int col = chunk * GCH;
        #pragma unroll
        for (int t = 0; t < 8; t++) {
            int idx = tid + t * 128;
            int r = idx >> 3, u = idx & 7;
            const uint32_t d = (uint32_t)buf * HSTG_B + (uint32_t)(r * GPADH + u * 8) * 2;
            cp16(sA + d, Arow + (size_t)r * CC + col + u * 8);
            cp16(sW + d, Wrow + (size_t)r * CC + col + u * 8);
        }
        cp_commit();
    };

    stage(0, 0);
    stage(1, 1);

    int cur = 0;
    for (int i = 0; i < NCH; i++) {
        if (i + 1 < NCH) cp_wait<1>(); else cp_wait<0>();
        __syncthreads();

        if (i + 2 < NCH) {
            int nxt = cur + 2; if (nxt >= 3) nxt -= 3;
            stage(i + 2, nxt);
        }

        const uint32_t aOff = lmA + (uint32_t)cur * HSTG_B;
        const uint32_t bOff = lmB + (uint32_t)cur * HSTG_B;
        #pragma unroll
        for (int kc = 0; kc < 4; kc++) {
            uint32_t af[4][4], bq[4][4];
            #pragma unroll
            for (int mi = 0; mi < 4; mi++)
                ldsm4(af[mi], aOff + mi * 16 * GPADH * 2 + kc * 32);
            #pragma unroll
            for (int nj = 0; nj < 4; nj++)
                ldsm4(bq[nj], bOff + nj * 16 * GPADH * 2 + kc * 32);
            #pragma unroll
            for (int mi = 0; mi < 4; mi++) {
                #pragma unroll
                for (int nj = 0; nj < 4; nj++) {
                    mma_f16(acc[mi][nj * 2 + 0], af[mi], &bq[nj][0]);
                    mma_f16(acc[mi][nj * 2 + 1], af[mi], &bq[nj][2]);
                }
            }
        }
        cur++; if (cur == 3) cur = 0;
    }

    // ------------------------- epilogue -------------------------
    if (mode <= 1) {
        __half* Hout = (mode == 0) ? Hq : Hk;
        #pragma unroll
        for (int mi = 0; mi < 4; mi++) {
            #pragma unroll
            for (int half = 0; half < 2; half++) {
                const int row = m0 + wm * 64 + mi * 16 + g + half * 8;
                const int t = row & (TT - 1);
                const float* ct = cs + t * 32;
                const float* st = sn + t * 32;
                float y1v[4][2], y2v[4][2];
                float ss = 0.0f;
                #pragma unroll
                for (int nj = 0; nj < 4; nj++) {
                    #pragma unroll
                    for (int e = 0; e < 2; e++) {
                        const int i2 = nj * 8 + tg * 2 + e;
                        float x1 = acc[mi][nj    ][half * 2 + e];
                        float x2 = acc[mi][nj + 4][half * 2 + e];
                        float c = ct[i2], s = st[i2];
                        float y1 = x1 * c + x2 * s;
                        float y2 = -x1 * s + x2 * c;
                        ss += y1 * y1 + y2 * y2;
                        y1v[nj][e] = y1;
                        y2v[nj][e] = y2;
                    }
                }
                ss += __shfl_xor_sync(0xffffffffu, ss, 1);
                ss += __shfl_xor_sync(0xffffffffu, ss, 2);
                float r = rsqrtf(ss * (1.0f / 64.0f) + EPS);
                if (mode == 0) r *= 0.125f * LOG2E;   // fold scale + log2e for exp2
                __half* dst = Hout + (size_t)row * CC + n0 + wn * 64 + tg * 2;
                #pragma unroll
                for (int nj = 0; nj < 4; nj++) {
                    *(__half2*)(dst + nj * 8) =
                        __floats2half2_rn(y1v[nj][0] * r, y1v[nj][1] * r);
                    *(__half2*)(dst + (nj + 4) * 8) =
                        __floats2half2_rn(y2v[nj][0] * r, y2v[nj][1] * r);
                }
            }
        }
    } else {
        #pragma unroll
        for (int mi = 0; mi < 4; mi++) {
            int r = m0 + wm * 64 + mi * 16 + g;
            #pragma unroll
            for (int nj = 0; nj < 8; nj++) {
                int c = n0 + wn * 64 + nj * 8 + tg * 2;
                if (mode == 2) {
                    *(__half2*)&Hv[(size_t)r * CC + c] =
                        __floats2half2_rn(acc[mi][nj][0], acc[mi][nj][1]);
                    *(__half2*)&Hv[(size_t)(r + 8) * CC + c] =
                        __floats2half2_rn(acc[mi][nj][2], acc[mi][nj][3]);
                } else {
                    *(float2*)&Cf[(size_t)r * CC + c] =
                        make_float2(acc[mi][nj][0], acc[mi][nj][1]);
                    *(float2*)&Cf[(size_t)(r + 8) * CC + c] =
                        make_float2(acc[mi][nj][2], acc[mi][nj][3]);
                }
            }
        }
    }
}

// ---------------------------------------------------------------------------
// Flash attention, fp16 MMA + ldmatrix(.trans for V). Br=128, Bc=64, D=64.
// 8 warps. K/V double-buffered, ONE barrier per j-tile, loads overlap
// compute. Q fragments hoisted. P packed to A-fragments IN REGISTERS.
// Softmax in exp2 domain (log2e pre-folded into q). 55 KB smem, 2 CTAs/SM.
// ---------------------------------------------------------------------------
#define FLDH 72                // halves per smem row (64 + 8 pad)
#define NJT (TT / 64)
#define KVBUF_B (64 * FLDH * 2)

__global__ __launch_bounds__(256, 2) void flash_f16(
    const __half* __restrict__ q, const __half* __restrict__ kk,
    const __half* __restrict__ vv, __half* __restrict__ y)
{
    extern __shared__ __half smh[];
    __half* Qs = smh;                      // 128 x 72
    __half* Ks = smh + 128 * FLDH;         // 2 x 64 x 72
    __half* Vs = smh + 256 * FLDH;         // 2 x 64 x 72 ([s][d] natural)

    const int tid = threadIdx.x;
    const int wid = tid >> 5;
    const int lane = tid & 31;
    const int g = lane >> 2, tg = lane & 3;

    const int bh = blockIdx.y;
    const size_t base = (size_t)(bh / HH) * TT * CC + (size_t)(bh % HH) * DD;
    const int q0 = blockIdx.x * 128;

    const uint32_t sQ = (uint32_t)__cvta_generic_to_shared(Qs);
    const uint32_t sK = (uint32_t)__cvta_generic_to_shared(Ks);
    const uint32_t sV = (uint32_t)__cvta_generic_to_shared(Vs);

    const int mb = wid * 16;
    const uint32_t aRow = (lane & 7) + ((lane >> 3) & 1) * 8;
    const uint32_t aCol = ((lane >> 4) & 1) * 8;
    const uint32_t bRow = (lane & 7) + ((lane >> 4) & 1) * 8;
    const uint32_t bCol = ((lane >> 3) & 1) * 8;
    const uint32_t vRow = (lane & 7) + ((lane >> 3) & 1) * 8;
    const uint32_t vCol = ((lane >> 4) & 1) * 8;
    const uint32_t lmQ = sQ + ((mb + aRow) * FLDH + aCol) * 2;
    const uint32_t lmK = sK + (bRow * FLDH + bCol) * 2;
    const uint32_t lmV = sV + (vRow * FLDH + vCol) * 2;

    auto stageKV = [&](int jt, int buf) {
        const int j0 = jt * 64;
        #pragma unroll
        for (int t = 0; t < 2; t++) {
            int idx = tid + t * 256;
            int r = idx >> 3, u = idx & 7;
            const uint32_t d = (uint32_t)buf * KVBUF_B + (uint32_t)(r * FLDH + u * 8) * 2;
            cp16(sK + d, kk + base + (size_t)(j0 + r) * CC + u * 8);
            cp16(sV + d, vv + base + (size_t)(j0 + r) * CC + u * 8);
        }
        cp_commit();
    };

    #pragma unroll
    for (int t = 0; t < 4; t++) {
        int idx = tid + t * 256;
        int r = idx >> 3, u = idx & 7;
        cp16(sQ + (uint32_t)(r * FLDH + u * 8) * 2,
             q + base + (size_t)(q0 + r) * CC + u * 8);
    }
    stageKV(0, 0);

    float mrow[2] = {-1e30f, -1e30f};
    float lrow[2] = {0.0f, 0.0f};
    float oacc[8][4] = {};
    uint32_t qfrag[4][4];

    for (int jt = 0; jt < NJT; jt++) {
        const int cur = jt & 1;
        cp_wait<0>();
        __syncthreads();

        if (jt == 0) {
            #pragma unroll
            for (int kc = 0; kc < 4; kc++)
                ldsm4(qfrag[kc], lmQ + kc * 32);
        }

        if (jt + 1 < NJT) stageKV(jt + 1, cur ^ 1);

        // S' = (Q*scale*log2e) K^T  (exp2 domain)
        const uint32_t kOff = lmK + (uint32_t)cur * KVBUF_B;
        float sacc[8][4] = {};
        #pragma unroll
        for (int kc = 0; kc < 4; kc++) {
            #pragma unroll
            for (int nj = 0; nj < 4; nj++) {
                uint32_t bq[4];
                ldsm4(bq, kOff + nj * 16 * FLDH * 2 + kc * 32);
                mma_f16(sacc[nj * 2 + 0], qfrag[kc], &bq[0]);
                mma_f16(sacc[nj * 2 + 1], qfrag[kc], &bq[2]);
            }
        }

        // Online softmax (exp2 domain)
        float rmax[2] = {-1e30f, -1e30f};
        #pragma unroll
        for (int ni = 0; ni < 8; ni++) {
            rmax[0] = fmaxf(rmax[0], fmaxf(sacc[ni][0], sacc[ni][1]));
            rmax[1] = fmaxf(rmax[1], fmaxf(sacc[ni][2], sacc[ni][3]));
        }
        #pragma unroll
        for (int o = 1; o <= 2; o <<= 1) {
            rmax[0] = fmaxf(rmax[0], __shfl_xor_sync(0xffffffffu, rmax[0], o));
            rmax[1] = fmaxf(rmax[1], __shfl_xor_sync(0xffffffffu, rmax[1], o));
        }
        float nm0 = fmaxf(mrow[0], rmax[0]);
        float nm1 = fmaxf(mrow[1], rmax[1]);
        float alpha0 = exp2f(mrow[0] - nm0);
        float alpha1 = exp2f(mrow[1] - nm1);

        // exp2 + pack P into A-fragment registers
        uint32_t pf[8][2];
        float rsum[2] = {0.0f, 0.0f};
        #pragma unroll
        for (int ni = 0; ni < 8; ni++) {
            float p0 = exp2f(sacc[ni][0] - nm0);
            float p1 = exp2f(sacc[ni][1] - nm0);
            float p2 = exp2f(sacc[ni][2] - nm1);
            float p3 = exp2f(sacc[ni][3] - nm1);
            rsum[0] += p0 + p1;
            rsum[1] += p2 + p3;
            pf[ni][0] = h2_as_u32(__floats2half2_rn(p0, p1));
            pf[ni][1] = h2_as_u32(__floats2half2_rn(p2, p3));
        }
        #pragma unroll
        for (int o = 1; o <= 2; o <<= 1) {
            rsum[0] += __shfl_xor_sync(0xffffffffu, rsum[0], o);
            rsum[1] += __shfl_xor_sync(0xffffffffu, rsum[1], o);
        }
        lrow[0] = lrow[0] * alpha0 + rsum[0];
        lrow[1] = lrow[1] * alpha1 + rsum[1];
        mrow[0] = nm0;
        mrow[1] = nm1;

        #pragma unroll
        for (int ni = 0; ni < 8; ni++) {
            oacc[ni][0] *= alpha0; oacc[ni][1] *= alpha0;
            oacc[ni][2] *= alpha1; oacc[ni][3] *= alpha1;
        }

        // O += P V
        const uint32_t vOff = lmV + (uint32_t)cur * KVBUF_B;
        #pragma unroll
        for (int kc = 0; kc < 4; kc++) {
            uint32_t af[4] = { pf[2 * kc][0], pf[2 * kc][1],
                               pf[2 * kc + 1][0], pf[2 * kc + 1][1] };
            #pragma unroll
            for (int nj = 0; nj < 4; nj++) {
                uint32_t bq[4];
                ldsm4t(bq, vOff + kc * 16 * FLDH * 2 + nj * 32);
                mma_f16(oacc[nj * 2 + 0], af, &bq[0]);
                mma_f16(oacc[nj * 2 + 1], af, &bq[2]);
            }
        }
    }

    // Epilogue
    float inv0 = 1.0f / lrow[0];
    float inv1 = 1.0f / lrow[1];
    int r0 = q0 + mb + g;
    #pragma unroll
    for (int ni = 0; ni < 8; ni++) {
        int c = ni * 8 + tg * 2;
        *(__half2*)&y[base + (size_t)r0 * CC + c] =
            __floats2half2_rn(oacc[ni][0] * inv0, oacc[ni][1] * inv0);
        *(__half2*)&y[base + (size_t)(r0 + 8) * CC + c] =
            __floats2half2_rn(oacc[ni][2] * inv1, oacc[ni][3] * inv1);
    }
}

// ---------------------------------------------------------------------------
// Launch
// ---------------------------------------------------------------------------
extern "C" void kernel_launch(void* const* d_in, const int* in_sizes, int n_in,
                              void* d_out, int out_size)
{
    const float* x  = (const float*)d_in[0];
    const float* cs = (const float*)d_in[1];
    const float* sn = (const float*)d_in[2];
    const float* Wq = (const float*)d_in[3];
    const float* Wk = (const float*)d_in[4];
    const float* Wv = (const float*)d_in[5];
    const float* Wo = (const float*)d_in[6];
    float* out = (float*)d_out;

    __half *xh, *wh, *qh, *kh, *vh, *yh;
    cudaGetSymbolAddress((void**)&xh, h_x);
    cudaGetSymbolAddress((void**)&wh, h_w);
    cudaGetSymbolAddress((void**)&qh, h_q);
    cudaGetSymbolAddress((void**)&kh, h_k);
    cudaGetSymbolAddress((void**)&vh, h_v);
    cudaGetSymbolAddress((void**)&yh, h_y);

    const int NW = CC * CC;

    // Single fused conversion launch: 4 weights + 8 x-chunks of 1M elems
    dim3 cgrid(NW / 1024, 12);
    cvt_all<<<cgrid, 256>>>(x, Wq, Wk, Wv, Wo, wh, xh);

    const int gsmem = 6 * HSTG_B;   // 110592 B
    cudaFuncSetAttribute(gemm_f16, cudaFuncAttributeMaxDynamicSharedMemorySize, gsmem);

    // Fused QKV projections with rope/rms epilogues (modes 0,1,2)
    dim3 qkvgrid(CC / 128, (BB * TT) / 128, 3);
    gemm_f16<<<qkvgrid, 128, gsmem>>>(xh, wh, qh, kh, vh, nullptr, cs, sn, 0);

    const int fsmem = 384 * FLDH * 2;   // 55296 B
    cudaFuncSetAttribute(flash_f16, cudaFuncAttributeMaxDynamicSharedMemorySize, fsmem);
    dim3 fgrid(TT / 128, BB * HH);
    flash_f16<<<fgrid, 256, fsmem>>>(qh, kh, vh, yh);

    // Output projection (mode 3, fp32 out)
    dim3 ogrid(CC / 128, (BB * TT) / 128, 1);
    gemm_f16<<<ogrid, 128, gsmem>>>(yh, wh, nullptr, nullptr, nullptr, out, cs, sn, 3);
}

// round 17
// speedup vs baseline: 2.8275x; 1.0487x over previous
#include <cuda_runtime.h>
#include <cuda_fp16.h>
#include <math.h>
#include <stdint.h>
#include <string.h>

#define BB 4
#define TT 2048
#define CC 1024
#define HH 16
#define DD 64
#define EPS 1.1920929e-07f
#define LOG2E 1.44269504088896340736f

// ---------------------------------------------------------------------------
// Scratch (allocation-free rule)
// ---------------------------------------------------------------------------
__device__ __half h_x[BB * TT * CC];      // fp16 x
__device__ __half h_w[4 * CC * CC];       // fp16 weights
__device__ __half h_q[BB * TT * CC];      // fp16 q (post rope, x 0.125*log2e)
__device__ __half h_k[BB * TT * CC];      // fp16 k (post rope)
__device__ __half h_v[BB * TT * CC];      // fp16 v
__device__ __half h_y[BB * TT * CC];      // fp16 attention output

// ---------------------------------------------------------------------------
// helpers
// ---------------------------------------------------------------------------
__device__ __forceinline__ uint32_t h2_as_u32(__half2 h) {
    uint32_t u;
    memcpy(&u, &h, 4);
    return u;
}

__device__ __forceinline__ void mma_f16(float* c, const uint32_t* a, const uint32_t* b) {
    asm volatile(
        "mma.sync.aligned.m16n8k16.row.col.f32.f16.f16.f32 "
        "{%0,%1,%2,%3}, {%4,%5,%6,%7}, {%8,%9}, {%0,%1,%2,%3};"
        : "+f"(c[0]), "+f"(c[1]), "+f"(c[2]), "+f"(c[3])
        : "r"(a[0]), "r"(a[1]), "r"(a[2]), "r"(a[3]), "r"(b[0]), "r"(b[1]));
}

__device__ __forceinline__ void ldsm4(uint32_t* r, uint32_t addr) {
    asm volatile(
        "ldmatrix.sync.aligned.m8n8.x4.shared.b16 {%0,%1,%2,%3}, [%4];"
        : "=r"(r[0]), "=r"(r[1]), "=r"(r[2]), "=r"(r[3]) : "r"(addr));
}
__device__ __forceinline__ void ldsm4t(uint32_t* r, uint32_t addr) {
    asm volatile(
        "ldmatrix.sync.aligned.m8n8.x4.trans.shared.b16 {%0,%1,%2,%3}, [%4];"
        : "=r"(r[0]), "=r"(r[1]), "=r"(r[2]), "=r"(r[3]) : "r"(addr));
}

__device__ __forceinline__ void cp16(uint32_t dst, const void* src) {
    asm volatile("cp.async.ca.shared.global [%0], [%1], 16;" :: "r"(dst), "l"(src));
}
__device__ __forceinline__ void cp_commit() {
    asm volatile("cp.async.commit_group;");
}
template <int N>
__device__ __forceinline__ void cp_wait() {
    asm volatile("cp.async.wait_group %0;" :: "n"(N));
}

// ---------------------------------------------------------------------------
// Fused pre-pass: fp32 -> fp16 (rn) for 4 weights + x, one launch.
// grid.y: 0..3 -> weights (1M elems each), 4..11 -> x chunks (1M each).
// ---------------------------------------------------------------------------
__global__ __launch_bounds__(256) void cvt_all(
    const float* __restrict__ x,
    const float* __restrict__ w0, const float* __restrict__ w1,
    const float* __restrict__ w2, const float* __restrict__ w3,
    __half* __restrict__ dw, __half* __restrict__ dx)
{
    const int seg = blockIdx.y;
    const float* src;
    __half* dst;
    if (seg < 4) {
        src = seg == 0 ? w0 : (seg == 1 ? w1 : (seg == 2 ? w2 : w3));
        dst = dw + (size_t)seg * CC * CC;
    } else {
        src = x + (size_t)(seg - 4) * CC * CC;
        dst = dx + (size_t)(seg - 4) * CC * CC;
    }
    int i = (blockIdx.x * 256 + threadIdx.x) * 4;
    float4 v = *(const float4*)(src + i);
    *(__half2*)(dst + i)     = __floats2half2_rn(v.x, v.y);
    *(__half2*)(dst + i + 2) = __floats2half2_rn(v.z, v.w);
}

// ---------------------------------------------------------------------------
// GEMM NT (fp16 MMA m16n8k16 + ldmatrix): C[m,n] = sum_k A[m,k]*W[n,k].
// 128x128 CTA tile, 128 threads (4 warps as 2x2), warp tile 64x64.
// K-chunks of 64 halves, 2-stage cp.async pipeline, 3 CTAs/SM (12 warps).
// mode = modeBase + blockIdx.z:
//   0: RoPE+RMSnorm fused epilogue -> Hq (fp16, 0.125*log2e folded)
//   1: RoPE+RMSnorm fused epilogue -> Hk (fp16)
//   2: fp16 convert -> Hv
//   3: fp32 -> Cf (output projection)
// ---------------------------------------------------------------------------
#define GCH 64                 // K halves per chunk
#define NCH (CC / GCH)         // 16
#define GPADH 72               // halves per smem row (64 + 8 pad)
#define HSTG_B (128 * GPADH * 2)   // 18432 bytes per operand stage

__global__ __launch_bounds__(128, 3) void gemm_f16(
    const __half* __restrict__ A, const __half* __restrict__ Wbase,
    __half* __restrict__ Hq, __half* __restrict__ Hk, __half* __restrict__ Hv,
    float* __restrict__ Cf,
    const float* __restrict__ cs, const float* __restrict__ sn,
    int modeBase)
{
    extern __shared__ __half sg[];
    const uint32_t sA = (uint32_t)__cvta_generic_to_shared(sg);
    const uint32_t sW = sA + 2 * HSTG_B;

    const int mode = modeBase + blockIdx.z;
    const __half* W = Wbase + (size_t)blockIdx.z * CC * CC + (size_t)(modeBase == 3 ? 3 : 0) * CC * CC;

    const int tid = threadIdx.x;
    const int wid = tid >> 5;
    const int lane = tid & 31;
    const int wm = wid & 1;        // 2x2 warp grid
    const int wn = wid >> 1;
    const int g = lane >> 2;
    const int tg = lane & 3;

    const int m0 = blockIdx.y * 128;
    const int n0 = blockIdx.x * 128;

    const __half* Arow = A + (size_t)m0 * CC;
    const __half* Wrow = W + (size_t)n0 * CC;

    const uint32_t aRow = (lane & 7) + ((lane >> 3) & 1) * 8;
    const uint32_t aCol = ((lane >> 4) & 1) * 8;
    const uint32_t bRow = (lane & 7) + ((lane >> 4) & 1) * 8;
    const uint32_t bCol = ((lane >> 3) & 1) * 8;
    const uint32_t lmA = sA + ((wm * 64 + aRow) * GPADH + aCol) * 2;
    const uint32_t lmB = sW + ((wn * 64 + bRow) * GPADH + bCol) * 2;

    float acc[4][8][4] = {};

    auto stage = [&](int chunk, int buf) {
        const int col = chunk * GCH;
        #pragma unroll
        for (int t = 0; t < 8; t++) {
            int idx = tid + t * 128;
            int r = idx >> 3, u = idx & 7;
            const uint32_t d = (uint32_t)buf * HSTG_B + (uint32_t)(r * GPADH + u * 8) * 2;
            cp16(sA + d, Arow + (size_t)r * CC + col + u * 8);
            cp16(sW + d, Wrow + (size_t)r * CC + col + u * 8);
        }
        cp_commit();
    };

    stage(0, 0);   // prologue: stage 0 in flight

    for (int i = 0; i < NCH; i++) {
        const int cur = i & 1;
        cp_wait<0>();      // stage i arrived
        __syncthreads();   // visible; all warps done reading buf cur^1

        if (i + 1 < NCH) stage(i + 1, cur ^ 1);   // overlaps compute below

        const uint32_t aOff = lmA + (uint32_t)cur * HSTG_B;
        const uint32_t bOff = lmB + (uint32_t)cur * HSTG_B;
        #pragma unroll
        for (int kc = 0; kc < 4; kc++) {
            uint32_t af[4][4], bq[4][4];
            #pragma unroll
            for (int mi = 0; mi < 4; mi++)
                ldsm4(af[mi], aOff + mi * 16 * GPADH * 2 + kc * 32);
            #pragma unroll
            for (int nj = 0; nj < 4; nj++)
                ldsm4(bq[nj], bOff + nj * 16 * GPADH * 2 + kc * 32);
            #pragma unroll
            for (int mi = 0; mi < 4; mi++) {
                #pragma unroll
                for (int nj = 0; nj < 4; nj++) {
                    mma_f16(acc[mi][nj * 2 + 0], af[mi], &bq[nj][0]);
                    mma_f16(acc[mi][nj * 2 + 1], af[mi], &bq[nj][2]);
                }
            }
        }
    }

    // ------------------------- epilogue -------------------------
    if (mode <= 1) {
        __half* Hout = (mode == 0) ? Hq : Hk;
        #pragma unroll
        for (int mi = 0; mi < 4; mi++) {
            #pragma unroll
            for (int half = 0; half < 2; half++) {
                const int row = m0 + wm * 64 + mi * 16 + g + half * 8;
                const int t = row & (TT - 1);
                const float* ct = cs + t * 32;
                const float* st = sn + t * 32;
                float y1v[4][2], y2v[4][2];
                float ss = 0.0f;
                #pragma unroll
                for (int nj = 0; nj < 4; nj++) {
                    #pragma unroll
                    for (int e = 0; e < 2; e++) {
                        const int i2 = nj * 8 + tg * 2 + e;
                        float x1 = acc[mi][nj    ][half * 2 + e];
                        float x2 = acc[mi][nj + 4][half * 2 + e];
                        float c = ct[i2], s = st[i2];
                        float y1 = x1 * c + x2 * s;
                        float y2 = -x1 * s + x2 * c;
                        ss += y1 * y1 + y2 * y2;
                        y1v[nj][e] = y1;
                        y2v[nj][e] = y2;
                    }
                }
                ss += __shfl_xor_sync(0xffffffffu, ss, 1);
                ss += __shfl_xor_sync(0xffffffffu, ss, 2);
                float r = rsqrtf(ss * (1.0f / 64.0f) + EPS);
                if (mode == 0) r *= 0.125f * LOG2E;   // fold scale + log2e for exp2
                __half* dst = Hout + (size_t)row * CC + n0 + wn * 64 + tg * 2;
                #pragma unroll
                for (int nj = 0; nj < 4; nj++) {
                    *(__half2*)(dst + nj * 8) =
                        __floats2half2_rn(y1v[nj][0] * r, y1v[nj][1] * r);
                    *(__half2*)(dst + (nj + 4) * 8) =
                        __floats2half2_rn(y2v[nj][0] * r, y2v[nj][1] * r);
                }
            }
        }
    } else {
        #pragma unroll
        for (int mi = 0; mi < 4; mi++) {
            int r = m0 + wm * 64 + mi * 16 + g;
            #pragma unroll
            for (int nj = 0; nj < 8; nj++) {
                int c = n0 + wn * 64 + nj * 8 + tg * 2;
                if (mode == 2) {
                    *(__half2*)&Hv[(size_t)r * CC + c] =
                        __floats2half2_rn(acc[mi][nj][0], acc[mi][nj][1]);
                    *(__half2*)&Hv[(size_t)(r + 8) * CC + c] =
                        __floats2half2_rn(acc[mi][nj][2], acc[mi][nj][3]);
                } else {
                    *(float2*)&Cf[(size_t)r * CC + c] =
                        make_float2(acc[mi][nj][0], acc[mi][nj][1]);
                    *(float2*)&Cf[(size_t)(r + 8) * CC + c] =
                        make_float2(acc[mi][nj][2], acc[mi][nj][3]);
                }
            }
        }
    }
}

// ---------------------------------------------------------------------------
// Flash attention, fp16 MMA + ldmatrix(.trans for V). Br=128, Bc=64, D=64.
// 8 warps. K/V double-buffered, ONE barrier per j-tile, loads overlap
// compute. Q fragments hoisted. P packed to A-fragments IN REGISTERS.
// Softmax in exp2 domain (log2e pre-folded into q). 55 KB smem, 2 CTAs/SM.
// ---------------------------------------------------------------------------
#define FLDH 72                // halves per smem row (64 + 8 pad)
#define NJT (TT / 64)
#define KVBUF_B (64 * FLDH * 2)

__global__ __launch_bounds__(256, 2) void flash_f16(
    const __half* __restrict__ q, const __half* __restrict__ kk,
    const __half* __restrict__ vv, __half* __restrict__ y)
{
    extern __shared__ __half smh[];
    __half* Qs = smh;                      // 128 x 72
    __half* Ks = smh + 128 * FLDH;         // 2 x 64 x 72
    __half* Vs = smh + 256 * FLDH;         // 2 x 64 x 72 ([s][d] natural)

    const int tid = threadIdx.x;
    const int wid = tid >> 5;
    const int lane = tid & 31;
    const int g = lane >> 2, tg = lane & 3;

    const int bh = blockIdx.y;
    const size_t base = (size_t)(bh / HH) * TT * CC + (size_t)(bh % HH) * DD;
    const int q0 = blockIdx.x * 128;

    const uint32_t sQ = (uint32_t)__cvta_generic_to_shared(Qs);
    const uint32_t sK = (uint32_t)__cvta_generic_to_shared(Ks);
    const uint32_t sV = (uint32_t)__cvta_generic_to_shared(Vs);

    const int mb = wid * 16;
    const uint32_t aRow = (lane & 7) + ((lane >> 3) & 1) * 8;
    const uint32_t aCol = ((lane >> 4) & 1) * 8;
    const uint32_t bRow = (lane & 7) + ((lane >> 4) & 1) * 8;
    const uint32_t bCol = ((lane >> 3) & 1) * 8;
    const uint32_t vRow = (lane & 7) + ((lane >> 3) & 1) * 8;
    const uint32_t vCol = ((lane >> 4) & 1) * 8;
    const uint32_t lmQ = sQ + ((mb + aRow) * FLDH + aCol) * 2;
    const uint32_t lmK = sK + (bRow * FLDH + bCol) * 2;
    const uint32_t lmV = sV + (vRow * FLDH + vCol) * 2;

    auto stageKV = [&](int jt, int buf) {
        const int j0 = jt * 64;
        #pragma unroll
        for (int t = 0; t < 2; t++) {
            int idx = tid + t * 256;
            int r = idx >> 3, u = idx & 7;
            const uint32_t d = (uint32_t)buf * KVBUF_B + (uint32_t)(r * FLDH + u * 8) * 2;
            cp16(sK + d, kk + base + (size_t)(j0 + r) * CC + u * 8);
            cp16(sV + d, vv + base + (size_t)(j0 + r) * CC + u * 8);
        }
        cp_commit();
    };

    #pragma unroll
    for (int t = 0; t < 4; t++) {
        int idx = tid + t * 256;
        int r = idx >> 3, u = idx & 7;
        cp16(sQ + (uint32_t)(r * FLDH + u * 8) * 2,
             q + base + (size_t)(q0 + r) * CC + u * 8);
    }
    stageKV(0, 0);

    float mrow[2] = {-1e30f, -1e30f};
    float lrow[2] = {0.0f, 0.0f};
    float oacc[8][4] = {};
    uint32_t qfrag[4][4];

    for (int jt = 0; jt < NJT; jt++) {
        const int cur = jt & 1;
        cp_wait<0>();
        __syncthreads();

        if (jt == 0) {
            #pragma unroll
            for (int kc = 0; kc < 4; kc++)
                ldsm4(qfrag[kc], lmQ + kc * 32);
        }

        if (jt + 1 < NJT) stageKV(jt + 1, cur ^ 1);

        // S' = (Q*scale*log2e) K^T  (exp2 domain)
        const uint32_t kOff = lmK + (uint32_t)cur * KVBUF_B;
        float sacc[8][4] = {};
        #pragma unroll
        for (int kc = 0; kc < 4; kc++) {
            #pragma unroll
            for (int nj = 0; nj < 4; nj++) {
                uint32_t bq[4];
                ldsm4(bq, kOff + nj * 16 * FLDH * 2 + kc * 32);
                mma_f16(sacc[nj * 2 + 0], qfrag[kc], &bq[0]);
                mma_f16(sacc[nj * 2 + 1], qfrag[kc], &bq[2]);
            }
        }

        // Online softmax (exp2 domain)
        float rmax[2] = {-1e30f, -1e30f};
        #pragma unroll
        for (int ni = 0; ni < 8; ni++) {
            rmax[0] = fmaxf(rmax[0], fmaxf(sacc[ni][0], sacc[ni][1]));
            rmax[1] = fmaxf(rmax[1], fmaxf(sacc[ni][2], sacc[ni][3]));
        }
        #pragma unroll
        for (int o = 1; o <= 2; o <<= 1) {
            rmax[0] = fmaxf(rmax[0], __shfl_xor_sync(0xffffffffu, rmax[0], o));
            rmax[1] = fmaxf(rmax[1], __shfl_xor_sync(0xffffffffu, rmax[1], o));
        }
        float nm0 = fmaxf(mrow[0], rmax[0]);
        float nm1 = fmaxf(mrow[1], rmax[1]);
        float alpha0 = exp2f(mrow[0] - nm0);
        float alpha1 = exp2f(mrow[1] - nm1);

        // exp2 + pack P into A-fragment registers
        uint32_t pf[8][2];
        float rsum[2] = {0.0f, 0.0f};
        #pragma unroll
        for (int ni = 0; ni < 8; ni++) {
            float p0 = exp2f(sacc[ni][0] - nm0);
            float p1 = exp2f(sacc[ni][1] - nm0);
            float p2 = exp2f(sacc[ni][2] - nm1);
            float p3 = exp2f(sacc[ni][3] - nm1);
            rsum[0] += p0 + p1;
            rsum[1] += p2 + p3;
            pf[ni][0] = h2_as_u32(__floats2half2_rn(p0, p1));
            pf[ni][1] = h2_as_u32(__floats2half2_rn(p2, p3));
        }
        #pragma unroll
        for (int o = 1; o <= 2; o <<= 1) {
            rsum[0] += __shfl_xor_sync(0xffffffffu, rsum[0], o);
            rsum[1] += __shfl_xor_sync(0xffffffffu, rsum[1], o);
        }
        lrow[0] = lrow[0] * alpha0 + rsum[0];
        lrow[1] = lrow[1] * alpha1 + rsum[1];
        mrow[0] = nm0;
        mrow[1] = nm1;

        #pragma unroll
        for (int ni = 0; ni < 8; ni++) {
            oacc[ni][0] *= alpha0; oacc[ni][1] *= alpha0;
            oacc[ni][2] *= alpha1; oacc[ni][3] *= alpha1;
        }

        // O += P V
        const uint32_t vOff = lmV + (uint32_t)cur * KVBUF_B;
        #pragma unroll
        for (int kc = 0; kc < 4; kc++) {
            uint32_t af[4] = { pf[2 * kc][0], pf[2 * kc][1],
                               pf[2 * kc + 1][0], pf[2 * kc + 1][1] };
            #pragma unroll
            for (int nj = 0; nj < 4; nj++) {
                uint32_t bq[4];
                ldsm4t(bq, vOff + kc * 16 * FLDH * 2 + nj * 32);
                mma_f16(oacc[nj * 2 + 0], af, &bq[0]);
                mma_f16(oacc[nj * 2 + 1], af, &bq[2]);
            }
        }
    }

    // Epilogue
    float inv0 = 1.0f / lrow[0];
    float inv1 = 1.0f / lrow[1];
    int r0 = q0 + mb + g;
    #pragma unroll
    for (int ni = 0; ni < 8; ni++) {
        int c = ni * 8 + tg * 2;
        *(__half2*)&y[base + (size_t)r0 * CC + c] =
            __floats2half2_rn(oacc[ni][0] * inv0, oacc[ni][1] * inv0);
        *(__half2*)&y[base + (size_t)(r0 + 8) * CC + c] =
            __floats2half2_rn(oacc[ni][2] * inv1, oacc[ni][3] * inv1);
    }
}

// ---------------------------------------------------------------------------
// Launch
// ---------------------------------------------------------------------------
extern "C" void kernel_launch(void* const* d_in, const int* in_sizes, int n_in,
                              void* d_out, int out_size)
{
    const float* x  = (const float*)d_in[0];
    const float* cs = (const float*)d_in[1];
    const float* sn = (const float*)d_in[2];
    const float* Wq = (const float*)d_in[3];
    const float* Wk = (const float*)d_in[4];
    const float* Wv = (const float*)d_in[5];
    const float* Wo = (const float*)d_in[6];
    float* out = (float*)d_out;

    __half *xh, *wh, *qh, *kh, *vh, *yh;
    cudaGetSymbolAddress((void**)&xh, h_x);
    cudaGetSymbolAddress((void**)&wh, h_w);
    cudaGetSymbolAddress((void**)&qh, h_q);
    cudaGetSymbolAddress((void**)&kh, h_k);
    cudaGetSymbolAddress((void**)&vh, h_v);
    cudaGetSymbolAddress((void**)&yh, h_y);

    const int NW = CC * CC;

    // Single fused conversion launch: 4 weights + 8 x-chunks of 1M elems
    dim3 cgrid(NW / 1024, 12);
    cvt_all<<<cgrid, 256>>>(x, Wq, Wk, Wv, Wo, wh, xh);

    const int gsmem = 4 * HSTG_B;   // 73728 B (2-stage)
    cudaFuncSetAttribute(gemm_f16, cudaFuncAttributeMaxDynamicSharedMemorySize, gsmem);

    // Fused QKV projections with rope/rms epilogues (modes 0,1,2)
    dim3 qkvgrid(CC / 128, (BB * TT) / 128, 3);
    gemm_f16<<<qkvgrid, 128, gsmem>>>(xh, wh, qh, kh, vh, nullptr, cs, sn, 0);

    const int fsmem = 384 * FLDH * 2;   // 55296 B
    cudaFuncSetAttribute(flash_f16, cudaFuncAttributeMaxDynamicSharedMemorySize, fsmem);
    dim3 fgrid(TT / 128, BB * HH);
    flash_f16<<<fgrid, 256, fsmem>>>(qh, kh, vh, yh);

    // Output projection (mode 3, fp32 out)
    dim3 ogrid(CC / 128, (BB * TT) / 128, 1);
    gemm_f16<<<ogrid, 128, gsmem>>>(yh, wh, nullptr, nullptr, nullptr, out, cs, sn, 3);
}